// round 10
// baseline (speedup 1.0000x reference)
#include <cuda_runtime.h>
#include <cuda_bf16.h>
#include <cuda_fp16.h>
#include <math.h>
#include <stdint.h>

#define B_   64
#define S_   256
#define H_   1024
#define ENC_ 1024
#define E_   512
#define V_   32000
#define FDIM_ (H_ + ENC_ + E_)   // 2560
#define G4H_  (4 * H_)           // 4096
#define KCAT0 2560
#define KCAT1 2048
#define WKSCALE 2048.0f
#define INVWK   (1.0f / 2048.0f)

// ---------------- scratch ----------------------------------------------------
#define OFF_QUERY   0
#define OFF_GATES0  (OFF_QUERY + B_ * H_)
#define OFF_GATES1  (OFF_GATES0 + B_ * G4H_)
#define OFF_ENERGY  (OFF_GATES1 + B_ * G4H_)
#define SCRATCH_TOTAL (OFF_ENERGY + B_ * S_)

__device__ __align__(16) float g_scratch[SCRATCH_TOTAL];
__device__ int g_sidx[B_ * S_];
__device__ int g_scnt[B_];
__device__ int g_gidx[B_ * S_];
__device__ int g_total;

// fp16 buffers
__device__ __align__(16) __half g_enc_f16[(long)B_ * S_ * ENC_];
__device__ __align__(16) __half g_wk_h[H_ * ENC_];
__device__ __align__(16) __half g_wk_l[H_ * ENC_];
__device__ __align__(16) __half g_h1f[B_ * H_];
__device__ __align__(16) __half g_a0f[B_ * KCAT0];
__device__ __align__(16) __half g_a1f[B_ * KCAT1];
__device__ __align__(16) __half g_featf[B_ * FDIM_];

// ===================== low-level helpers =====================================
__device__ __forceinline__ uint32_t smem_to_u32(const void* p) {
    uint32_t a;
    asm("{ .reg .u64 t; cvta.to.shared.u64 t, %1; cvt.u32.u64 %0, t; }" : "=r"(a) : "l"(p));
    return a;
}

#define CP16(dst_u32, src_ptr) \
    asm volatile("cp.async.cg.shared.global [%0], [%1], 16;" :: "r"(dst_u32), "l"(src_ptr))
#define CP_COMMIT() asm volatile("cp.async.commit_group;" ::: "memory")
template<int N> __device__ __forceinline__ void cp_wait() {
    asm volatile("cp.async.wait_group %0;" :: "n"(N) : "memory");
}

__device__ __forceinline__ void ldmx4(uint32_t addr, uint32_t r[4]) {
    asm volatile("ldmatrix.sync.aligned.m8n8.x4.shared.b16 {%0,%1,%2,%3}, [%4];"
        : "=r"(r[0]), "=r"(r[1]), "=r"(r[2]), "=r"(r[3]) : "r"(addr));
}

__device__ __forceinline__ void mma16816h(float* c, const uint32_t a[4],
                                          uint32_t b0, uint32_t b1) {
    asm volatile("mma.sync.aligned.m16n8k16.row.col.f32.f16.f16.f32 "
        "{%0,%1,%2,%3}, {%4,%5,%6,%7}, {%8,%9}, {%0,%1,%2,%3};"
        : "+f"(c[0]), "+f"(c[1]), "+f"(c[2]), "+f"(c[3])
        : "r"(a[0]), "r"(a[1]), "r"(a[2]), "r"(a[3]), "r"(b0), "r"(b1));
}

#define STS128(addr, a, b, c, d) \
    asm volatile("st.shared.v4.b32 [%0], {%1,%2,%3,%4};" \
        :: "r"(addr), "r"(a), "r"(b), "r"(c), "r"(d) : "memory")

__device__ __forceinline__ uint32_t swz(int row, int chunk16) {
    return (uint32_t)(row * 128 + ((chunk16 ^ (row & 7)) * 16));
}

// fp16 scaled split: w*2048 = hi + lo
__device__ __forceinline__ void split2h(float a, float b, uint32_t& hi, uint32_t& lo) {
    float as = a * WKSCALE, bs = b * WKSCALE;
    __half2 h2 = __floats2half2_rn(as, bs);
    float ra = as - __half2float(__low2half(h2));
    float rb = bs - __half2float(__high2half(h2));
    __half2 l2 = __floats2half2_rn(ra, rb);
    hi = *reinterpret_cast<uint32_t*>(&h2);
    lo = *reinterpret_cast<uint32_t*>(&l2);
}

// ===================== mega prep+split kernel ================================
#define ENC_BLKS ((B_ * S_ * ENC_) / 1024)   // 16384
#define WK_BLKS  ((H_ * ENC_) / 1024)        // 1024
#define P0 (ENC_BLKS + WK_BLKS)              // 17408
#define PREP_BLKS (P0 + 64 + 64 + 64 + 256 + 256 + 2000)

__global__ void prep_kernel(const float* __restrict__ enc,
                            const float* __restrict__ wk,
                            const int* __restrict__ mask,
                            const float* __restrict__ hidden,
                            const int* __restrict__ tok,
                            const float* __restrict__ emb,
                            const float* __restrict__ bih0,
                            const float* __restrict__ bhh0,
                            const float* __restrict__ bih1,
                            const float* __restrict__ bhh1,
                            const float* __restrict__ bout,
                            float* __restrict__ energy,
                            float* __restrict__ query,
                            float* __restrict__ gates0,
                            float* __restrict__ gates1,
                            float* __restrict__ out_pred) {
    const int tid = threadIdx.x;
    const int blk = blockIdx.x;
    if (blk < ENC_BLKS) {
        long i = ((long)blk * 256 + tid) * 4;
        float4 v = *reinterpret_cast<const float4*>(enc + i);
        __half2 h0 = __floats2half2_rn(v.x, v.y);
        __half2 h1 = __floats2half2_rn(v.z, v.w);
        uint2 o = {*reinterpret_cast<uint32_t*>(&h0), *reinterpret_cast<uint32_t*>(&h1)};
        *reinterpret_cast<uint2*>(g_enc_f16 + i) = o;
    } else if (blk < P0) {
        long i = ((long)(blk - ENC_BLKS) * 256 + tid) * 4;
        float4 v = *reinterpret_cast<const float4*>(wk + i);
        uint2 H, L;
        split2h(v.x, v.y, H.x, L.x);
        split2h(v.z, v.w, H.y, L.y);
        *reinterpret_cast<uint2*>(g_wk_h + i) = H;
        *reinterpret_cast<uint2*>(g_wk_l + i) = L;
    } else if (blk < P0 + 64) {
        const int b = blk - P0;
        __shared__ int sc[256];
        int m = (mask[b * S_ + tid] != 0) ? 1 : 0;
        sc[tid] = m;
        __syncthreads();
#pragma unroll
        for (int off = 1; off < 256; off <<= 1) {
            int t = (tid >= off) ? sc[tid - off] : 0;
            __syncthreads();
            sc[tid] += t;
            __syncthreads();
        }
        int total = sc[255];
        int my = sc[tid] - m;
        if (m) g_sidx[b * S_ + my] = tid;
        if (tid >= total) g_sidx[b * S_ + tid] = 0;
        energy[b * S_ + tid] = m ? 0.f : -1e10f;
        if (tid == 0) g_scnt[b] = total;
        const int t = tok[b];
        for (int j = tid; j < E_; j += 256) {
            __half hv = __float2half_rn(emb[(long)t * E_ + j]);
            g_a0f[b * KCAT0 + j] = hv;
            g_featf[b * FDIM_ + (H_ + ENC_) + j] = hv;
        }
        for (int j = tid; j < H_; j += 256) {
            g_a0f[b * KCAT0 + (E_ + ENC_) + j] = __float2half_rn(hidden[b * H_ + j]);
            g_a1f[b * KCAT1 + H_ + j] = __float2half_rn(hidden[B_ * H_ + b * H_ + j]);
        }
    } else if (blk < P0 + 128) {
        long i = ((long)(blk - P0 - 64) * 256 + tid) * 4;
        float4 v = *reinterpret_cast<const float4*>(hidden + (long)B_ * H_ + i);
        __half2 h0 = __floats2half2_rn(v.x, v.y);
        __half2 h1 = __floats2half2_rn(v.z, v.w);
        uint2 o = {*reinterpret_cast<uint32_t*>(&h0), *reinterpret_cast<uint32_t*>(&h1)};
        *reinterpret_cast<uint2*>(g_h1f + i) = o;
    } else if (blk < P0 + 192) {
        long i = ((long)(blk - P0 - 128) * 256 + tid) * 4;
        float4 z = {0.f, 0.f, 0.f, 0.f};
        *reinterpret_cast<float4*>(query + i) = z;
    } else if (blk < P0 + 448) {
        long i = ((long)(blk - P0 - 192) * 256 + tid) * 4;
        int n = (int)(i & (G4H_ - 1));
        float4 o = {bih0[n] + bhh0[n], bih0[n + 1] + bhh0[n + 1],
                    bih0[n + 2] + bhh0[n + 2], bih0[n + 3] + bhh0[n + 3]};
        *reinterpret_cast<float4*>(gates0 + i) = o;
    } else if (blk < P0 + 704) {
        long i = ((long)(blk - P0 - 448) * 256 + tid) * 4;
        int n = (int)(i & (G4H_ - 1));
        float4 o = {bih1[n] + bhh1[n], bih1[n + 1] + bhh1[n + 1],
                    bih1[n + 2] + bhh1[n + 2], bih1[n + 3] + bhh1[n + 3]};
        *reinterpret_cast<float4*>(gates1 + i) = o;
    } else {
        long i = ((long)(blk - P0 - 704) * 1024 + tid * 4);
        int col = (int)(i % V_);
        float4 o = {bout[col], bout[col + 1], bout[col + 2], bout[col + 3]};
        *reinterpret_cast<float4*>(out_pred + i) = o;
    }
}

// ===================== global gather =========================================
__global__ void gather_kernel() {
    __shared__ int offs[B_ + 1];
    const int tid = threadIdx.x;
    if (tid == 0) {
        int acc = 0;
        for (int b = 0; b < B_; b++) { offs[b] = acc; acc += g_scnt[b]; }
        offs[B_] = acc;
        g_total = acc;
    }
    __syncthreads();
    for (int b = 0; b < B_; b++) {
        int o = offs[b], cnt = offs[b + 1] - o;
        for (int j = tid; j < cnt; j += 256)
            g_gidx[o + j] = b * S_ + g_sidx[b * S_ + j];
    }
    int total = offs[B_];
    for (int j = total + tid; j < B_ * S_; j += 256) g_gidx[j] = 0;
}

// ===================== fat-B HMMA kernel (fp16 2-term) =======================
#define WO_A_TILE 8192
#define WO_B_TILE 16384
#define WO_STAGE  (WO_A_TILE + 2 * WO_B_TILE)   // 40KB
#define WO_SMEM_BYTES (1024 + 2 * WO_STAGE)

__device__ __forceinline__ void wo_load_A(const __half* f, int lda, int c0, uint32_t stg) {
    const int tid = threadIdx.x;
#pragma unroll
    for (int i = 0; i < 2; i++) {
        int idx = tid + i * 256;
        int r = idx >> 3, cc = idx & 7;
        uint32_t off = swz(r, cc);
        CP16(stg + off, f + (long)r * lda + c0 + cc * 8);
    }
}

template<bool ATOMIC>
__global__ __launch_bounds__(256, 2)
void hmma_m64_kernel(const __half* __restrict__ a_g,
                     int Ktot,
                     const float* __restrict__ B1, int k1,
                     const float* __restrict__ B2,
                     const float* __restrict__ bias1,
                     float* __restrict__ C, int ldc, int nks) {
    extern __shared__ char smem[];
    uint32_t sb = smem_to_u32(smem);
    uint32_t tiles = (sb + 1023) & ~1023u;

    const int tid = threadIdx.x;
    const int wid = tid >> 5, lane = tid & 31;
    const int warp_m = (wid & 1) * 32;
    const int warp_n = (wid >> 1) * 32;
    const int n0 = blockIdx.x * 128;

    const int br = tid >> 1;
    const int bhalf = tid & 1;
    const int k2 = Ktot - k1;

    const int KT = Ktot / 64;
    const int kt0 = (int)blockIdx.y * (KT / nks);
    const int kt1 = kt0 + KT / nks;

    auto bptr = [&](int c0) -> const float* {
        return (c0 < k1) ? B1 + (long)(n0 + br) * k1 + c0 + bhalf * 32
                         : B2 + (long)(n0 + br) * k2 + (c0 - k1) + bhalf * 32;
    };

    float c[2][4][4];
#pragma unroll
    for (int i = 0; i < 2; i++)
#pragma unroll
        for (int j = 0; j < 4; j++)
#pragma unroll
            for (int k = 0; k < 4; k++) c[i][j][k] = 0.f;

    wo_load_A(a_g, Ktot, kt0 * 64, tiles + (kt0 & 1) * WO_STAGE);
    CP_COMMIT();

    for (int kt = kt0; kt < kt1; kt++) {
        uint32_t stg = tiles + (kt & 1) * WO_STAGE;
        if (kt + 1 < kt1) {
            wo_load_A(a_g, Ktot, (kt + 1) * 64, tiles + ((kt + 1) & 1) * WO_STAGE);
            CP_COMMIT();
        }
        uint32_t Bh = stg + WO_A_TILE, Bl = Bh + WO_B_TILE;
        const float* w = bptr(kt * 64);
#pragma unroll
        for (int j = 0; j < 4; j++) {
            float4 v0 = *reinterpret_cast<const float4*>(w + j * 8);
            float4 v1 = *reinterpret_cast<const float4*>(w + j * 8 + 4);
            uint4 Hq, Lq;
            split2h(v0.x, v0.y, Hq.x, Lq.x);
            split2h(v0.z, v0.w, Hq.y, Lq.y);
            split2h(v1.x, v1.y, Hq.z, Lq.z);
            split2h(v1.z, v1.w, Hq.w, Lq.w);
            uint32_t off = swz(br, bhalf * 4 + j);
            STS128(Bh + off, Hq.x, Hq.y, Hq.z, Hq.w);
            STS128(Bl + off, Lq.x, Lq.y, Lq.z, Lq.w);
        }
        if (kt + 1 < kt1) cp_wait<1>(); else cp_wait<0>();
        __syncthreads();
        {
            const uint32_t Ah = stg;
            const int lm = lane & 15, lh = lane >> 4;
#pragma unroll
            for (int ks = 0; ks < 4; ks++) {
                const int ch = ks * 2 + lh;
                uint32_t ah[2][4];
#pragma unroll
                for (int mf = 0; mf < 2; mf++) {
                    uint32_t off = swz(warp_m + mf * 16 + lm, ch);
                    ldmx4(Ah + off, ah[mf]);
                }
                uint32_t bb[2][4];
#pragma unroll
                for (int nf2 = 0; nf2 < 2; nf2++) {
                    uint32_t off = swz(warp_n + nf2 * 16 + lm, ch);
                    ldmx4(Bh + off, bb[nf2]);
                }
#pragma unroll
                for (int nf2 = 0; nf2 < 2; nf2++)
#pragma unroll
                    for (int mf = 0; mf < 2; mf++) {
                        mma16816h(c[mf][nf2 * 2 + 0], ah[mf], bb[nf2][0], bb[nf2][2]);
                        mma16816h(c[mf][nf2 * 2 + 1], ah[mf], bb[nf2][1], bb[nf2][3]);
                    }
#pragma unroll
                for (int nf2 = 0; nf2 < 2; nf2++) {
                    uint32_t off = swz(warp_n + nf2 * 16 + lm, ch);
                    ldmx4(Bl + off, bb[nf2]);
                }
#pragma unroll
                for (int nf2 = 0; nf2 < 2; nf2++)
#pragma unroll
                    for (int mf = 0; mf < 2; mf++) {
                        mma16816h(c[mf][nf2 * 2 + 0], ah[mf], bb[nf2][0], bb[nf2][2]);
                        mma16816h(c[mf][nf2 * 2 + 1], ah[mf], bb[nf2][1], bb[nf2][3]);
                    }
            }
        }
        __syncthreads();
    }

#pragma unroll
    for (int mf = 0; mf < 2; mf++)
#pragma unroll
        for (int nf = 0; nf < 4; nf++) {
            int col = n0 + warp_n + nf * 8 + (lane & 3) * 2;
            int r0 = warp_m + mf * 16 + (lane >> 2);
            if (ATOMIC) {
                atomicAdd(&C[(long)r0 * ldc + col],           c[mf][nf][0] * INVWK);
                atomicAdd(&C[(long)r0 * ldc + col + 1],       c[mf][nf][1] * INVWK);
                atomicAdd(&C[(long)(r0 + 8) * ldc + col],     c[mf][nf][2] * INVWK);
                atomicAdd(&C[(long)(r0 + 8) * ldc + col + 1], c[mf][nf][3] * INVWK);
            } else {
                float b0 = 0.f, b1 = 0.f;
                if (bias1) { b0 = bias1[col]; b1 = bias1[col + 1]; }
                float2 o0 = {c[mf][nf][0] * INVWK + b0, c[mf][nf][1] * INVWK + b1};
                float2 o1 = {c[mf][nf][2] * INVWK + b0, c[mf][nf][3] * INVWK + b1};
                *reinterpret_cast<float2*>(C + (long)r0 * ldc + col) = o0;
                *reinterpret_cast<float2*>(C + (long)(r0 + 8) * ldc + col) = o1;
            }
        }
}

// ===================== energy: fp16 2-term, 256x64 tiles, occ=2 ==============
// block = 256 gathered rows x 64 h-cols; warp tile 64x32 (4 mf x 4 nf).
// stage = A(32KB) + Bh(8KB) + Bl(8KB) = 48KB; 2 stages -> 2 CTAs/SM.
#define EN_AT 32768
#define EN_BT 8192
#define EN_STAGE (EN_AT + 2 * EN_BT)        // 48KB
#define EN_SMEM_BYTES (2048 + 2 * EN_STAGE) // ~98KB

__global__ __launch_bounds__(256, 2)
void energy_f16_kernel(const __half* __restrict__ ef,
                       const __half* __restrict__ wh,
                       const __half* __restrict__ wl,
                       const float* __restrict__ vvec,
                       const float* __restrict__ query,
                       float* __restrict__ energy) {
    const int total = g_total;
    const int mt = (int)blockIdx.y * 256;
    if (mt >= total) return;

    extern __shared__ char smem[];
    uint32_t sb = smem_to_u32(smem);
    uint32_t tiles = (sb + 2048 + 1023) & ~1023u;

    const int tid = threadIdx.x;
    const int wid = tid >> 5, lane = tid & 31;
    const int warp_m = (wid & 3) * 64;     // 4 m-positions x 64 rows
    const int warp_n = (wid >> 2) * 32;    // 2 n-positions x 32 cols
    const int n0 = blockIdx.x * 64;

    float* vs = (float*)smem;              // 64 floats
    int*   sid = (int*)(vs + 64);          // 256 ints
    if (tid < 64) vs[tid] = vvec[n0 + tid];
    sid[tid] = g_gidx[mt + tid];
    __syncthreads();

    // hoisted load offsets: A 8 chunks/thread, B 2 rows/thread x 2 halves
    const int rb = tid >> 3, cc8 = (tid & 7) * 8;
    uint32_t aoff[8], soffA[8];
#pragma unroll
    for (int i = 0; i < 8; i++) {
        int r = rb + 32 * i;
        soffA[i] = swz(r, tid & 7);
        aoff[i]  = (uint32_t)sid[r] * ENC_ + cc8;
    }
    uint32_t boff[2], soffB[2];
#pragma unroll
    for (int j = 0; j < 2; j++) {
        int r = rb + 32 * j;
        soffB[j] = swz(r, tid & 7);
        boff[j]  = (uint32_t)(n0 + r) * ENC_ + cc8;
    }

    float c[4][4][4];
#pragma unroll
    for (int i = 0; i < 4; i++)
#pragma unroll
        for (int j = 0; j < 4; j++)
#pragma unroll
            for (int k = 0; k < 4; k++) c[i][j][k] = 0.f;

    auto load_stage = [&](int c0v, uint32_t stg) {
#pragma unroll
        for (int i = 0; i < 8; i++)
            CP16(stg + soffA[i], ef + aoff[i] + c0v);
#pragma unroll
        for (int j = 0; j < 2; j++) {
            CP16(stg + EN_AT + soffB[j],         wh + boff[j] + c0v);
            CP16(stg + EN_AT + EN_BT + soffB[j], wl + boff[j] + c0v);
        }
    };

    load_stage(0, tiles);
    CP_COMMIT();

    const int KT = ENC_ / 64;   // 16
    for (int kt = 0; kt < KT; kt++) {
        uint32_t stg = tiles + (kt & 1) * EN_STAGE;
        if (kt + 1 < KT) {
            load_stage((kt + 1) * 64, tiles + ((kt + 1) & 1) * EN_STAGE);
            CP_COMMIT();
            cp_wait<1>();
        } else {
            cp_wait<0>();
        }
        __syncthreads();
        {
            const uint32_t A = stg;
            const uint32_t Bh = stg + EN_AT, Bl = stg + EN_AT + EN_BT;
            const int lm = lane & 15, lh = lane >> 4;
#pragma unroll
            for (int ks = 0; ks < 4; ks++) {
                const int ch = ks * 2 + lh;
                uint32_t af[4][4];
#pragma unroll
                for (int mf = 0; mf < 4; mf++) {
                    uint32_t off = swz(warp_m + mf * 16 + lm, ch);
                    ldmx4(A + off, af[mf]);
                }
                uint32_t bb[2][4];
#pragma unroll
                for (int nf2 = 0; nf2 < 2; nf2++) {
                    uint32_t off = swz(warp_n + nf2 * 16 + lm, ch);
                    ldmx4(Bh + off, bb[nf2]);
                }
#pragma unroll
                for (int nf2 = 0; nf2 < 2; nf2++)
#pragma unroll
                    for (int mf = 0; mf < 4; mf++) {
                        mma16816h(c[mf][nf2 * 2 + 0], af[mf], bb[nf2][0], bb[nf2][2]);
                        mma16816h(c[mf][nf2 * 2 + 1], af[mf], bb[nf2][1], bb[nf2][3]);
                    }
#pragma unroll
                for (int nf2 = 0; nf2 < 2; nf2++) {
                    uint32_t off = swz(warp_n + nf2 * 16 + lm, ch);
                    ldmx4(Bl + off, bb[nf2]);
                }
#pragma unroll
                for (int nf2 = 0; nf2 < 2; nf2++)
#pragma unroll
                    for (int mf = 0; mf < 4; mf++) {
                        mma16816h(c[mf][nf2 * 2 + 0], af[mf], bb[nf2][0], bb[nf2][2]);
                        mma16816h(c[mf][nf2 * 2 + 1], af[mf], bb[nf2][1], bb[nf2][3]);
                    }
            }
        }
        __syncthreads();
    }

    // epilogue: keys = c/2048; energy += v*tanh(q + keys); reduce 32 cols/warp
#pragma unroll
    for (int mf = 0; mf < 4; mf++) {
        int rl = warp_m + mf * 16 + (lane >> 2);
        int rh = rl + 8;
        int gl = sid[rl], gh = sid[rh];
        const float* ql = query + (long)(gl >> 8) * H_ + n0;
        const float* qh = query + (long)(gh >> 8) * H_ + n0;
        float s_lo = 0.f, s_hi = 0.f;
#pragma unroll
        for (int nf = 0; nf < 4; nf++) {
            int col = warp_n + nf * 8 + (lane & 3) * 2;
            float v0 = vs[col], v1 = vs[col + 1];
            s_lo += v0 * tanhf(ql[col] + c[mf][nf][0] * INVWK)
                  + v1 * tanhf(ql[col + 1] + c[mf][nf][1] * INVWK);
            s_hi += v0 * tanhf(qh[col] + c[mf][nf][2] * INVWK)
                  + v1 * tanhf(qh[col + 1] + c[mf][nf][3] * INVWK);
        }
        s_lo += __shfl_xor_sync(0xffffffff, s_lo, 1);
        s_lo += __shfl_xor_sync(0xffffffff, s_lo, 2);
        s_hi += __shfl_xor_sync(0xffffffff, s_hi, 1);
        s_hi += __shfl_xor_sync(0xffffffff, s_hi, 2);
        if ((lane & 3) == 0) {
            if (mt + rl < total) atomicAdd(&energy[gl], s_lo);
            if (mt + rh < total) atomicAdd(&energy[gh], s_hi);
        }
    }
}

// ===================== fused softmax + compacted context =====================
__global__ void softmax_context_kernel(const float* __restrict__ energy,
                                       const float* __restrict__ enc,
                                       float* __restrict__ out_attn) {
    __shared__ float red[256];
    __shared__ float w[256];
    __shared__ int sid[256];
    __shared__ int cnts;
    const int b = blockIdx.x;
    const int tid = threadIdx.x;

    float val = energy[b * S_ + tid];
    red[tid] = val;
    sid[tid] = g_sidx[b * S_ + tid];
    if (tid == 0) cnts = g_scnt[b];
    __syncthreads();
#pragma unroll
    for (int off = 128; off > 0; off >>= 1) {
        if (tid < off) red[tid] = fmaxf(red[tid], red[tid + off]);
        __syncthreads();
    }
    float mx = red[0];
    __syncthreads();
    float ex = expf(val - mx);
    red[tid] = ex;
    __syncthreads();
#pragma unroll
    for (int off = 128; off > 0; off >>= 1) {
        if (tid < off) red[tid] += red[tid + off];
        __syncthreads();
    }
    float aw = ex / red[0];
    if (blockIdx.y == 0) out_attn[b * S_ + tid] = aw;
    w[tid] = aw;
    __syncthreads();

    const int cnt = cnts;
    const int col = blockIdx.y * 256 + tid;
    const float* eb = enc + (long)b * S_ * ENC_;
    float a0 = 0.f, a1 = 0.f, a2 = 0.f, a3 = 0.f;
    int j = 0;
    for (; j + 4 <= cnt; j += 4) {
        a0 = fmaf(w[sid[j]],     eb[(long)sid[j] * ENC_ + col],     a0);
        a1 = fmaf(w[sid[j + 1]], eb[(long)sid[j + 1] * ENC_ + col], a1);
        a2 = fmaf(w[sid[j + 2]], eb[(long)sid[j + 2] * ENC_ + col], a2);
        a3 = fmaf(w[sid[j + 3]], eb[(long)sid[j + 3] * ENC_ + col], a3);
    }
    for (; j < cnt; j++)
        a0 = fmaf(w[sid[j]], eb[(long)sid[j] * ENC_ + col], a0);
    float acc = (a0 + a1) + (a2 + a3);
    __half hv = __float2half_rn(acc);
    g_a0f[b * KCAT0 + E_ + col] = hv;
    g_featf[b * FDIM_ + H_ + col] = hv;
}

// ===================== LSTM pointwise ========================================
__global__ void lstm_kernel(const float* __restrict__ gates,
                            const float* __restrict__ c_prev,
                            float* __restrict__ c_out,
                            float* __restrict__ h_out_f32,
                            __half* __restrict__ hb,
                            int sb) {
    const int b = blockIdx.x;
    const int idx = blockIdx.y * 256 + threadIdx.x;
    float gi = gates[b * G4H_ + idx];
    float gf = gates[b * G4H_ + H_ + idx];
    float gg = gates[b * G4H_ + 2 * H_ + idx];
    float go = gates[b * G4H_ + 3 * H_ + idx];
    float c  = c_prev[b * H_ + idx];
    float si = 1.f / (1.f + expf(-gi));
    float sf = 1.f / (1.f + expf(-gf));
    float so = 1.f / (1.f + expf(-go));
    float cn = sf * c + si * tanhf(gg);
    float hn = so * tanhf(cn);
    c_out[b * H_ + idx]     = cn;
    h_out_f32[b * H_ + idx] = hn;
    hb[b * sb + idx] = __float2half_rn(hn);
}

// ===================== launch ================================================
extern "C" void kernel_launch(void* const* d_in, const int* in_sizes, int n_in,
                              void* d_out, int out_size) {
    const int*   tok    = (const int*)  d_in[0];
    const float* hidden = (const float*)d_in[1];
    const float* cell   = (const float*)d_in[2];
    const float* enc    = (const float*)d_in[3];
    const int*   mask   = (const int*)  d_in[4];
    const float* emb    = (const float*)d_in[5];
    const float* Wq     = (const float*)d_in[6];
    const float* Wk     = (const float*)d_in[7];
    const float* v      = (const float*)d_in[8];
    const float* Wih0   = (const float*)d_in[9];
    const float* Whh0   = (const float*)d_in[10];
    const float* bih0   = (const float*)d_in[11];
    const float* bhh0   = (const float*)d_in[12];
    const float* Wih1   = (const float*)d_in[13];
    const float* Whh1   = (const float*)d_in[14];
    const float* bih1   = (const float*)d_in[15];
    const float* bhh1   = (const float*)d_in[16];
    const float* Wout   = (const float*)d_in[17];
    const float* bout   = (const float*)d_in[18];

    float* out      = (float*)d_out;
    float* out_pred = out;
    float* out_hid  = out + (long)B_ * V_;
    float* out_cell = out_hid + 2 * B_ * H_;
    float* out_attn = out_cell + 2 * B_ * H_;

    void* sp = nullptr;
    cudaGetSymbolAddress(&sp, g_scratch);
    float* scratch = (float*)sp;
    float* query  = scratch + OFF_QUERY;
    float* gates0 = scratch + OFF_GATES0;
    float* gates1 = scratch + OFF_GATES1;
    float* energy = scratch + OFF_ENERGY;

    void *p_ef, *p_wh, *p_wl, *p_h1, *p_a0, *p_a1, *p_ft;
    cudaGetSymbolAddress(&p_ef, g_enc_f16);
    cudaGetSymbolAddress(&p_wh, g_wk_h);
    cudaGetSymbolAddress(&p_wl, g_wk_l);
    cudaGetSymbolAddress(&p_h1, g_h1f);
    cudaGetSymbolAddress(&p_a0, g_a0f);
    cudaGetSymbolAddress(&p_a1, g_a1f);
    cudaGetSymbolAddress(&p_ft, g_featf);

    cudaFuncSetAttribute(hmma_m64_kernel<false>, cudaFuncAttributeMaxDynamicSharedMemorySize, WO_SMEM_BYTES);
    cudaFuncSetAttribute(hmma_m64_kernel<true>,  cudaFuncAttributeMaxDynamicSharedMemorySize, WO_SMEM_BYTES);
    cudaFuncSetAttribute(energy_f16_kernel,      cudaFuncAttributeMaxDynamicSharedMemorySize, EN_SMEM_BYTES);

    // 1. fused prep: enc/Wk fp16 conversion + mask compact + inits + scatters
    prep_kernel<<<PREP_BLKS, 256>>>(enc, Wk, mask, hidden, tok, emb,
                                    bih0, bhh0, bih1, bhh1, bout,
                                    energy, query, gates0, gates1, out_pred);

    // 2. global compaction
    gather_kernel<<<1, 256>>>();

    // 3. query = hidden[1] @ Wq^T (fp16 2-term, K-split 4, atomic)
    hmma_m64_kernel<true><<<dim3(H_ / 128, 4), 256, WO_SMEM_BYTES>>>(
        (const __half*)p_h1, H_, Wq, H_, Wq, nullptr, query, H_, 4);

    // 4. energy (fp16 2-term, 256x64 tiles, occupancy 2)
    energy_f16_kernel<<<dim3(H_ / 64, (B_ * S_) / 256), 256, EN_SMEM_BYTES>>>(
        (const __half*)p_ef, (const __half*)p_wh, (const __half*)p_wl,
        v, query, energy);

    // 5. fused masked softmax + compacted context
    softmax_context_kernel<<<dim3(B_, 4), 256>>>(energy, enc, out_attn);

    // 6. layer-0 gates + LSTM
    hmma_m64_kernel<true><<<dim3(G4H_ / 128, 4), 256, WO_SMEM_BYTES>>>(
        (const __half*)p_a0, KCAT0, Wih0, E_ + ENC_, Whh0, nullptr, gates0, G4H_, 4);
    lstm_kernel<<<dim3(B_, H_ / 256), 256>>>(gates0, cell, out_cell, out_hid,
                                             (__half*)p_a1, KCAT1);

    // 7. layer-1 gates + LSTM
    hmma_m64_kernel<true><<<dim3(G4H_ / 128, 4), 256, WO_SMEM_BYTES>>>(
        (const __half*)p_a1, KCAT1, Wih1, H_, Whh1, nullptr, gates1, G4H_, 4);
    lstm_kernel<<<dim3(B_, H_ / 256), 256>>>(gates1, cell + B_ * H_, out_cell + B_ * H_,
                                             out_hid + B_ * H_, (__half*)p_ft, FDIM_);

    // 8. prediction = feat @ Wout^T + bout (fp16 2-term, K-split 2, atomic)
    hmma_m64_kernel<true><<<dim3(V_ / 128, 2), 256, WO_SMEM_BYTES>>>(
        (const __half*)p_ft, FDIM_, Wout, FDIM_, Wout, nullptr, out_pred, V_, 2);
}

// round 11
// speedup vs baseline: 1.4736x; 1.4736x over previous
#include <cuda_runtime.h>
#include <cuda_bf16.h>
#include <cuda_fp16.h>
#include <math.h>
#include <stdint.h>

#define B_   64
#define S_   256
#define H_   1024
#define ENC_ 1024
#define E_   512
#define V_   32000
#define FDIM_ (H_ + ENC_ + E_)   // 2560
#define G4H_  (4 * H_)           // 4096
#define KCAT0 2560
#define KCAT1 2048
#define WKSCALE 2048.0f
#define INVWK   (1.0f / 2048.0f)

// ---------------- scratch ----------------------------------------------------
#define OFF_QUERY   0
#define OFF_GATES0  (OFF_QUERY + B_ * H_)
#define OFF_GATES1  (OFF_GATES0 + B_ * G4H_)
#define OFF_ENERGY  (OFF_GATES1 + B_ * G4H_)
#define SCRATCH_TOTAL (OFF_ENERGY + B_ * S_)

__device__ __align__(16) float g_scratch[SCRATCH_TOTAL];
__device__ int g_sidx[B_ * S_];
__device__ int g_scnt[B_];
__device__ int g_gidx[B_ * S_];
__device__ int g_total;

// fp16 buffers
__device__ __align__(16) __half g_enc_f16[(long)B_ * S_ * ENC_];
__device__ __align__(16) __half g_wk_h[H_ * ENC_];
__device__ __align__(16) __half g_wk_l[H_ * ENC_];
__device__ __align__(16) __half g_h1f[B_ * H_];
__device__ __align__(16) __half g_a0f[B_ * KCAT0];
__device__ __align__(16) __half g_a1f[B_ * KCAT1];
__device__ __align__(16) __half g_featf[B_ * FDIM_];

// ===================== low-level helpers =====================================
__device__ __forceinline__ uint32_t smem_to_u32(const void* p) {
    uint32_t a;
    asm("{ .reg .u64 t; cvta.to.shared.u64 t, %1; cvt.u32.u64 %0, t; }" : "=r"(a) : "l"(p));
    return a;
}

#define CP16(dst_u32, src_ptr) \
    asm volatile("cp.async.cg.shared.global [%0], [%1], 16;" :: "r"(dst_u32), "l"(src_ptr))
#define CP_COMMIT() asm volatile("cp.async.commit_group;" ::: "memory")
template<int N> __device__ __forceinline__ void cp_wait() {
    asm volatile("cp.async.wait_group %0;" :: "n"(N) : "memory");
}

__device__ __forceinline__ void ldmx4(uint32_t addr, uint32_t r[4]) {
    asm volatile("ldmatrix.sync.aligned.m8n8.x4.shared.b16 {%0,%1,%2,%3}, [%4];"
        : "=r"(r[0]), "=r"(r[1]), "=r"(r[2]), "=r"(r[3]) : "r"(addr));
}

__device__ __forceinline__ void mma16816h(float* c, const uint32_t a[4],
                                          uint32_t b0, uint32_t b1) {
    asm volatile("mma.sync.aligned.m16n8k16.row.col.f32.f16.f16.f32 "
        "{%0,%1,%2,%3}, {%4,%5,%6,%7}, {%8,%9}, {%0,%1,%2,%3};"
        : "+f"(c[0]), "+f"(c[1]), "+f"(c[2]), "+f"(c[3])
        : "r"(a[0]), "r"(a[1]), "r"(a[2]), "r"(a[3]), "r"(b0), "r"(b1));
}

#define STS128(addr, a, b, c, d) \
    asm volatile("st.shared.v4.b32 [%0], {%1,%2,%3,%4};" \
        :: "r"(addr), "r"(a), "r"(b), "r"(c), "r"(d) : "memory")

__device__ __forceinline__ uint32_t swz(int row, int chunk16) {
    return (uint32_t)(row * 128 + ((chunk16 ^ (row & 7)) * 16));
}

// fp16 scaled split: w*2048 = hi + lo
__device__ __forceinline__ void split2h(float a, float b, uint32_t& hi, uint32_t& lo) {
    float as = a * WKSCALE, bs = b * WKSCALE;
    __half2 h2 = __floats2half2_rn(as, bs);
    float ra = as - __half2float(__low2half(h2));
    float rb = bs - __half2float(__high2half(h2));
    __half2 l2 = __floats2half2_rn(ra, rb);
    hi = *reinterpret_cast<uint32_t*>(&h2);
    lo = *reinterpret_cast<uint32_t*>(&l2);
}

// ===================== mega prep+split kernel ================================
#define ENC_BLKS ((B_ * S_ * ENC_) / 1024)   // 16384
#define WK_BLKS  ((H_ * ENC_) / 1024)        // 1024
#define P0 (ENC_BLKS + WK_BLKS)              // 17408
#define PREP_BLKS (P0 + 64 + 64 + 64 + 256 + 256 + 2000)

__global__ void prep_kernel(const float* __restrict__ enc,
                            const float* __restrict__ wk,
                            const int* __restrict__ mask,
                            const float* __restrict__ hidden,
                            const int* __restrict__ tok,
                            const float* __restrict__ emb,
                            const float* __restrict__ bih0,
                            const float* __restrict__ bhh0,
                            const float* __restrict__ bih1,
                            const float* __restrict__ bhh1,
                            const float* __restrict__ bout,
                            float* __restrict__ energy,
                            float* __restrict__ query,
                            float* __restrict__ gates0,
                            float* __restrict__ gates1,
                            float* __restrict__ out_pred) {
    const int tid = threadIdx.x;
    const int blk = blockIdx.x;
    if (blk < ENC_BLKS) {
        long i = ((long)blk * 256 + tid) * 4;
        float4 v = *reinterpret_cast<const float4*>(enc + i);
        __half2 h0 = __floats2half2_rn(v.x, v.y);
        __half2 h1 = __floats2half2_rn(v.z, v.w);
        uint2 o = {*reinterpret_cast<uint32_t*>(&h0), *reinterpret_cast<uint32_t*>(&h1)};
        *reinterpret_cast<uint2*>(g_enc_f16 + i) = o;
    } else if (blk < P0) {
        long i = ((long)(blk - ENC_BLKS) * 256 + tid) * 4;
        float4 v = *reinterpret_cast<const float4*>(wk + i);
        uint2 H, L;
        split2h(v.x, v.y, H.x, L.x);
        split2h(v.z, v.w, H.y, L.y);
        *reinterpret_cast<uint2*>(g_wk_h + i) = H;
        *reinterpret_cast<uint2*>(g_wk_l + i) = L;
    } else if (blk < P0 + 64) {
        const int b = blk - P0;
        __shared__ int sc[256];
        int m = (mask[b * S_ + tid] != 0) ? 1 : 0;
        sc[tid] = m;
        __syncthreads();
#pragma unroll
        for (int off = 1; off < 256; off <<= 1) {
            int t = (tid >= off) ? sc[tid - off] : 0;
            __syncthreads();
            sc[tid] += t;
            __syncthreads();
        }
        int total = sc[255];
        int my = sc[tid] - m;
        if (m) g_sidx[b * S_ + my] = tid;
        if (tid >= total) g_sidx[b * S_ + tid] = 0;
        energy[b * S_ + tid] = m ? 0.f : -1e10f;
        if (tid == 0) g_scnt[b] = total;
        const int t = tok[b];
        for (int j = tid; j < E_; j += 256) {
            __half hv = __float2half_rn(emb[(long)t * E_ + j]);
            g_a0f[b * KCAT0 + j] = hv;
            g_featf[b * FDIM_ + (H_ + ENC_) + j] = hv;
        }
        for (int j = tid; j < H_; j += 256) {
            g_a0f[b * KCAT0 + (E_ + ENC_) + j] = __float2half_rn(hidden[b * H_ + j]);
            g_a1f[b * KCAT1 + H_ + j] = __float2half_rn(hidden[B_ * H_ + b * H_ + j]);
        }
    } else if (blk < P0 + 128) {
        long i = ((long)(blk - P0 - 64) * 256 + tid) * 4;
        float4 v = *reinterpret_cast<const float4*>(hidden + (long)B_ * H_ + i);
        __half2 h0 = __floats2half2_rn(v.x, v.y);
        __half2 h1 = __floats2half2_rn(v.z, v.w);
        uint2 o = {*reinterpret_cast<uint32_t*>(&h0), *reinterpret_cast<uint32_t*>(&h1)};
        *reinterpret_cast<uint2*>(g_h1f + i) = o;
    } else if (blk < P0 + 192) {
        long i = ((long)(blk - P0 - 128) * 256 + tid) * 4;
        float4 z = {0.f, 0.f, 0.f, 0.f};
        *reinterpret_cast<float4*>(query + i) = z;
    } else if (blk < P0 + 448) {
        long i = ((long)(blk - P0 - 192) * 256 + tid) * 4;
        int n = (int)(i & (G4H_ - 1));
        float4 o = {bih0[n] + bhh0[n], bih0[n + 1] + bhh0[n + 1],
                    bih0[n + 2] + bhh0[n + 2], bih0[n + 3] + bhh0[n + 3]};
        *reinterpret_cast<float4*>(gates0 + i) = o;
    } else if (blk < P0 + 704) {
        long i = ((long)(blk - P0 - 448) * 256 + tid) * 4;
        int n = (int)(i & (G4H_ - 1));
        float4 o = {bih1[n] + bhh1[n], bih1[n + 1] + bhh1[n + 1],
                    bih1[n + 2] + bhh1[n + 2], bih1[n + 3] + bhh1[n + 3]};
        *reinterpret_cast<float4*>(gates1 + i) = o;
    } else {
        long i = ((long)(blk - P0 - 704) * 1024 + tid * 4);
        int col = (int)(i % V_);
        float4 o = {bout[col], bout[col + 1], bout[col + 2], bout[col + 3]};
        *reinterpret_cast<float4*>(out_pred + i) = o;
    }
}

// ===================== global gather =========================================
__global__ void gather_kernel() {
    __shared__ int offs[B_ + 1];
    const int tid = threadIdx.x;
    if (tid == 0) {
        int acc = 0;
        for (int b = 0; b < B_; b++) { offs[b] = acc; acc += g_scnt[b]; }
        offs[B_] = acc;
        g_total = acc;
    }
    __syncthreads();
    for (int b = 0; b < B_; b++) {
        int o = offs[b], cnt = offs[b + 1] - o;
        for (int j = tid; j < cnt; j += 256)
            g_gidx[o + j] = b * S_ + g_sidx[b * S_ + j];
    }
    int total = offs[B_];
    for (int j = total + tid; j < B_ * S_; j += 256) g_gidx[j] = 0;
}

// ===================== fat-B HMMA kernel (fp16 2-term) =======================
#define WO_A_TILE 8192
#define WO_B_TILE 16384
#define WO_STAGE  (WO_A_TILE + 2 * WO_B_TILE)   // 40KB
#define WO_SMEM_BYTES (1024 + 2 * WO_STAGE)

__device__ __forceinline__ void wo_load_A(const __half* f, int lda, int c0, uint32_t stg) {
    const int tid = threadIdx.x;
#pragma unroll
    for (int i = 0; i < 2; i++) {
        int idx = tid + i * 256;
        int r = idx >> 3, cc = idx & 7;
        uint32_t off = swz(r, cc);
        CP16(stg + off, f + (long)r * lda + c0 + cc * 8);
    }
}

template<bool ATOMIC>
__global__ __launch_bounds__(256, 2)
void hmma_m64_kernel(const __half* __restrict__ a_g,
                     int Ktot,
                     const float* __restrict__ B1, int k1,
                     const float* __restrict__ B2,
                     const float* __restrict__ bias1,
                     float* __restrict__ C, int ldc, int nks) {
    extern __shared__ char smem[];
    uint32_t sb = smem_to_u32(smem);
    uint32_t tiles = (sb + 1023) & ~1023u;

    const int tid = threadIdx.x;
    const int wid = tid >> 5, lane = tid & 31;
    const int warp_m = (wid & 1) * 32;
    const int warp_n = (wid >> 1) * 32;
    const int n0 = blockIdx.x * 128;

    const int br = tid >> 1;
    const int bhalf = tid & 1;
    const int k2 = Ktot - k1;

    const int KT = Ktot / 64;
    const int kt0 = (int)blockIdx.y * (KT / nks);
    const int kt1 = kt0 + KT / nks;

    auto bptr = [&](int c0) -> const float* {
        return (c0 < k1) ? B1 + (long)(n0 + br) * k1 + c0 + bhalf * 32
                         : B2 + (long)(n0 + br) * k2 + (c0 - k1) + bhalf * 32;
    };

    float c[2][4][4];
#pragma unroll
    for (int i = 0; i < 2; i++)
#pragma unroll
        for (int j = 0; j < 4; j++)
#pragma unroll
            for (int k = 0; k < 4; k++) c[i][j][k] = 0.f;

    wo_load_A(a_g, Ktot, kt0 * 64, tiles + (kt0 & 1) * WO_STAGE);
    CP_COMMIT();

    for (int kt = kt0; kt < kt1; kt++) {
        uint32_t stg = tiles + (kt & 1) * WO_STAGE;
        if (kt + 1 < kt1) {
            wo_load_A(a_g, Ktot, (kt + 1) * 64, tiles + ((kt + 1) & 1) * WO_STAGE);
            CP_COMMIT();
        }
        uint32_t Bh = stg + WO_A_TILE, Bl = Bh + WO_B_TILE;
        const float* w = bptr(kt * 64);
#pragma unroll
        for (int j = 0; j < 4; j++) {
            float4 v0 = *reinterpret_cast<const float4*>(w + j * 8);
            float4 v1 = *reinterpret_cast<const float4*>(w + j * 8 + 4);
            uint4 Hq, Lq;
            split2h(v0.x, v0.y, Hq.x, Lq.x);
            split2h(v0.z, v0.w, Hq.y, Lq.y);
            split2h(v1.x, v1.y, Hq.z, Lq.z);
            split2h(v1.z, v1.w, Hq.w, Lq.w);
            uint32_t off = swz(br, bhalf * 4 + j);
            STS128(Bh + off, Hq.x, Hq.y, Hq.z, Hq.w);
            STS128(Bl + off, Lq.x, Lq.y, Lq.z, Lq.w);
        }
        if (kt + 1 < kt1) cp_wait<1>(); else cp_wait<0>();
        __syncthreads();
        {
            const uint32_t Ah = stg;
            const int lm = lane & 15, lh = lane >> 4;
#pragma unroll
            for (int ks = 0; ks < 4; ks++) {
                const int ch = ks * 2 + lh;
                uint32_t ah[2][4];
#pragma unroll
                for (int mf = 0; mf < 2; mf++) {
                    uint32_t off = swz(warp_m + mf * 16 + lm, ch);
                    ldmx4(Ah + off, ah[mf]);
                }
                uint32_t bb[2][4];
#pragma unroll
                for (int nf2 = 0; nf2 < 2; nf2++) {
                    uint32_t off = swz(warp_n + nf2 * 16 + lm, ch);
                    ldmx4(Bh + off, bb[nf2]);
                }
#pragma unroll
                for (int nf2 = 0; nf2 < 2; nf2++)
#pragma unroll
                    for (int mf = 0; mf < 2; mf++) {
                        mma16816h(c[mf][nf2 * 2 + 0], ah[mf], bb[nf2][0], bb[nf2][2]);
                        mma16816h(c[mf][nf2 * 2 + 1], ah[mf], bb[nf2][1], bb[nf2][3]);
                    }
#pragma unroll
                for (int nf2 = 0; nf2 < 2; nf2++) {
                    uint32_t off = swz(warp_n + nf2 * 16 + lm, ch);
                    ldmx4(Bl + off, bb[nf2]);
                }
#pragma unroll
                for (int nf2 = 0; nf2 < 2; nf2++)
#pragma unroll
                    for (int mf = 0; mf < 2; mf++) {
                        mma16816h(c[mf][nf2 * 2 + 0], ah[mf], bb[nf2][0], bb[nf2][2]);
                        mma16816h(c[mf][nf2 * 2 + 1], ah[mf], bb[nf2][1], bb[nf2][3]);
                    }
            }
        }
        __syncthreads();
    }

#pragma unroll
    for (int mf = 0; mf < 2; mf++)
#pragma unroll
        for (int nf = 0; nf < 4; nf++) {
            int col = n0 + warp_n + nf * 8 + (lane & 3) * 2;
            int r0 = warp_m + mf * 16 + (lane >> 2);
            if (ATOMIC) {
                atomicAdd(&C[(long)r0 * ldc + col],           c[mf][nf][0] * INVWK);
                atomicAdd(&C[(long)r0 * ldc + col + 1],       c[mf][nf][1] * INVWK);
                atomicAdd(&C[(long)(r0 + 8) * ldc + col],     c[mf][nf][2] * INVWK);
                atomicAdd(&C[(long)(r0 + 8) * ldc + col + 1], c[mf][nf][3] * INVWK);
            } else {
                float b0 = 0.f, b1 = 0.f;
                if (bias1) { b0 = bias1[col]; b1 = bias1[col + 1]; }
                float2 o0 = {c[mf][nf][0] * INVWK + b0, c[mf][nf][1] * INVWK + b1};
                float2 o1 = {c[mf][nf][2] * INVWK + b0, c[mf][nf][3] * INVWK + b1};
                *reinterpret_cast<float2*>(C + (long)r0 * ldc + col) = o0;
                *reinterpret_cast<float2*>(C + (long)(r0 + 8) * ldc + col) = o1;
            }
        }
}

// ===================== energy: fp16 2-term, 256-row super-tiles (r9) =========
#define EN_T 16384
#define EN_STAGE (4 * EN_T)
#define EN_SMEM_BYTES (2048 + 2 * EN_STAGE)

__global__ __launch_bounds__(256, 1)
void energy_f16_kernel(const __half* __restrict__ ef,
                       const __half* __restrict__ wh,
                       const __half* __restrict__ wl,
                       const float* __restrict__ vvec,
                       const float* __restrict__ query,
                       float* __restrict__ energy) {
    const int total = g_total;
    const int mt = (int)blockIdx.y * 256;
    if (mt >= total) return;

    extern __shared__ char smem[];
    uint32_t sb = smem_to_u32(smem);
    uint32_t tiles = (sb + 2048 + 1023) & ~1023u;

    const int tid = threadIdx.x;
    const int wid = tid >> 5, lane = tid & 31;
    const int warp_m = (wid & 3) * 32;
    const int warp_n = (wid >> 2) * 64;
    const int n0 = blockIdx.x * 128;

    float* vs = (float*)smem;
    int*   sid = (int*)(vs + 128);
    if (tid < 128) vs[tid] = vvec[n0 + tid];
    sid[tid] = g_gidx[mt + tid];
    __syncthreads();

    const int rb = tid >> 3, cc8 = (tid & 7) * 8;
    uint32_t a0off[4], a1off[4], boff[4], soffs[4];
#pragma unroll
    for (int i = 0; i < 4; i++) {
        int r = rb + 32 * i;
        soffs[i] = swz(r, tid & 7);
        a0off[i] = (uint32_t)sid[r] * ENC_ + cc8;
        a1off[i] = (uint32_t)sid[r + 128] * ENC_ + cc8;
        boff[i]  = (uint32_t)(n0 + r) * ENC_ + cc8;
    }

    float c0[2][8][4], c1[2][8][4];
#pragma unroll
    for (int i = 0; i < 2; i++)
#pragma unroll
        for (int j = 0; j < 8; j++)
#pragma unroll
            for (int k = 0; k < 4; k++) { c0[i][j][k] = 0.f; c1[i][j][k] = 0.f; }

    auto load_stage = [&](int c0v, uint32_t stg) {
#pragma unroll
        for (int i = 0; i < 4; i++) {
            CP16(stg + soffs[i],            ef + a0off[i] + c0v);
            CP16(stg + EN_T + soffs[i],     ef + a1off[i] + c0v);
            CP16(stg + 2 * EN_T + soffs[i], wh + boff[i] + c0v);
            CP16(stg + 3 * EN_T + soffs[i], wl + boff[i] + c0v);
        }
    };

    load_stage(0, tiles);
    CP_COMMIT();

    const int KT = ENC_ / 64;
    for (int kt = 0; kt < KT; kt++) {
        uint32_t stg = tiles + (kt & 1) * EN_STAGE;
        if (kt + 1 < KT) {
            load_stage((kt + 1) * 64, tiles + ((kt + 1) & 1) * EN_STAGE);
            CP_COMMIT();
            cp_wait<1>();
        } else {
            cp_wait<0>();
        }
        __syncthreads();
        {
            const uint32_t A0 = stg, A1 = stg + EN_T;
            const uint32_t Bh = stg + 2 * EN_T, Bl = stg + 3 * EN_T;
            const int lm = lane & 15, lh = lane >> 4;
#pragma unroll
            for (int ks = 0; ks < 4; ks++) {
                const int ch = ks * 2 + lh;
                uint32_t a0[2][4], a1[2][4];
#pragma unroll
                for (int mf = 0; mf < 2; mf++) {
                    uint32_t off = swz(warp_m + mf * 16 + lm, ch);
                    ldmx4(A0 + off, a0[mf]);
                    ldmx4(A1 + off, a1[mf]);
                }
                uint32_t bb[4][4];
#pragma unroll
                for (int nf2 = 0; nf2 < 4; nf2++) {
                    uint32_t off = swz(warp_n + nf2 * 16 + lm, ch);
                    ldmx4(Bh + off, bb[nf2]);
                }
#pragma unroll
                for (int nf2 = 0; nf2 < 4; nf2++)
#pragma unroll
                    for (int mf = 0; mf < 2; mf++) {
                        mma16816h(c0[mf][nf2 * 2 + 0], a0[mf], bb[nf2][0], bb[nf2][2]);
                        mma16816h(c0[mf][nf2 * 2 + 1], a0[mf], bb[nf2][1], bb[nf2][3]);
                        mma16816h(c1[mf][nf2 * 2 + 0], a1[mf], bb[nf2][0], bb[nf2][2]);
                        mma16816h(c1[mf][nf2 * 2 + 1], a1[mf], bb[nf2][1], bb[nf2][3]);
                    }
#pragma unroll
                for (int nf2 = 0; nf2 < 4; nf2++) {
                    uint32_t off = swz(warp_n + nf2 * 16 + lm, ch);
                    ldmx4(Bl + off, bb[nf2]);
                }
#pragma unroll
                for (int nf2 = 0; nf2 < 4; nf2++)
#pragma unroll
                    for (int mf = 0; mf < 2; mf++) {
                        mma16816h(c0[mf][nf2 * 2 + 0], a0[mf], bb[nf2][0], bb[nf2][2]);
                        mma16816h(c0[mf][nf2 * 2 + 1], a0[mf], bb[nf2][1], bb[nf2][3]);
                        mma16816h(c1[mf][nf2 * 2 + 0], a1[mf], bb[nf2][0], bb[nf2][2]);
                        mma16816h(c1[mf][nf2 * 2 + 1], a1[mf], bb[nf2][1], bb[nf2][3]);
                    }
            }
        }
        __syncthreads();
    }

#pragma unroll
    for (int t = 0; t < 2; t++) {
#pragma unroll
        for (int mf = 0; mf < 2; mf++) {
            int rl = t * 128 + warp_m + mf * 16 + (lane >> 2);
            int rh = rl + 8;
            int gl = sid[rl], gh = sid[rh];
            const float* ql = query + (long)(gl >> 8) * H_ + n0;
            const float* qh = query + (long)(gh >> 8) * H_ + n0;
            float s_lo = 0.f, s_hi = 0.f;
#pragma unroll
            for (int nf = 0; nf < 8; nf++) {
                int col = warp_n + nf * 8 + (lane & 3) * 2;
                float v0 = vs[col], v1 = vs[col + 1];
                float* cc = t ? c1[mf][nf] : c0[mf][nf];
                s_lo += v0 * tanhf(ql[col] + cc[0] * INVWK) + v1 * tanhf(ql[col + 1] + cc[1] * INVWK);
                s_hi += v0 * tanhf(qh[col] + cc[2] * INVWK) + v1 * tanhf(qh[col + 1] + cc[3] * INVWK);
            }
            s_lo += __shfl_xor_sync(0xffffffff, s_lo, 1);
            s_lo += __shfl_xor_sync(0xffffffff, s_lo, 2);
            s_hi += __shfl_xor_sync(0xffffffff, s_hi, 1);
            s_hi += __shfl_xor_sync(0xffffffff, s_hi, 2);
            if ((lane & 3) == 0) {
                if (mt + rl < total) atomicAdd(&energy[gl], s_lo);
                if (mt + rh < total) atomicAdd(&energy[gh], s_hi);
            }
        }
    }
}

// ===================== fused softmax + compacted context =====================
__global__ void softmax_context_kernel(const float* __restrict__ energy,
                                       const float* __restrict__ enc,
                                       float* __restrict__ out_attn) {
    __shared__ float red[256];
    __shared__ float w[256];
    __shared__ int sid[256];
    __shared__ int cnts;
    const int b = blockIdx.x;
    const int tid = threadIdx.x;

    float val = energy[b * S_ + tid];
    red[tid] = val;
    sid[tid] = g_sidx[b * S_ + tid];
    if (tid == 0) cnts = g_scnt[b];
    __syncthreads();
#pragma unroll
    for (int off = 128; off > 0; off >>= 1) {
        if (tid < off) red[tid] = fmaxf(red[tid], red[tid + off]);
        __syncthreads();
    }
    float mx = red[0];
    __syncthreads();
    float ex = expf(val - mx);
    red[tid] = ex;
    __syncthreads();
#pragma unroll
    for (int off = 128; off > 0; off >>= 1) {
        if (tid < off) red[tid] += red[tid + off];
        __syncthreads();
    }
    float aw = ex / red[0];
    if (blockIdx.y == 0) out_attn[b * S_ + tid] = aw;
    w[tid] = aw;
    __syncthreads();

    const int cnt = cnts;
    const int col = blockIdx.y * 256 + tid;
    const float* eb = enc + (long)b * S_ * ENC_;
    float a0 = 0.f, a1 = 0.f, a2 = 0.f, a3 = 0.f;
    int j = 0;
    for (; j + 4 <= cnt; j += 4) {
        a0 = fmaf(w[sid[j]],     eb[(long)sid[j] * ENC_ + col],     a0);
        a1 = fmaf(w[sid[j + 1]], eb[(long)sid[j + 1] * ENC_ + col], a1);
        a2 = fmaf(w[sid[j + 2]], eb[(long)sid[j + 2] * ENC_ + col], a2);
        a3 = fmaf(w[sid[j + 3]], eb[(long)sid[j + 3] * ENC_ + col], a3);
    }
    for (; j < cnt; j++)
        a0 = fmaf(w[sid[j]], eb[(long)sid[j] * ENC_ + col], a0);
    float acc = (a0 + a1) + (a2 + a3);
    __half hv = __float2half_rn(acc);
    g_a0f[b * KCAT0 + E_ + col] = hv;
    g_featf[b * FDIM_ + H_ + col] = hv;
}

// ===================== LSTM pointwise ========================================
__global__ void lstm_kernel(const float* __restrict__ gates,
                            const float* __restrict__ c_prev,
                            float* __restrict__ c_out,
                            float* __restrict__ h_out_f32,
                            __half* __restrict__ hb,
                            int sb) {
    const int b = blockIdx.x;
    const int idx = blockIdx.y * 256 + threadIdx.x;
    float gi = gates[b * G4H_ + idx];
    float gf = gates[b * G4H_ + H_ + idx];
    float gg = gates[b * G4H_ + 2 * H_ + idx];
    float go = gates[b * G4H_ + 3 * H_ + idx];
    float c  = c_prev[b * H_ + idx];
    float si = 1.f / (1.f + expf(-gi));
    float sf = 1.f / (1.f + expf(-gf));
    float so = 1.f / (1.f + expf(-go));
    float cn = sf * c + si * tanhf(gg);
    float hn = so * tanhf(cn);
    c_out[b * H_ + idx]     = cn;
    h_out_f32[b * H_ + idx] = hn;
    hb[b * sb + idx] = __float2half_rn(hn);
}

// ===================== launch ================================================
extern "C" void kernel_launch(void* const* d_in, const int* in_sizes, int n_in,
                              void* d_out, int out_size) {
    const int*   tok    = (const int*)  d_in[0];
    const float* hidden = (const float*)d_in[1];
    const float* cell   = (const float*)d_in[2];
    const float* enc    = (const float*)d_in[3];
    const int*   mask   = (const int*)  d_in[4];
    const float* emb    = (const float*)d_in[5];
    const float* Wq     = (const float*)d_in[6];
    const float* Wk     = (const float*)d_in[7];
    const float* v      = (const float*)d_in[8];
    const float* Wih0   = (const float*)d_in[9];
    const float* Whh0   = (const float*)d_in[10];
    const float* bih0   = (const float*)d_in[11];
    const float* bhh0   = (const float*)d_in[12];
    const float* Wih1   = (const float*)d_in[13];
    const float* Whh1   = (const float*)d_in[14];
    const float* bih1   = (const float*)d_in[15];
    const float* bhh1   = (const float*)d_in[16];
    const float* Wout   = (const float*)d_in[17];
    const float* bout   = (const float*)d_in[18];

    float* out      = (float*)d_out;
    float* out_pred = out;
    float* out_hid  = out + (long)B_ * V_;
    float* out_cell = out_hid + 2 * B_ * H_;
    float* out_attn = out_cell + 2 * B_ * H_;

    void* sp = nullptr;
    cudaGetSymbolAddress(&sp, g_scratch);
    float* scratch = (float*)sp;
    float* query  = scratch + OFF_QUERY;
    float* gates0 = scratch + OFF_GATES0;
    float* gates1 = scratch + OFF_GATES1;
    float* energy = scratch + OFF_ENERGY;

    void *p_ef, *p_wh, *p_wl, *p_h1, *p_a0, *p_a1, *p_ft;
    cudaGetSymbolAddress(&p_ef, g_enc_f16);
    cudaGetSymbolAddress(&p_wh, g_wk_h);
    cudaGetSymbolAddress(&p_wl, g_wk_l);
    cudaGetSymbolAddress(&p_h1, g_h1f);
    cudaGetSymbolAddress(&p_a0, g_a0f);
    cudaGetSymbolAddress(&p_a1, g_a1f);
    cudaGetSymbolAddress(&p_ft, g_featf);

    cudaFuncSetAttribute(hmma_m64_kernel<false>, cudaFuncAttributeMaxDynamicSharedMemorySize, WO_SMEM_BYTES);
    cudaFuncSetAttribute(hmma_m64_kernel<true>,  cudaFuncAttributeMaxDynamicSharedMemorySize, WO_SMEM_BYTES);
    cudaFuncSetAttribute(energy_f16_kernel,      cudaFuncAttributeMaxDynamicSharedMemorySize, EN_SMEM_BYTES);

    // 1. fused prep
    prep_kernel<<<PREP_BLKS, 256>>>(enc, Wk, mask, hidden, tok, emb,
                                    bih0, bhh0, bih1, bhh1, bout,
                                    energy, query, gates0, gates1, out_pred);

    // 2. global compaction
    gather_kernel<<<1, 256>>>();

    // 3. query = hidden[1] @ Wq^T (fp16 2-term, K-split 4, atomic)
    hmma_m64_kernel<true><<<dim3(H_ / 128, 4), 256, WO_SMEM_BYTES>>>(
        (const __half*)p_h1, H_, Wq, H_, Wq, nullptr, query, H_, 4);

    // 4. energy (fp16 2-term, 256-row super-tiles, r9 tiling)
    energy_f16_kernel<<<dim3(H_ / 128, (B_ * S_) / 256), 256, EN_SMEM_BYTES>>>(
        (const __half*)p_ef, (const __half*)p_wh, (const __half*)p_wl,
        v, query, energy);

    // 5. fused masked softmax + compacted context
    softmax_context_kernel<<<dim3(B_, 4), 256>>>(energy, enc, out_attn);

    // 6. layer-0 gates + LSTM
    hmma_m64_kernel<true><<<dim3(G4H_ / 128, 4), 256, WO_SMEM_BYTES>>>(
        (const __half*)p_a0, KCAT0, Wih0, E_ + ENC_, Whh0, nullptr, gates0, G4H_, 4);
    lstm_kernel<<<dim3(B_, H_ / 256), 256>>>(gates0, cell, out_cell, out_hid,
                                             (__half*)p_a1, KCAT1);

    // 7. layer-1 gates + LSTM
    hmma_m64_kernel<true><<<dim3(G4H_ / 128, 4), 256, WO_SMEM_BYTES>>>(
        (const __half*)p_a1, KCAT1, Wih1, H_, Whh1, nullptr, gates1, G4H_, 4);
    lstm_kernel<<<dim3(B_, H_ / 256), 256>>>(gates1, cell + B_ * H_, out_cell + B_ * H_,
                                             out_hid + B_ * H_, (__half*)p_ft, FDIM_);

    // 8. prediction = feat @ Wout^T + bout (fp16 2-term, K-split 4, atomic)
    hmma_m64_kernel<true><<<dim3(V_ / 128, 4), 256, WO_SMEM_BYTES>>>(
        (const __half*)p_ft, FDIM_, Wout, FDIM_, Wout, nullptr, out_pred, V_, 4);
}

// round 12
// speedup vs baseline: 1.5736x; 1.0679x over previous
#include <cuda_runtime.h>
#include <cuda_bf16.h>
#include <cuda_fp16.h>
#include <math.h>
#include <stdint.h>

#define B_   64
#define S_   256
#define H_   1024
#define ENC_ 1024
#define E_   512
#define V_   32000
#define FDIM_ (H_ + ENC_ + E_)   // 2560
#define G4H_  (4 * H_)           // 4096
#define KCAT0 2560
#define KCAT1 2048
#define WKSCALE 2048.0f
#define INVWK   (1.0f / 2048.0f)

// ---------------- scratch ----------------------------------------------------
#define OFF_QUERY   0
#define OFF_GATES0  (OFF_QUERY + B_ * H_)
#define OFF_GATES1  (OFF_GATES0 + B_ * G4H_)
#define OFF_ENERGY  (OFF_GATES1 + B_ * G4H_)
#define SCRATCH_TOTAL (OFF_ENERGY + B_ * S_)

__device__ __align__(16) float g_scratch[SCRATCH_TOTAL];
__device__ int g_sidx[B_ * S_];
__device__ int g_scnt[B_];
__device__ int g_gidx[B_ * S_];
__device__ int g_total;

// fp16 buffers (g_enc_f16 holds GATHERED unmasked rows, compact)
__device__ __align__(16) __half g_enc_f16[(long)B_ * S_ * ENC_];
__device__ __align__(16) __half g_wk_h[H_ * ENC_];
__device__ __align__(16) __half g_wk_l[H_ * ENC_];
__device__ __align__(16) __half g_h1f[B_ * H_];
__device__ __align__(16) __half g_a0f[B_ * KCAT0];
__device__ __align__(16) __half g_a1f[B_ * KCAT1];
__device__ __align__(16) __half g_featf[B_ * FDIM_];

// ===================== low-level helpers =====================================
__device__ __forceinline__ uint32_t smem_to_u32(const void* p) {
    uint32_t a;
    asm("{ .reg .u64 t; cvta.to.shared.u64 t, %1; cvt.u32.u64 %0, t; }" : "=r"(a) : "l"(p));
    return a;
}

#define CP16(dst_u32, src_ptr) \
    asm volatile("cp.async.cg.shared.global [%0], [%1], 16;" :: "r"(dst_u32), "l"(src_ptr))
#define CP_COMMIT() asm volatile("cp.async.commit_group;" ::: "memory")
template<int N> __device__ __forceinline__ void cp_wait() {
    asm volatile("cp.async.wait_group %0;" :: "n"(N) : "memory");
}

__device__ __forceinline__ void ldmx4(uint32_t addr, uint32_t r[4]) {
    asm volatile("ldmatrix.sync.aligned.m8n8.x4.shared.b16 {%0,%1,%2,%3}, [%4];"
        : "=r"(r[0]), "=r"(r[1]), "=r"(r[2]), "=r"(r[3]) : "r"(addr));
}

__device__ __forceinline__ void mma16816h(float* c, const uint32_t a[4],
                                          uint32_t b0, uint32_t b1) {
    asm volatile("mma.sync.aligned.m16n8k16.row.col.f32.f16.f16.f32 "
        "{%0,%1,%2,%3}, {%4,%5,%6,%7}, {%8,%9}, {%0,%1,%2,%3};"
        : "+f"(c[0]), "+f"(c[1]), "+f"(c[2]), "+f"(c[3])
        : "r"(a[0]), "r"(a[1]), "r"(a[2]), "r"(a[3]), "r"(b0), "r"(b1));
}

#define STS128(addr, a, b, c, d) \
    asm volatile("st.shared.v4.b32 [%0], {%1,%2,%3,%4};" \
        :: "r"(addr), "r"(a), "r"(b), "r"(c), "r"(d) : "memory")

__device__ __forceinline__ uint32_t swz(int row, int chunk16) {
    return (uint32_t)(row * 128 + ((chunk16 ^ (row & 7)) * 16));
}

// fp16 scaled split: w*2048 = hi + lo
__device__ __forceinline__ void split2h(float a, float b, uint32_t& hi, uint32_t& lo) {
    float as = a * WKSCALE, bs = b * WKSCALE;
    __half2 h2 = __floats2half2_rn(as, bs);
    float ra = as - __half2float(__low2half(h2));
    float rb = bs - __half2float(__high2half(h2));
    __half2 l2 = __floats2half2_rn(ra, rb);
    hi = *reinterpret_cast<uint32_t*>(&h2);
    lo = *reinterpret_cast<uint32_t*>(&l2);
}

// ===================== scan kernel (everything except enc/wk conversion) =====
// [0,64): per-b mask scan + energy init + embed + hidden scatter
// [64,128): h1 fp16   [128,192): query zero
// [192,448): gates0 bias  [448,704): gates1 bias  [704,2704): out_pred = bout
#define SCAN_BLKS 2704

__global__ void scan_kernel(const int* __restrict__ mask,
                            const float* __restrict__ hidden,
                            const int* __restrict__ tok,
                            const float* __restrict__ emb,
                            const float* __restrict__ bih0,
                            const float* __restrict__ bhh0,
                            const float* __restrict__ bih1,
                            const float* __restrict__ bhh1,
                            const float* __restrict__ bout,
                            float* __restrict__ energy,
                            float* __restrict__ query,
                            float* __restrict__ gates0,
                            float* __restrict__ gates1,
                            float* __restrict__ out_pred) {
    const int tid = threadIdx.x;
    const int blk = blockIdx.x;
    if (blk < 64) {
        const int b = blk;
        __shared__ int sc[256];
        int m = (mask[b * S_ + tid] != 0) ? 1 : 0;
        sc[tid] = m;
        __syncthreads();
#pragma unroll
        for (int off = 1; off < 256; off <<= 1) {
            int t = (tid >= off) ? sc[tid - off] : 0;
            __syncthreads();
            sc[tid] += t;
            __syncthreads();
        }
        int total = sc[255];
        int my = sc[tid] - m;
        if (m) g_sidx[b * S_ + my] = tid;
        if (tid >= total) g_sidx[b * S_ + tid] = 0;
        energy[b * S_ + tid] = m ? 0.f : -1e10f;
        if (tid == 0) g_scnt[b] = total;
        const int t = tok[b];
        for (int j = tid; j < E_; j += 256) {
            __half hv = __float2half_rn(emb[(long)t * E_ + j]);
            g_a0f[b * KCAT0 + j] = hv;
            g_featf[b * FDIM_ + (H_ + ENC_) + j] = hv;
        }
        for (int j = tid; j < H_; j += 256) {
            g_a0f[b * KCAT0 + (E_ + ENC_) + j] = __float2half_rn(hidden[b * H_ + j]);
            g_a1f[b * KCAT1 + H_ + j] = __float2half_rn(hidden[B_ * H_ + b * H_ + j]);
        }
    } else if (blk < 128) {
        long i = ((long)(blk - 64) * 256 + tid) * 4;
        float4 v = *reinterpret_cast<const float4*>(hidden + (long)B_ * H_ + i);
        __half2 h0 = __floats2half2_rn(v.x, v.y);
        __half2 h1 = __floats2half2_rn(v.z, v.w);
        uint2 o = {*reinterpret_cast<uint32_t*>(&h0), *reinterpret_cast<uint32_t*>(&h1)};
        *reinterpret_cast<uint2*>(g_h1f + i) = o;
    } else if (blk < 192) {
        long i = ((long)(blk - 128) * 256 + tid) * 4;
        float4 z = {0.f, 0.f, 0.f, 0.f};
        *reinterpret_cast<float4*>(query + i) = z;
    } else if (blk < 448) {
        long i = ((long)(blk - 192) * 256 + tid) * 4;
        int n = (int)(i & (G4H_ - 1));
        float4 o = {bih0[n] + bhh0[n], bih0[n + 1] + bhh0[n + 1],
                    bih0[n + 2] + bhh0[n + 2], bih0[n + 3] + bhh0[n + 3]};
        *reinterpret_cast<float4*>(gates0 + i) = o;
    } else if (blk < 704) {
        long i = ((long)(blk - 448) * 256 + tid) * 4;
        int n = (int)(i & (G4H_ - 1));
        float4 o = {bih1[n] + bhh1[n], bih1[n + 1] + bhh1[n + 1],
                    bih1[n + 2] + bhh1[n + 2], bih1[n + 3] + bhh1[n + 3]};
        *reinterpret_cast<float4*>(gates1 + i) = o;
    } else {
        long i = ((long)(blk - 704) * 1024 + tid * 4);
        int col = (int)(i % V_);
        float4 o = {bout[col], bout[col + 1], bout[col + 2], bout[col + 3]};
        *reinterpret_cast<float4*>(out_pred + i) = o;
    }
}

// ===================== global gather =========================================
__global__ void gather_kernel() {
    __shared__ int offs[B_ + 1];
    const int tid = threadIdx.x;
    if (tid == 0) {
        int acc = 0;
        for (int b = 0; b < B_; b++) { offs[b] = acc; acc += g_scnt[b]; }
        offs[B_] = acc;
        g_total = acc;
    }
    __syncthreads();
    for (int b = 0; b < B_; b++) {
        int o = offs[b], cnt = offs[b + 1] - o;
        for (int j = tid; j < cnt; j += 256)
            g_gidx[o + j] = b * S_ + g_sidx[b * S_ + j];
    }
    int total = offs[B_];
    for (int j = total + tid; j < B_ * S_; j += 256) g_gidx[j] = 0;
}

// ===================== prep2: gathered enc conversion + wk split =============
#define ENC_RBLKS ((B_ * S_) / 4)            // 4096 blocks, 4 rows each
#define WK_BLKS   ((H_ * ENC_) / 1024)       // 1024
#define PREP2_BLKS (ENC_RBLKS + WK_BLKS)

__global__ void prep2_kernel(const float* __restrict__ enc,
                             const float* __restrict__ wk) {
    const int tid = threadIdx.x;
    const int blk = blockIdx.x;
    if (blk < ENC_RBLKS) {
        int row0 = blk * 4;
        int lim = (g_total + 255) & ~255;     // energy reads full 256-row tiles
        if (row0 >= lim) return;
        const int e = tid * 4;
#pragma unroll
        for (int rr = 0; rr < 4; rr++) {
            int row = row0 + rr;
            long src = (long)g_gidx[row] * ENC_ + e;
            float4 v = *reinterpret_cast<const float4*>(enc + src);
            __half2 h0 = __floats2half2_rn(v.x, v.y);
            __half2 h1 = __floats2half2_rn(v.z, v.w);
            uint2 o = {*reinterpret_cast<uint32_t*>(&h0), *reinterpret_cast<uint32_t*>(&h1)};
            *reinterpret_cast<uint2*>(g_enc_f16 + (long)row * ENC_ + e) = o;
        }
    } else {
        long i = ((long)(blk - ENC_RBLKS) * 256 + tid) * 4;
        float4 v = *reinterpret_cast<const float4*>(wk + i);
        uint2 H, L;
        split2h(v.x, v.y, H.x, L.x);
        split2h(v.z, v.w, H.y, L.y);
        *reinterpret_cast<uint2*>(g_wk_h + i) = H;
        *reinterpret_cast<uint2*>(g_wk_l + i) = L;
    }
}

// ===================== fat-B HMMA kernel (fp16, NT terms) ====================
#define WO_A_TILE 8192
#define WO_B_TILE 16384
#define WO_STAGE  (WO_A_TILE + 2 * WO_B_TILE)   // 40KB
#define WO_SMEM_BYTES (1024 + 2 * WO_STAGE)

__device__ __forceinline__ void wo_load_A(const __half* f, int lda, int c0, uint32_t stg) {
    const int tid = threadIdx.x;
#pragma unroll
    for (int i = 0; i < 2; i++) {
        int idx = tid + i * 256;
        int r = idx >> 3, cc = idx & 7;
        uint32_t off = swz(r, cc);
        CP16(stg + off, f + (long)r * lda + c0 + cc * 8);
    }
}

template<int NT>
__global__ __launch_bounds__(256, 2)
void hmma_m64_kernel(const __half* __restrict__ a_g,
                     int Ktot,
                     const float* __restrict__ B1, int k1,
                     const float* __restrict__ B2,
                     float* __restrict__ C, int ldc, int nks) {
    extern __shared__ char smem[];
    uint32_t sb = smem_to_u32(smem);
    uint32_t tiles = (sb + 1023) & ~1023u;

    const int tid = threadIdx.x;
    const int wid = tid >> 5, lane = tid & 31;
    const int warp_m = (wid & 1) * 32;
    const int warp_n = (wid >> 1) * 32;
    const int n0 = blockIdx.x * 128;

    const int br = tid >> 1;
    const int bhalf = tid & 1;
    const int k2 = Ktot - k1;

    const int KT = Ktot / 64;
    const int kt0 = (int)blockIdx.y * (KT / nks);
    const int kt1 = kt0 + KT / nks;

    auto bptr = [&](int c0) -> const float* {
        return (c0 < k1) ? B1 + (long)(n0 + br) * k1 + c0 + bhalf * 32
                         : B2 + (long)(n0 + br) * k2 + (c0 - k1) + bhalf * 32;
    };

    float c[2][4][4];
#pragma unroll
    for (int i = 0; i < 2; i++)
#pragma unroll
        for (int j = 0; j < 4; j++)
#pragma unroll
            for (int k = 0; k < 4; k++) c[i][j][k] = 0.f;

    wo_load_A(a_g, Ktot, kt0 * 64, tiles + (kt0 & 1) * WO_STAGE);
    CP_COMMIT();

    for (int kt = kt0; kt < kt1; kt++) {
        uint32_t stg = tiles + (kt & 1) * WO_STAGE;
        if (kt + 1 < kt1) {
            wo_load_A(a_g, Ktot, (kt + 1) * 64, tiles + ((kt + 1) & 1) * WO_STAGE);
            CP_COMMIT();
        }
        uint32_t Bh = stg + WO_A_TILE, Bl = Bh + WO_B_TILE;
        const float* w = bptr(kt * 64);
#pragma unroll
        for (int j = 0; j < 4; j++) {
            float4 v0 = *reinterpret_cast<const float4*>(w + j * 8);
            float4 v1 = *reinterpret_cast<const float4*>(w + j * 8 + 4);
            uint4 Hq, Lq;
            split2h(v0.x, v0.y, Hq.x, Lq.x);
            split2h(v0.z, v0.w, Hq.y, Lq.y);
            split2h(v1.x, v1.y, Hq.z, Lq.z);
            split2h(v1.z, v1.w, Hq.w, Lq.w);
            uint32_t off = swz(br, bhalf * 4 + j);
            STS128(Bh + off, Hq.x, Hq.y, Hq.z, Hq.w);
            if (NT == 2) STS128(Bl + off, Lq.x, Lq.y, Lq.z, Lq.w);
        }
        if (kt + 1 < kt1) cp_wait<1>(); else cp_wait<0>();
        __syncthreads();
        {
            const uint32_t Ah = stg;
            const int lm = lane & 15, lh = lane >> 4;
#pragma unroll
            for (int ks = 0; ks < 4; ks++) {
                const int ch = ks * 2 + lh;
                uint32_t ah[2][4];
#pragma unroll
                for (int mf = 0; mf < 2; mf++) {
                    uint32_t off = swz(warp_m + mf * 16 + lm, ch);
                    ldmx4(Ah + off, ah[mf]);
                }
                uint32_t bb[2][4];
#pragma unroll
                for (int nf2 = 0; nf2 < 2; nf2++) {
                    uint32_t off = swz(warp_n + nf2 * 16 + lm, ch);
                    ldmx4(Bh + off, bb[nf2]);
                }
#pragma unroll
                for (int nf2 = 0; nf2 < 2; nf2++)
#pragma unroll
                    for (int mf = 0; mf < 2; mf++) {
                        mma16816h(c[mf][nf2 * 2 + 0], ah[mf], bb[nf2][0], bb[nf2][2]);
                        mma16816h(c[mf][nf2 * 2 + 1], ah[mf], bb[nf2][1], bb[nf2][3]);
                    }
                if (NT == 2) {
#pragma unroll
                    for (int nf2 = 0; nf2 < 2; nf2++) {
                        uint32_t off = swz(warp_n + nf2 * 16 + lm, ch);
                        ldmx4(Bl + off, bb[nf2]);
                    }
#pragma unroll
                    for (int nf2 = 0; nf2 < 2; nf2++)
#pragma unroll
                        for (int mf = 0; mf < 2; mf++) {
                            mma16816h(c[mf][nf2 * 2 + 0], ah[mf], bb[nf2][0], bb[nf2][2]);
                            mma16816h(c[mf][nf2 * 2 + 1], ah[mf], bb[nf2][1], bb[nf2][3]);
                        }
                }
            }
        }
        __syncthreads();
    }

#pragma unroll
    for (int mf = 0; mf < 2; mf++)
#pragma unroll
        for (int nf = 0; nf < 4; nf++) {
            int col = n0 + warp_n + nf * 8 + (lane & 3) * 2;
            int r0 = warp_m + mf * 16 + (lane >> 2);
            atomicAdd(&C[(long)r0 * ldc + col],           c[mf][nf][0] * INVWK);
            atomicAdd(&C[(long)r0 * ldc + col + 1],       c[mf][nf][1] * INVWK);
            atomicAdd(&C[(long)(r0 + 8) * ldc + col],     c[mf][nf][2] * INVWK);
            atomicAdd(&C[(long)(r0 + 8) * ldc + col + 1], c[mf][nf][3] * INVWK);
        }
}

// ===================== energy: fp16 2-term, compact 256-row tiles ============
#define EN_T 16384
#define EN_STAGE (4 * EN_T)
#define EN_SMEM_BYTES (2048 + 2 * EN_STAGE)

__global__ __launch_bounds__(256, 1)
void energy_f16_kernel(const __half* __restrict__ ef,
                       const __half* __restrict__ wh,
                       const __half* __restrict__ wl,
                       const float* __restrict__ vvec,
                       const float* __restrict__ query,
                       float* __restrict__ energy) {
    const int total = g_total;
    const int mt = (int)blockIdx.y * 256;
    if (mt >= total) return;

    extern __shared__ char smem[];
    uint32_t sb = smem_to_u32(smem);
    uint32_t tiles = (sb + 2048 + 1023) & ~1023u;

    const int tid = threadIdx.x;
    const int wid = tid >> 5, lane = tid & 31;
    const int warp_m = (wid & 3) * 32;
    const int warp_n = (wid >> 2) * 64;
    const int n0 = blockIdx.x * 128;

    float* vs = (float*)smem;
    int*   sid = (int*)(vs + 128);
    if (tid < 128) vs[tid] = vvec[n0 + tid];
    sid[tid] = g_gidx[mt + tid];
    __syncthreads();

    // A rows are compact: linear offsets
    const int rb = tid >> 3, cc8 = (tid & 7) * 8;
    uint32_t a0off[4], boff[4], soffs[4];
#pragma unroll
    for (int i = 0; i < 4; i++) {
        int r = rb + 32 * i;
        soffs[i] = swz(r, tid & 7);
        a0off[i] = (uint32_t)(mt + r) * ENC_ + cc8;
        boff[i]  = (uint32_t)(n0 + r) * ENC_ + cc8;
    }

    float c0[2][8][4], c1[2][8][4];
#pragma unroll
    for (int i = 0; i < 2; i++)
#pragma unroll
        for (int j = 0; j < 8; j++)
#pragma unroll
            for (int k = 0; k < 4; k++) { c0[i][j][k] = 0.f; c1[i][j][k] = 0.f; }

    auto load_stage = [&](int c0v, uint32_t stg) {
#pragma unroll
        for (int i = 0; i < 4; i++) {
            CP16(stg + soffs[i],            ef + a0off[i] + c0v);
            CP16(stg + EN_T + soffs[i],     ef + a0off[i] + 128 * ENC_ + c0v);
            CP16(stg + 2 * EN_T + soffs[i], wh + boff[i] + c0v);
            CP16(stg + 3 * EN_T + soffs[i], wl + boff[i] + c0v);
        }
    };

    load_stage(0, tiles);
    CP_COMMIT();

    const int KT = ENC_ / 64;
    for (int kt = 0; kt < KT; kt++) {
        uint32_t stg = tiles + (kt & 1) * EN_STAGE;
        if (kt + 1 < KT) {
            load_stage((kt + 1) * 64, tiles + ((kt + 1) & 1) * EN_STAGE);
            CP_COMMIT();
            cp_wait<1>();
        } else {
            cp_wait<0>();
        }
        __syncthreads();
        {
            const uint32_t A0 = stg, A1 = stg + EN_T;
            const uint32_t Bh = stg + 2 * EN_T, Bl = stg + 3 * EN_T;
            const int lm = lane & 15, lh = lane >> 4;
#pragma unroll
            for (int ks = 0; ks < 4; ks++) {
                const int ch = ks * 2 + lh;
                uint32_t a0[2][4], a1[2][4];
#pragma unroll
                for (int mf = 0; mf < 2; mf++) {
                    uint32_t off = swz(warp_m + mf * 16 + lm, ch);
                    ldmx4(A0 + off, a0[mf]);
                    ldmx4(A1 + off, a1[mf]);
                }
                uint32_t bb[4][4];
#pragma unroll
                for (int nf2 = 0; nf2 < 4; nf2++) {
                    uint32_t off = swz(warp_n + nf2 * 16 + lm, ch);
                    ldmx4(Bh + off, bb[nf2]);
                }
#pragma unroll
                for (int nf2 = 0; nf2 < 4; nf2++)
#pragma unroll
                    for (int mf = 0; mf < 2; mf++) {
                        mma16816h(c0[mf][nf2 * 2 + 0], a0[mf], bb[nf2][0], bb[nf2][2]);
                        mma16816h(c0[mf][nf2 * 2 + 1], a0[mf], bb[nf2][1], bb[nf2][3]);
                        mma16816h(c1[mf][nf2 * 2 + 0], a1[mf], bb[nf2][0], bb[nf2][2]);
                        mma16816h(c1[mf][nf2 * 2 + 1], a1[mf], bb[nf2][1], bb[nf2][3]);
                    }
#pragma unroll
                for (int nf2 = 0; nf2 < 4; nf2++) {
                    uint32_t off = swz(warp_n + nf2 * 16 + lm, ch);
                    ldmx4(Bl + off, bb[nf2]);
                }
#pragma unroll
                for (int nf2 = 0; nf2 < 4; nf2++)
#pragma unroll
                    for (int mf = 0; mf < 2; mf++) {
                        mma16816h(c0[mf][nf2 * 2 + 0], a0[mf], bb[nf2][0], bb[nf2][2]);
                        mma16816h(c0[mf][nf2 * 2 + 1], a0[mf], bb[nf2][1], bb[nf2][3]);
                        mma16816h(c1[mf][nf2 * 2 + 0], a1[mf], bb[nf2][0], bb[nf2][2]);
                        mma16816h(c1[mf][nf2 * 2 + 1], a1[mf], bb[nf2][1], bb[nf2][3]);
                    }
            }
        }
        __syncthreads();
    }

#pragma unroll
    for (int t = 0; t < 2; t++) {
#pragma unroll
        for (int mf = 0; mf < 2; mf++) {
            int rl = t * 128 + warp_m + mf * 16 + (lane >> 2);
            int rh = rl + 8;
            int gl = sid[rl], gh = sid[rh];
            const float* ql = query + (long)(gl >> 8) * H_ + n0;
            const float* qh = query + (long)(gh >> 8) * H_ + n0;
            float s_lo = 0.f, s_hi = 0.f;
#pragma unroll
            for (int nf = 0; nf < 8; nf++) {
                int col = warp_n + nf * 8 + (lane & 3) * 2;
                float v0 = vs[col], v1 = vs[col + 1];
                float* cc = t ? c1[mf][nf] : c0[mf][nf];
                s_lo += v0 * tanhf(ql[col] + cc[0] * INVWK) + v1 * tanhf(ql[col + 1] + cc[1] * INVWK);
                s_hi += v0 * tanhf(qh[col] + cc[2] * INVWK) + v1 * tanhf(qh[col + 1] + cc[3] * INVWK);
            }
            s_lo += __shfl_xor_sync(0xffffffff, s_lo, 1);
            s_lo += __shfl_xor_sync(0xffffffff, s_lo, 2);
            s_hi += __shfl_xor_sync(0xffffffff, s_hi, 1);
            s_hi += __shfl_xor_sync(0xffffffff, s_hi, 2);
            if ((lane & 3) == 0) {
                if (mt + rl < total) atomicAdd(&energy[gl], s_lo);
                if (mt + rh < total) atomicAdd(&energy[gh], s_hi);
            }
        }
    }
}

// ===================== fused softmax + compacted context =====================
__global__ void softmax_context_kernel(const float* __restrict__ energy,
                                       const float* __restrict__ enc,
                                       float* __restrict__ out_attn) {
    __shared__ float red[256];
    __shared__ float w[256];
    __shared__ int sid[256];
    __shared__ int cnts;
    const int b = blockIdx.x;
    const int tid = threadIdx.x;

    float val = energy[b * S_ + tid];
    red[tid] = val;
    sid[tid] = g_sidx[b * S_ + tid];
    if (tid == 0) cnts = g_scnt[b];
    __syncthreads();
#pragma unroll
    for (int off = 128; off > 0; off >>= 1) {
        if (tid < off) red[tid] = fmaxf(red[tid], red[tid + off]);
        __syncthreads();
    }
    float mx = red[0];
    __syncthreads();
    float ex = expf(val - mx);
    red[tid] = ex;
    __syncthreads();
#pragma unroll
    for (int off = 128; off > 0; off >>= 1) {
        if (tid < off) red[tid] += red[tid + off];
        __syncthreads();
    }
    float aw = ex / red[0];
    if (blockIdx.y == 0) out_attn[b * S_ + tid] = aw;
    w[tid] = aw;
    __syncthreads();

    const int cnt = cnts;
    const int col = blockIdx.y * 256 + tid;
    const float* eb = enc + (long)b * S_ * ENC_;
    float a0 = 0.f, a1 = 0.f, a2 = 0.f, a3 = 0.f;
    int j = 0;
    for (; j + 4 <= cnt; j += 4) {
        a0 = fmaf(w[sid[j]],     eb[(long)sid[j] * ENC_ + col],     a0);
        a1 = fmaf(w[sid[j + 1]], eb[(long)sid[j + 1] * ENC_ + col], a1);
        a2 = fmaf(w[sid[j + 2]], eb[(long)sid[j + 2] * ENC_ + col], a2);
        a3 = fmaf(w[sid[j + 3]], eb[(long)sid[j + 3] * ENC_ + col], a3);
    }
    for (; j < cnt; j++)
        a0 = fmaf(w[sid[j]], eb[(long)sid[j] * ENC_ + col], a0);
    float acc = (a0 + a1) + (a2 + a3);
    __half hv = __float2half_rn(acc);
    g_a0f[b * KCAT0 + E_ + col] = hv;
    g_featf[b * FDIM_ + H_ + col] = hv;
}

// ===================== LSTM pointwise ========================================
__global__ void lstm_kernel(const float* __restrict__ gates,
                            const float* __restrict__ c_prev,
                            float* __restrict__ c_out,
                            float* __restrict__ h_out_f32,
                            __half* __restrict__ hb,
                            int sb) {
    const int b = blockIdx.x;
    const int idx = blockIdx.y * 256 + threadIdx.x;
    float gi = gates[b * G4H_ + idx];
    float gf = gates[b * G4H_ + H_ + idx];
    float gg = gates[b * G4H_ + 2 * H_ + idx];
    float go = gates[b * G4H_ + 3 * H_ + idx];
    float c  = c_prev[b * H_ + idx];
    float si = 1.f / (1.f + expf(-gi));
    float sf = 1.f / (1.f + expf(-gf));
    float so = 1.f / (1.f + expf(-go));
    float cn = sf * c + si * tanhf(gg);
    float hn = so * tanhf(cn);
    c_out[b * H_ + idx]     = cn;
    h_out_f32[b * H_ + idx] = hn;
    hb[b * sb + idx] = __float2half_rn(hn);
}

// ===================== launch ================================================
extern "C" void kernel_launch(void* const* d_in, const int* in_sizes, int n_in,
                              void* d_out, int out_size) {
    const int*   tok    = (const int*)  d_in[0];
    const float* hidden = (const float*)d_in[1];
    const float* cell   = (const float*)d_in[2];
    const float* enc    = (const float*)d_in[3];
    const int*   mask   = (const int*)  d_in[4];
    const float* emb    = (const float*)d_in[5];
    const float* Wq     = (const float*)d_in[6];
    const float* Wk     = (const float*)d_in[7];
    const float* v      = (const float*)d_in[8];
    const float* Wih0   = (const float*)d_in[9];
    const float* Whh0   = (const float*)d_in[10];
    const float* bih0   = (const float*)d_in[11];
    const float* bhh0   = (const float*)d_in[12];
    const float* Wih1   = (const float*)d_in[13];
    const float* Whh1   = (const float*)d_in[14];
    const float* bih1   = (const float*)d_in[15];
    const float* bhh1   = (const float*)d_in[16];
    const float* Wout   = (const float*)d_in[17];
    const float* bout   = (const float*)d_in[18];

    float* out      = (float*)d_out;
    float* out_pred = out;
    float* out_hid  = out + (long)B_ * V_;
    float* out_cell = out_hid + 2 * B_ * H_;
    float* out_attn = out_cell + 2 * B_ * H_;

    void* sp = nullptr;
    cudaGetSymbolAddress(&sp, g_scratch);
    float* scratch = (float*)sp;
    float* query  = scratch + OFF_QUERY;
    float* gates0 = scratch + OFF_GATES0;
    float* gates1 = scratch + OFF_GATES1;
    float* energy = scratch + OFF_ENERGY;

    void *p_ef, *p_wh, *p_wl, *p_h1, *p_a0, *p_a1, *p_ft;
    cudaGetSymbolAddress(&p_ef, g_enc_f16);
    cudaGetSymbolAddress(&p_wh, g_wk_h);
    cudaGetSymbolAddress(&p_wl, g_wk_l);
    cudaGetSymbolAddress(&p_h1, g_h1f);
    cudaGetSymbolAddress(&p_a0, g_a0f);
    cudaGetSymbolAddress(&p_a1, g_a1f);
    cudaGetSymbolAddress(&p_ft, g_featf);

    cudaFuncSetAttribute(hmma_m64_kernel<2>, cudaFuncAttributeMaxDynamicSharedMemorySize, WO_SMEM_BYTES);
    cudaFuncSetAttribute(hmma_m64_kernel<1>, cudaFuncAttributeMaxDynamicSharedMemorySize, WO_SMEM_BYTES);
    cudaFuncSetAttribute(energy_f16_kernel,  cudaFuncAttributeMaxDynamicSharedMemorySize, EN_SMEM_BYTES);

    // 1. scan: mask compact + inits + embed/hidden/h1 scatter
    scan_kernel<<<SCAN_BLKS, 256>>>(mask, hidden, tok, emb,
                                    bih0, bhh0, bih1, bhh1, bout,
                                    energy, query, gates0, gates1, out_pred);

    // 2. global compaction
    gather_kernel<<<1, 256>>>();

    // 3. prep2: gathered enc -> fp16 compact + Wk split
    prep2_kernel<<<PREP2_BLKS, 256>>>(enc, Wk);

    // 4. query = hidden[1] @ Wq^T (fp16 2-term, K-split 4, atomic)
    hmma_m64_kernel<2><<<dim3(H_ / 128, 4), 256, WO_SMEM_BYTES>>>(
        (const __half*)p_h1, H_, Wq, H_, Wq, query, H_, 4);

    // 5. energy (fp16 2-term, compact A rows)
    energy_f16_kernel<<<dim3(H_ / 128, (B_ * S_) / 256), 256, EN_SMEM_BYTES>>>(
        (const __half*)p_ef, (const __half*)p_wh, (const __half*)p_wl,
        v, query, energy);

    // 6. fused masked softmax + compacted context
    softmax_context_kernel<<<dim3(B_, 4), 256>>>(energy, enc, out_attn);

    // 7. layer-0 gates + LSTM
    hmma_m64_kernel<2><<<dim3(G4H_ / 128, 4), 256, WO_SMEM_BYTES>>>(
        (const __half*)p_a0, KCAT0, Wih0, E_ + ENC_, Whh0, gates0, G4H_, 4);
    lstm_kernel<<<dim3(B_, H_ / 256), 256>>>(gates0, cell, out_cell, out_hid,
                                             (__half*)p_a1, KCAT1);

    // 8. layer-1 gates + LSTM
    hmma_m64_kernel<2><<<dim3(G4H_ / 128, 4), 256, WO_SMEM_BYTES>>>(
        (const __half*)p_a1, KCAT1, Wih1, H_, Whh1, gates1, G4H_, 4);
    lstm_kernel<<<dim3(B_, H_ / 256), 256>>>(gates1, cell + B_ * H_, out_cell + B_ * H_,
                                             out_hid + B_ * H_, (__half*)p_ft, FDIM_);

    // 9. prediction = feat @ Wout^T + bout (fp16 1-term, K-split 4, atomic)
    hmma_m64_kernel<1><<<dim3(V_ / 128, 4), 256, WO_SMEM_BYTES>>>(
        (const __half*)p_ft, FDIM_, Wout, FDIM_, Wout, out_pred, V_, 4);
}

// round 13
// speedup vs baseline: 2.0670x; 1.3136x over previous
#include <cuda_runtime.h>
#include <cuda_bf16.h>
#include <cuda_fp16.h>
#include <math.h>
#include <stdint.h>

#define B_   64
#define S_   256
#define H_   1024
#define ENC_ 1024
#define E_   512
#define V_   32000
#define FDIM_ (H_ + ENC_ + E_)   // 2560
#define G4H_  (4 * H_)           // 4096
#define KCAT0 2560
#define KCAT1 2048
#define WKSCALE 2048.0f
#define INVWK   (1.0f / 2048.0f)

// ---------------- scratch ----------------------------------------------------
#define OFF_QUERY   0
#define OFF_GATES0  (OFF_QUERY + B_ * H_)
#define OFF_GATES1  (OFF_GATES0 + B_ * G4H_)
#define OFF_ENERGY  (OFF_GATES1 + B_ * G4H_)
#define SCRATCH_TOTAL (OFF_ENERGY + B_ * S_)

__device__ __align__(16) float g_scratch[SCRATCH_TOTAL];
__device__ int g_sidx[B_ * S_];
__device__ int g_scnt[B_];
__device__ int g_gidx[B_ * S_];
__device__ int g_total;

// fp16 buffers (g_enc_f16 holds GATHERED unmasked rows, compact)
__device__ __align__(16) __half g_enc_f16[(long)B_ * S_ * ENC_];
__device__ __align__(16) __half g_wk_h[H_ * ENC_];
__device__ __align__(16) __half g_wk_l[H_ * ENC_];
__device__ __align__(16) __half g_h1f[B_ * H_];
__device__ __align__(16) __half g_a0f[B_ * KCAT0];
__device__ __align__(16) __half g_a1f[B_ * KCAT1];
__device__ __align__(16) __half g_featf[B_ * FDIM_];

// ===================== low-level helpers =====================================
__device__ __forceinline__ uint32_t smem_to_u32(const void* p) {
    uint32_t a;
    asm("{ .reg .u64 t; cvta.to.shared.u64 t, %1; cvt.u32.u64 %0, t; }" : "=r"(a) : "l"(p));
    return a;
}

#define CP16(dst_u32, src_ptr) \
    asm volatile("cp.async.cg.shared.global [%0], [%1], 16;" :: "r"(dst_u32), "l"(src_ptr))
#define CP_COMMIT() asm volatile("cp.async.commit_group;" ::: "memory")
template<int N> __device__ __forceinline__ void cp_wait() {
    asm volatile("cp.async.wait_group %0;" :: "n"(N) : "memory");
}

__device__ __forceinline__ void ldmx4(uint32_t addr, uint32_t r[4]) {
    asm volatile("ldmatrix.sync.aligned.m8n8.x4.shared.b16 {%0,%1,%2,%3}, [%4];"
        : "=r"(r[0]), "=r"(r[1]), "=r"(r[2]), "=r"(r[3]) : "r"(addr));
}

__device__ __forceinline__ void mma16816h(float* c, const uint32_t a[4],
                                          uint32_t b0, uint32_t b1) {
    asm volatile("mma.sync.aligned.m16n8k16.row.col.f32.f16.f16.f32 "
        "{%0,%1,%2,%3}, {%4,%5,%6,%7}, {%8,%9}, {%0,%1,%2,%3};"
        : "+f"(c[0]), "+f"(c[1]), "+f"(c[2]), "+f"(c[3])
        : "r"(a[0]), "r"(a[1]), "r"(a[2]), "r"(a[3]), "r"(b0), "r"(b1));
}

#define STS128(addr, a, b, c, d) \
    asm volatile("st.shared.v4.b32 [%0], {%1,%2,%3,%4};" \
        :: "r"(addr), "r"(a), "r"(b), "r"(c), "r"(d) : "memory")

#define LDS128U(addr, r0, r1, r2, r3) \
    asm volatile("ld.shared.v4.b32 {%0,%1,%2,%3}, [%4];" \
        : "=r"(r0), "=r"(r1), "=r"(r2), "=r"(r3) : "r"(addr))

__device__ __forceinline__ uint32_t swz(int row, int chunk16) {
    return (uint32_t)(row * 128 + ((chunk16 ^ (row & 7)) * 16));
}

// fp16 scaled split: w*2048 = hi + lo
__device__ __forceinline__ void split2h(float a, float b, uint32_t& hi, uint32_t& lo) {
    float as = a * WKSCALE, bs = b * WKSCALE;
    __half2 h2 = __floats2half2_rn(as, bs);
    float ra = as - __half2float(__low2half(h2));
    float rb = bs - __half2float(__high2half(h2));
    __half2 l2 = __floats2half2_rn(ra, rb);
    hi = *reinterpret_cast<uint32_t*>(&h2);
    lo = *reinterpret_cast<uint32_t*>(&l2);
}

// ===================== scan kernel ===========================================
// [0,64): mask scan + energy init + embed + hidden scatter
// [64,128): h1 fp16   [128,192): query zero
// [192,448): gates0 bias  [448,704): gates1 bias  [704,2704): out_pred = bout
// [2704,3728): Wk scaled fp16 split
#define SCAN_BLKS 3728

__global__ void scan_kernel(const int* __restrict__ mask,
                            const float* __restrict__ hidden,
                            const int* __restrict__ tok,
                            const float* __restrict__ emb,
                            const float* __restrict__ wk,
                            const float* __restrict__ bih0,
                            const float* __restrict__ bhh0,
                            const float* __restrict__ bih1,
                            const float* __restrict__ bhh1,
                            const float* __restrict__ bout,
                            float* __restrict__ energy,
                            float* __restrict__ query,
                            float* __restrict__ gates0,
                            float* __restrict__ gates1,
                            float* __restrict__ out_pred) {
    const int tid = threadIdx.x;
    const int blk = blockIdx.x;
    if (blk < 64) {
        const int b = blk;
        __shared__ int sc[256];
        int m = (mask[b * S_ + tid] != 0) ? 1 : 0;
        sc[tid] = m;
        __syncthreads();
#pragma unroll
        for (int off = 1; off < 256; off <<= 1) {
            int t = (tid >= off) ? sc[tid - off] : 0;
            __syncthreads();
            sc[tid] += t;
            __syncthreads();
        }
        int total = sc[255];
        int my = sc[tid] - m;
        if (m) g_sidx[b * S_ + my] = tid;
        if (tid >= total) g_sidx[b * S_ + tid] = 0;
        energy[b * S_ + tid] = m ? 0.f : -1e10f;
        if (tid == 0) g_scnt[b] = total;
        const int t = tok[b];
        for (int j = tid; j < E_; j += 256) {
            __half hv = __float2half_rn(emb[(long)t * E_ + j]);
            g_a0f[b * KCAT0 + j] = hv;
            g_featf[b * FDIM_ + (H_ + ENC_) + j] = hv;
        }
        for (int j = tid; j < H_; j += 256) {
            g_a0f[b * KCAT0 + (E_ + ENC_) + j] = __float2half_rn(hidden[b * H_ + j]);
            g_a1f[b * KCAT1 + H_ + j] = __float2half_rn(hidden[B_ * H_ + b * H_ + j]);
        }
    } else if (blk < 128) {
        long i = ((long)(blk - 64) * 256 + tid) * 4;
        float4 v = *reinterpret_cast<const float4*>(hidden + (long)B_ * H_ + i);
        __half2 h0 = __floats2half2_rn(v.x, v.y);
        __half2 h1 = __floats2half2_rn(v.z, v.w);
        uint2 o = {*reinterpret_cast<uint32_t*>(&h0), *reinterpret_cast<uint32_t*>(&h1)};
        *reinterpret_cast<uint2*>(g_h1f + i) = o;
    } else if (blk < 192) {
        long i = ((long)(blk - 128) * 256 + tid) * 4;
        float4 z = {0.f, 0.f, 0.f, 0.f};
        *reinterpret_cast<float4*>(query + i) = z;
    } else if (blk < 448) {
        long i = ((long)(blk - 192) * 256 + tid) * 4;
        int n = (int)(i & (G4H_ - 1));
        float4 o = {bih0[n] + bhh0[n], bih0[n + 1] + bhh0[n + 1],
                    bih0[n + 2] + bhh0[n + 2], bih0[n + 3] + bhh0[n + 3]};
        *reinterpret_cast<float4*>(gates0 + i) = o;
    } else if (blk < 704) {
        long i = ((long)(blk - 448) * 256 + tid) * 4;
        int n = (int)(i & (G4H_ - 1));
        float4 o = {bih1[n] + bhh1[n], bih1[n + 1] + bhh1[n + 1],
                    bih1[n + 2] + bhh1[n + 2], bih1[n + 3] + bhh1[n + 3]};
        *reinterpret_cast<float4*>(gates1 + i) = o;
    } else if (blk < 2704) {
        long i = ((long)(blk - 704) * 1024 + tid * 4);
        int col = (int)(i % V_);
        float4 o = {bout[col], bout[col + 1], bout[col + 2], bout[col + 3]};
        *reinterpret_cast<float4*>(out_pred + i) = o;
    } else {
        long i = ((long)(blk - 2704) * 256 + tid) * 4;
        float4 v = *reinterpret_cast<const float4*>(wk + i);
        uint2 Hq, Lq;
        split2h(v.x, v.y, Hq.x, Lq.x);
        split2h(v.z, v.w, Hq.y, Lq.y);
        *reinterpret_cast<uint2*>(g_wk_h + i) = Hq;
        *reinterpret_cast<uint2*>(g_wk_l + i) = Lq;
    }
}

// ===================== global gather =========================================
__global__ void gather_kernel() {
    __shared__ int offs[B_ + 1];
    const int tid = threadIdx.x;
    if (tid == 0) {
        int acc = 0;
        for (int b = 0; b < B_; b++) { offs[b] = acc; acc += g_scnt[b]; }
        offs[B_] = acc;
        g_total = acc;
    }
    __syncthreads();
    for (int b = 0; b < B_; b++) {
        int o = offs[b], cnt = offs[b + 1] - o;
        for (int j = tid; j < cnt; j += 256)
            g_gidx[o + j] = b * S_ + g_sidx[b * S_ + j];
    }
    int total = offs[B_];
    for (int j = total + tid; j < B_ * S_; j += 256) g_gidx[j] = 0;
}

// ===================== prep2: gathered enc conversion ========================
#define ENC_RBLKS ((B_ * S_) / 4)            // 4096 blocks, 4 rows each

__global__ void prep2_kernel(const float* __restrict__ enc) {
    const int tid = threadIdx.x;
    int row0 = blockIdx.x * 4;
    int lim = (g_total + 255) & ~255;
    if (row0 >= lim) return;
    const int e = tid * 4;
#pragma unroll
    for (int rr = 0; rr < 4; rr++) {
        int row = row0 + rr;
        long src = (long)g_gidx[row] * ENC_ + e;
        float4 v = *reinterpret_cast<const float4*>(enc + src);
        __half2 h0 = __floats2half2_rn(v.x, v.y);
        __half2 h1 = __floats2half2_rn(v.z, v.w);
        uint2 o = {*reinterpret_cast<uint32_t*>(&h0), *reinterpret_cast<uint32_t*>(&h1)};
        *reinterpret_cast<uint2*>(g_enc_f16 + (long)row * ENC_ + e) = o;
    }
}

// ===================== fat-B HMMA kernel (fp16, cp.async B staging) ==========
// smem: A 2x8KB | Braw 2x32KB (swizzled fp32) | Bh 16KB | Bl 16KB
#define WO_SMEM_BYTES (1024 + 16384 + 65536 + 32768)

template<int NT>
__global__ __launch_bounds__(256, 2)
void hmma_m64_kernel(const __half* __restrict__ a_g,
                     int Ktot,
                     const float* __restrict__ B1, int k1,
                     const float* __restrict__ B2,
                     float* __restrict__ C, int ldc, int nks) {
    extern __shared__ char smem[];
    uint32_t sb = smem_to_u32(smem);
    uint32_t tiles = (sb + 1023) & ~1023u;
    const uint32_t A_   = tiles;
    const uint32_t BRAW = tiles + 16384;
    const uint32_t BH   = tiles + 81920;
    const uint32_t BL   = BH + 16384;

    const int tid = threadIdx.x;
    const int wid = tid >> 5, lane = tid & 31;
    const int warp_m = (wid & 1) * 32;
    const int warp_n = (wid >> 1) * 32;
    const int n0 = blockIdx.x * 128;
    const int k2 = Ktot - k1;

    const int KT = Ktot / 64;
    const int kt0 = (int)blockIdx.y * (KT / nks);
    const int kt1 = kt0 + KT / nks;

    const int br = tid >> 1, bhalf = tid & 1;
    const int srr = br * 2 + bhalf;            // conversion-read sub-row

    float c[2][4][4];
#pragma unroll
    for (int i = 0; i < 2; i++)
#pragma unroll
        for (int j = 0; j < 4; j++)
#pragma unroll
            for (int k = 0; k < 4; k++) c[i][j][k] = 0.f;

    auto load_stage = [&](int kt) {
        const int s = kt & 1;
        const int c0 = kt * 64;
        // A: 64 rows x 64 halves
#pragma unroll
        for (int i = 0; i < 2; i++) {
            int idx = tid + i * 256;
            int r = idx >> 3, cc = idx & 7;
            CP16(A_ + s * 8192 + swz(r, cc), a_g + (long)r * Ktot + c0 + cc * 8);
        }
        // B raw fp32: 128 rows x 64 floats, swizzled 16B chunks
#pragma unroll
        for (int i = 0; i < 8; i++) {
            int g = tid + i * 256;
            int brow = g >> 4, j = g & 15;
            int sr = brow * 2 + (j >> 3), cch = j & 7;
            uint32_t dst = BRAW + s * 32768 +
                           (uint32_t)(sr * 128 + ((cch ^ (sr & 7)) * 16));
            const float* src = (c0 < k1)
                ? B1 + (long)(n0 + brow) * k1 + c0 + j * 4
                : B2 + (long)(n0 + brow) * k2 + (c0 - k1) + j * 4;
            CP16(dst, src);
        }
    };

    load_stage(kt0);
    CP_COMMIT();

    for (int kt = kt0; kt < kt1; kt++) {
        const int s = kt & 1;
        if (kt + 1 < kt1) {
            load_stage(kt + 1);
            CP_COMMIT();
            cp_wait<1>();
        } else {
            cp_wait<0>();
        }
        __syncthreads();
        // convert Braw[s] -> Bh/Bl (this thread: row br, k-half bhalf)
        {
            const uint32_t braw = BRAW + s * 32768;
            const int sx = srr & 7;
#pragma unroll
            for (int jo = 0; jo < 4; jo++) {
                uint32_t o0 = braw + (uint32_t)(srr * 128 + (((2 * jo)     ^ sx) * 16));
                uint32_t o1 = braw + (uint32_t)(srr * 128 + (((2 * jo + 1) ^ sx) * 16));
                uint32_t u0, u1, u2, u3, w0, w1, w2, w3;
                LDS128U(o0, u0, u1, u2, u3);
                LDS128U(o1, w0, w1, w2, w3);
                uint4 Hq, Lq;
                split2h(__uint_as_float(u0), __uint_as_float(u1), Hq.x, Lq.x);
                split2h(__uint_as_float(u2), __uint_as_float(u3), Hq.y, Lq.y);
                split2h(__uint_as_float(w0), __uint_as_float(w1), Hq.z, Lq.z);
                split2h(__uint_as_float(w2), __uint_as_float(w3), Hq.w, Lq.w);
                uint32_t off = swz(br, bhalf * 4 + jo);
                STS128(BH + off, Hq.x, Hq.y, Hq.z, Hq.w);
                if (NT == 2) STS128(BL + off, Lq.x, Lq.y, Lq.z, Lq.w);
            }
        }
        __syncthreads();
        // compute
        {
            const uint32_t Ah = A_ + s * 8192;
            const int lm = lane & 15, lh = lane >> 4;
#pragma unroll
            for (int ks = 0; ks < 4; ks++) {
                const int ch = ks * 2 + lh;
                uint32_t ah[2][4];
#pragma unroll
                for (int mf = 0; mf < 2; mf++) {
                    uint32_t off = swz(warp_m + mf * 16 + lm, ch);
                    ldmx4(Ah + off, ah[mf]);
                }
                uint32_t bb[2][4];
#pragma unroll
                for (int nf2 = 0; nf2 < 2; nf2++) {
                    uint32_t off = swz(warp_n + nf2 * 16 + lm, ch);
                    ldmx4(BH + off, bb[nf2]);
                }
#pragma unroll
                for (int nf2 = 0; nf2 < 2; nf2++)
#pragma unroll
                    for (int mf = 0; mf < 2; mf++) {
                        mma16816h(c[mf][nf2 * 2 + 0], ah[mf], bb[nf2][0], bb[nf2][2]);
                        mma16816h(c[mf][nf2 * 2 + 1], ah[mf], bb[nf2][1], bb[nf2][3]);
                    }
                if (NT == 2) {
#pragma unroll
                    for (int nf2 = 0; nf2 < 2; nf2++) {
                        uint32_t off = swz(warp_n + nf2 * 16 + lm, ch);
                        ldmx4(BL + off, bb[nf2]);
                    }
#pragma unroll
                    for (int nf2 = 0; nf2 < 2; nf2++)
#pragma unroll
                        for (int mf = 0; mf < 2; mf++) {
                            mma16816h(c[mf][nf2 * 2 + 0], ah[mf], bb[nf2][0], bb[nf2][2]);
                            mma16816h(c[mf][nf2 * 2 + 1], ah[mf], bb[nf2][1], bb[nf2][3]);
                        }
                }
            }
        }
        __syncthreads();
    }

#pragma unroll
    for (int mf = 0; mf < 2; mf++)
#pragma unroll
        for (int nf = 0; nf < 4; nf++) {
            int col = n0 + warp_n + nf * 8 + (lane & 3) * 2;
            int r0 = warp_m + mf * 16 + (lane >> 2);
            atomicAdd(&C[(long)r0 * ldc + col],           c[mf][nf][0] * INVWK);
            atomicAdd(&C[(long)r0 * ldc + col + 1],       c[mf][nf][1] * INVWK);
            atomicAdd(&C[(long)(r0 + 8) * ldc + col],     c[mf][nf][2] * INVWK);
            atomicAdd(&C[(long)(r0 + 8) * ldc + col + 1], c[mf][nf][3] * INVWK);
        }
}

// ===================== energy: fp16 2-term, compact 256-row tiles ============
#define EN_T 16384
#define EN_STAGE (4 * EN_T)
#define EN_SMEM_BYTES (2048 + 2 * EN_STAGE)

__global__ __launch_bounds__(256, 1)
void energy_f16_kernel(const __half* __restrict__ ef,
                       const __half* __restrict__ wh,
                       const __half* __restrict__ wl,
                       const float* __restrict__ vvec,
                       const float* __restrict__ query,
                       float* __restrict__ energy) {
    const int total = g_total;
    const int mt = (int)blockIdx.y * 256;
    if (mt >= total) return;

    extern __shared__ char smem[];
    uint32_t sb = smem_to_u32(smem);
    uint32_t tiles = (sb + 2048 + 1023) & ~1023u;

    const int tid = threadIdx.x;
    const int wid = tid >> 5, lane = tid & 31;
    const int warp_m = (wid & 3) * 32;
    const int warp_n = (wid >> 2) * 64;
    const int n0 = blockIdx.x * 128;

    float* vs = (float*)smem;
    int*   sid = (int*)(vs + 128);
    if (tid < 128) vs[tid] = vvec[n0 + tid];
    sid[tid] = g_gidx[mt + tid];
    __syncthreads();

    const int rb = tid >> 3, cc8 = (tid & 7) * 8;
    uint32_t a0off[4], boff[4], soffs[4];
#pragma unroll
    for (int i = 0; i < 4; i++) {
        int r = rb + 32 * i;
        soffs[i] = swz(r, tid & 7);
        a0off[i] = (uint32_t)(mt + r) * ENC_ + cc8;
        boff[i]  = (uint32_t)(n0 + r) * ENC_ + cc8;
    }

    float c0[2][8][4], c1[2][8][4];
#pragma unroll
    for (int i = 0; i < 2; i++)
#pragma unroll
        for (int j = 0; j < 8; j++)
#pragma unroll
            for (int k = 0; k < 4; k++) { c0[i][j][k] = 0.f; c1[i][j][k] = 0.f; }

    auto load_stage = [&](int c0v, uint32_t stg) {
#pragma unroll
        for (int i = 0; i < 4; i++) {
            CP16(stg + soffs[i],            ef + a0off[i] + c0v);
            CP16(stg + EN_T + soffs[i],     ef + a0off[i] + 128 * ENC_ + c0v);
            CP16(stg + 2 * EN_T + soffs[i], wh + boff[i] + c0v);
            CP16(stg + 3 * EN_T + soffs[i], wl + boff[i] + c0v);
        }
    };

    load_stage(0, tiles);
    CP_COMMIT();

    const int KT = ENC_ / 64;
    for (int kt = 0; kt < KT; kt++) {
        uint32_t stg = tiles + (kt & 1) * EN_STAGE;
        if (kt + 1 < KT) {
            load_stage((kt + 1) * 64, tiles + ((kt + 1) & 1) * EN_STAGE);
            CP_COMMIT();
            cp_wait<1>();
        } else {
            cp_wait<0>();
        }
        __syncthreads();
        {
            const uint32_t A0 = stg, A1 = stg + EN_T;
            const uint32_t Bh = stg + 2 * EN_T, Bl = stg + 3 * EN_T;
            const int lm = lane & 15, lh = lane >> 4;
#pragma unroll
            for (int ks = 0; ks < 4; ks++) {
                const int ch = ks * 2 + lh;
                uint32_t a0[2][4], a1[2][4];
#pragma unroll
                for (int mf = 0; mf < 2; mf++) {
                    uint32_t off = swz(warp_m + mf * 16 + lm, ch);
                    ldmx4(A0 + off, a0[mf]);
                    ldmx4(A1 + off, a1[mf]);
                }
                uint32_t bb[4][4];
#pragma unroll
                for (int nf2 = 0; nf2 < 4; nf2++) {
                    uint32_t off = swz(warp_n + nf2 * 16 + lm, ch);
                    ldmx4(Bh + off, bb[nf2]);
                }
#pragma unroll
                for (int nf2 = 0; nf2 < 4; nf2++)
#pragma unroll
                    for (int mf = 0; mf < 2; mf++) {
                        mma16816h(c0[mf][nf2 * 2 + 0], a0[mf], bb[nf2][0], bb[nf2][2]);
                        mma16816h(c0[mf][nf2 * 2 + 1], a0[mf], bb[nf2][1], bb[nf2][3]);
                        mma16816h(c1[mf][nf2 * 2 + 0], a1[mf], bb[nf2][0], bb[nf2][2]);
                        mma16816h(c1[mf][nf2 * 2 + 1], a1[mf], bb[nf2][1], bb[nf2][3]);
                    }
#pragma unroll
                for (int nf2 = 0; nf2 < 4; nf2++) {
                    uint32_t off = swz(warp_n + nf2 * 16 + lm, ch);
                    ldmx4(Bl + off, bb[nf2]);
                }
#pragma unroll
                for (int nf2 = 0; nf2 < 4; nf2++)
#pragma unroll
                    for (int mf = 0; mf < 2; mf++) {
                        mma16816h(c0[mf][nf2 * 2 + 0], a0[mf], bb[nf2][0], bb[nf2][2]);
                        mma16816h(c0[mf][nf2 * 2 + 1], a0[mf], bb[nf2][1], bb[nf2][3]);
                        mma16816h(c1[mf][nf2 * 2 + 0], a1[mf], bb[nf2][0], bb[nf2][2]);
                        mma16816h(c1[mf][nf2 * 2 + 1], a1[mf], bb[nf2][1], bb[nf2][3]);
                    }
            }
        }
        __syncthreads();
    }

#pragma unroll
    for (int t = 0; t < 2; t++) {
#pragma unroll
        for (int mf = 0; mf < 2; mf++) {
            int rl = t * 128 + warp_m + mf * 16 + (lane >> 2);
            int rh = rl + 8;
            int gl = sid[rl], gh = sid[rh];
            const float* ql = query + (long)(gl >> 8) * H_ + n0;
            const float* qh = query + (long)(gh >> 8) * H_ + n0;
            float s_lo = 0.f, s_hi = 0.f;
#pragma unroll
            for (int nf = 0; nf < 8; nf++) {
                int col = warp_n + nf * 8 + (lane & 3) * 2;
                float v0 = vs[col], v1 = vs[col + 1];
                float* cc = t ? c1[mf][nf] : c0[mf][nf];
                s_lo += v0 * tanhf(ql[col] + cc[0] * INVWK) + v1 * tanhf(ql[col + 1] + cc[1] * INVWK);
                s_hi += v0 * tanhf(qh[col] + cc[2] * INVWK) + v1 * tanhf(qh[col + 1] + cc[3] * INVWK);
            }
            s_lo += __shfl_xor_sync(0xffffffff, s_lo, 1);
            s_lo += __shfl_xor_sync(0xffffffff, s_lo, 2);
            s_hi += __shfl_xor_sync(0xffffffff, s_hi, 1);
            s_hi += __shfl_xor_sync(0xffffffff, s_hi, 2);
            if ((lane & 3) == 0) {
                if (mt + rl < total) atomicAdd(&energy[gl], s_lo);
                if (mt + rh < total) atomicAdd(&energy[gh], s_hi);
            }
        }
    }
}

// ===================== fused softmax + compacted context =====================
__global__ void softmax_context_kernel(const float* __restrict__ energy,
                                       const float* __restrict__ enc,
                                       float* __restrict__ out_attn) {
    __shared__ float red[256];
    __shared__ float w[256];
    __shared__ int sid[256];
    __shared__ int cnts;
    const int b = blockIdx.x;
    const int tid = threadIdx.x;

    float val = energy[b * S_ + tid];
    red[tid] = val;
    sid[tid] = g_sidx[b * S_ + tid];
    if (tid == 0) cnts = g_scnt[b];
    __syncthreads();
#pragma unroll
    for (int off = 128; off > 0; off >>= 1) {
        if (tid < off) red[tid] = fmaxf(red[tid], red[tid + off]);
        __syncthreads();
    }
    float mx = red[0];
    __syncthreads();
    float ex = expf(val - mx);
    red[tid] = ex;
    __syncthreads();
#pragma unroll
    for (int off = 128; off > 0; off >>= 1) {
        if (tid < off) red[tid] += red[tid + off];
        __syncthreads();
    }
    float aw = ex / red[0];
    if (blockIdx.y == 0) out_attn[b * S_ + tid] = aw;
    w[tid] = aw;
    __syncthreads();

    const int cnt = cnts;
    const int col = blockIdx.y * 256 + tid;
    const float* eb = enc + (long)b * S_ * ENC_;
    float a0 = 0.f, a1 = 0.f, a2 = 0.f, a3 = 0.f;
    int j = 0;
    for (; j + 4 <= cnt; j += 4) {
        a0 = fmaf(w[sid[j]],     eb[(long)sid[j] * ENC_ + col],     a0);
        a1 = fmaf(w[sid[j + 1]], eb[(long)sid[j + 1] * ENC_ + col], a1);
        a2 = fmaf(w[sid[j + 2]], eb[(long)sid[j + 2] * ENC_ + col], a2);
        a3 = fmaf(w[sid[j + 3]], eb[(long)sid[j + 3] * ENC_ + col], a3);
    }
    for (; j < cnt; j++)
        a0 = fmaf(w[sid[j]], eb[(long)sid[j] * ENC_ + col], a0);
    float acc = (a0 + a1) + (a2 + a3);
    __half hv = __float2half_rn(acc);
    g_a0f[b * KCAT0 + E_ + col] = hv;
    g_featf[b * FDIM_ + H_ + col] = hv;
}

// ===================== LSTM pointwise ========================================
__global__ void lstm_kernel(const float* __restrict__ gates,
                            const float* __restrict__ c_prev,
                            float* __restrict__ c_out,
                            float* __restrict__ h_out_f32,
                            __half* __restrict__ hb,
                            int sb) {
    const int b = blockIdx.x;
    const int idx = blockIdx.y * 256 + threadIdx.x;
    float gi = gates[b * G4H_ + idx];
    float gf = gates[b * G4H_ + H_ + idx];
    float gg = gates[b * G4H_ + 2 * H_ + idx];
    float go = gates[b * G4H_ + 3 * H_ + idx];
    float c  = c_prev[b * H_ + idx];
    float si = 1.f / (1.f + expf(-gi));
    float sf = 1.f / (1.f + expf(-gf));
    float so = 1.f / (1.f + expf(-go));
    float cn = sf * c + si * tanhf(gg);
    float hn = so * tanhf(cn);
    c_out[b * H_ + idx]     = cn;
    h_out_f32[b * H_ + idx] = hn;
    hb[b * sb + idx] = __float2half_rn(hn);
}

// ===================== launch ================================================
extern "C" void kernel_launch(void* const* d_in, const int* in_sizes, int n_in,
                              void* d_out, int out_size) {
    const int*   tok    = (const int*)  d_in[0];
    const float* hidden = (const float*)d_in[1];
    const float* cell   = (const float*)d_in[2];
    const float* enc    = (const float*)d_in[3];
    const int*   mask   = (const int*)  d_in[4];
    const float* emb    = (const float*)d_in[5];
    const float* Wq     = (const float*)d_in[6];
    const float* Wk     = (const float*)d_in[7];
    const float* v      = (const float*)d_in[8];
    const float* Wih0   = (const float*)d_in[9];
    const float* Whh0   = (const float*)d_in[10];
    const float* bih0   = (const float*)d_in[11];
    const float* bhh0   = (const float*)d_in[12];
    const float* Wih1   = (const float*)d_in[13];
    const float* Whh1   = (const float*)d_in[14];
    const float* bih1   = (const float*)d_in[15];
    const float* bhh1   = (const float*)d_in[16];
    const float* Wout   = (const float*)d_in[17];
    const float* bout   = (const float*)d_in[18];

    float* out      = (float*)d_out;
    float* out_pred = out;
    float* out_hid  = out + (long)B_ * V_;
    float* out_cell = out_hid + 2 * B_ * H_;
    float* out_attn = out_cell + 2 * B_ * H_;

    void* sp = nullptr;
    cudaGetSymbolAddress(&sp, g_scratch);
    float* scratch = (float*)sp;
    float* query  = scratch + OFF_QUERY;
    float* gates0 = scratch + OFF_GATES0;
    float* gates1 = scratch + OFF_GATES1;
    float* energy = scratch + OFF_ENERGY;

    void *p_ef, *p_wh, *p_wl, *p_h1, *p_a0, *p_a1, *p_ft;
    cudaGetSymbolAddress(&p_ef, g_enc_f16);
    cudaGetSymbolAddress(&p_wh, g_wk_h);
    cudaGetSymbolAddress(&p_wl, g_wk_l);
    cudaGetSymbolAddress(&p_h1, g_h1f);
    cudaGetSymbolAddress(&p_a0, g_a0f);
    cudaGetSymbolAddress(&p_a1, g_a1f);
    cudaGetSymbolAddress(&p_ft, g_featf);

    cudaFuncSetAttribute(hmma_m64_kernel<2>, cudaFuncAttributeMaxDynamicSharedMemorySize, WO_SMEM_BYTES);
    cudaFuncSetAttribute(hmma_m64_kernel<1>, cudaFuncAttributeMaxDynamicSharedMemorySize, WO_SMEM_BYTES);
    cudaFuncSetAttribute(energy_f16_kernel,  cudaFuncAttributeMaxDynamicSharedMemorySize, EN_SMEM_BYTES);

    // 1. scan: mask compact + inits + scatters + Wk split
    scan_kernel<<<SCAN_BLKS, 256>>>(mask, hidden, tok, emb, Wk,
                                    bih0, bhh0, bih1, bhh1, bout,
                                    energy, query, gates0, gates1, out_pred);

    // 2. global compaction
    gather_kernel<<<1, 256>>>();

    // 3. prep2: gathered enc -> fp16 compact
    prep2_kernel<<<ENC_RBLKS, 256>>>(enc);

    // 4. query = hidden[1] @ Wq^T (fp16 2-term, K-split 8, atomic)
    hmma_m64_kernel<2><<<dim3(H_ / 128, 8), 256, WO_SMEM_BYTES>>>(
        (const __half*)p_h1, H_, Wq, H_, Wq, query, H_, 8);

    // 5. energy (fp16 2-term, compact A rows)
    energy_f16_kernel<<<dim3(H_ / 128, (B_ * S_) / 256), 256, EN_SMEM_BYTES>>>(
        (const __half*)p_ef, (const __half*)p_wh, (const __half*)p_wl,
        v, query, energy);

    // 6. fused masked softmax + compacted context
    softmax_context_kernel<<<dim3(B_, 4), 256>>>(energy, enc, out_attn);

    // 7. layer-0 gates (K-split 5) + LSTM
    hmma_m64_kernel<2><<<dim3(G4H_ / 128, 5), 256, WO_SMEM_BYTES>>>(
        (const __half*)p_a0, KCAT0, Wih0, E_ + ENC_, Whh0, gates0, G4H_, 5);
    lstm_kernel<<<dim3(B_, H_ / 256), 256>>>(gates0, cell, out_cell, out_hid,
                                             (__half*)p_a1, KCAT1);

    // 8. layer-1 gates (K-split 8) + LSTM
    hmma_m64_kernel<2><<<dim3(G4H_ / 128, 8), 256, WO_SMEM_BYTES>>>(
        (const __half*)p_a1, KCAT1, Wih1, H_, Whh1, gates1, G4H_, 8);
    lstm_kernel<<<dim3(B_, H_ / 256), 256>>>(gates1, cell + B_ * H_, out_cell + B_ * H_,
                                             out_hid + B_ * H_, (__half*)p_ft, FDIM_);

    // 9. prediction = feat @ Wout^T + bout (fp16 1-term, K-split 4, atomic)
    hmma_m64_kernel<1><<<dim3(V_ / 128, 4), 256, WO_SMEM_BYTES>>>(
        (const __half*)p_ft, FDIM_, Wout, FDIM_, Wout, out_pred, V_, 4);
}

// round 14
// speedup vs baseline: 2.4691x; 1.1945x over previous
#include <cuda_runtime.h>
#include <cuda_bf16.h>
#include <cuda_fp16.h>
#include <math.h>
#include <stdint.h>

#define B_   64
#define S_   256
#define H_   1024
#define ENC_ 1024
#define E_   512
#define V_   32000
#define FDIM_ (H_ + ENC_ + E_)   // 2560
#define G4H_  (4 * H_)           // 4096
#define KCAT0 2560
#define KCAT1 2048
#define WKSCALE 2048.0f
#define INVWK   (1.0f / 2048.0f)

// ---------------- scratch ----------------------------------------------------
#define OFF_QUERY   0
#define OFF_GATES0  (OFF_QUERY + B_ * H_)
#define OFF_GATES1  (OFF_GATES0 + B_ * G4H_)
#define OFF_ENERGY  (OFF_GATES1 + B_ * G4H_)
#define SCRATCH_TOTAL (OFF_ENERGY + B_ * S_)

__device__ __align__(16) float g_scratch[SCRATCH_TOTAL];
__device__ int g_sidx[B_ * S_];
__device__ int g_scnt[B_];
__device__ int g_gidx[B_ * S_];
__device__ int g_total;

// fp16 buffers (g_enc_f16 holds GATHERED unmasked rows, compact)
__device__ __align__(16) __half g_enc_f16[(long)B_ * S_ * ENC_];
__device__ __align__(16) __half g_wk_h[H_ * ENC_];
__device__ __align__(16) __half g_h1f[B_ * H_];
__device__ __align__(16) __half g_a0f[B_ * KCAT0];
__device__ __align__(16) __half g_a1f[B_ * KCAT1];
__device__ __align__(16) __half g_featf[B_ * FDIM_];

// ===================== low-level helpers =====================================
__device__ __forceinline__ uint32_t smem_to_u32(const void* p) {
    uint32_t a;
    asm("{ .reg .u64 t; cvta.to.shared.u64 t, %1; cvt.u32.u64 %0, t; }" : "=r"(a) : "l"(p));
    return a;
}

#define CP16(dst_u32, src_ptr) \
    asm volatile("cp.async.cg.shared.global [%0], [%1], 16;" :: "r"(dst_u32), "l"(src_ptr))
#define CP_COMMIT() asm volatile("cp.async.commit_group;" ::: "memory")
template<int N> __device__ __forceinline__ void cp_wait() {
    asm volatile("cp.async.wait_group %0;" :: "n"(N) : "memory");
}

__device__ __forceinline__ void ldmx4(uint32_t addr, uint32_t r[4]) {
    asm volatile("ldmatrix.sync.aligned.m8n8.x4.shared.b16 {%0,%1,%2,%3}, [%4];"
        : "=r"(r[0]), "=r"(r[1]), "=r"(r[2]), "=r"(r[3]) : "r"(addr));
}

__device__ __forceinline__ void mma16816h(float* c, const uint32_t a[4],
                                          uint32_t b0, uint32_t b1) {
    asm volatile("mma.sync.aligned.m16n8k16.row.col.f32.f16.f16.f32 "
        "{%0,%1,%2,%3}, {%4,%5,%6,%7}, {%8,%9}, {%0,%1,%2,%3};"
        : "+f"(c[0]), "+f"(c[1]), "+f"(c[2]), "+f"(c[3])
        : "r"(a[0]), "r"(a[1]), "r"(a[2]), "r"(a[3]), "r"(b0), "r"(b1));
}

#define STS128(addr, a, b, c, d) \
    asm volatile("st.shared.v4.b32 [%0], {%1,%2,%3,%4};" \
        :: "r"(addr), "r"(a), "r"(b), "r"(c), "r"(d) : "memory")

#define LDS128U(addr, r0, r1, r2, r3) \
    asm volatile("ld.shared.v4.b32 {%0,%1,%2,%3}, [%4];" \
        : "=r"(r0), "=r"(r1), "=r"(r2), "=r"(r3) : "r"(addr))

__device__ __forceinline__ uint32_t swz(int row, int chunk16) {
    return (uint32_t)(row * 128 + ((chunk16 ^ (row & 7)) * 16));
}

// fp16 scaled split: w*2048 = hi + lo
__device__ __forceinline__ void split2h(float a, float b, uint32_t& hi, uint32_t& lo) {
    float as = a * WKSCALE, bs = b * WKSCALE;
    __half2 h2 = __floats2half2_rn(as, bs);
    float ra = as - __half2float(__low2half(h2));
    float rb = bs - __half2float(__high2half(h2));
    __half2 l2 = __floats2half2_rn(ra, rb);
    hi = *reinterpret_cast<uint32_t*>(&h2);
    lo = *reinterpret_cast<uint32_t*>(&l2);
}

// ===================== scan kernel ===========================================
// [0,64): mask scan + energy init + embed + hidden scatter
// [64,128): h1 fp16   [128,192): query zero
// [192,448): gates0 bias  [448,704): gates1 bias
// [704,1728): Wk scaled fp16 (hi only)
#define SCAN_BLKS 1728

__global__ void scan_kernel(const int* __restrict__ mask,
                            const float* __restrict__ hidden,
                            const int* __restrict__ tok,
                            const float* __restrict__ emb,
                            const float* __restrict__ wk,
                            const float* __restrict__ bih0,
                            const float* __restrict__ bhh0,
                            const float* __restrict__ bih1,
                            const float* __restrict__ bhh1,
                            float* __restrict__ energy,
                            float* __restrict__ query,
                            float* __restrict__ gates0,
                            float* __restrict__ gates1) {
    const int tid = threadIdx.x;
    const int blk = blockIdx.x;
    if (blk < 64) {
        const int b = blk;
        __shared__ int sc[256];
        int m = (mask[b * S_ + tid] != 0) ? 1 : 0;
        sc[tid] = m;
        __syncthreads();
#pragma unroll
        for (int off = 1; off < 256; off <<= 1) {
            int t = (tid >= off) ? sc[tid - off] : 0;
            __syncthreads();
            sc[tid] += t;
            __syncthreads();
        }
        int total = sc[255];
        int my = sc[tid] - m;
        if (m) g_sidx[b * S_ + my] = tid;
        if (tid >= total) g_sidx[b * S_ + tid] = 0;
        energy[b * S_ + tid] = m ? 0.f : -1e10f;
        if (tid == 0) g_scnt[b] = total;
        const int t = tok[b];
        for (int j = tid; j < E_; j += 256) {
            __half hv = __float2half_rn(emb[(long)t * E_ + j]);
            g_a0f[b * KCAT0 + j] = hv;
            g_featf[b * FDIM_ + (H_ + ENC_) + j] = hv;
        }
        for (int j = tid; j < H_; j += 256) {
            g_a0f[b * KCAT0 + (E_ + ENC_) + j] = __float2half_rn(hidden[b * H_ + j]);
            g_a1f[b * KCAT1 + H_ + j] = __float2half_rn(hidden[B_ * H_ + b * H_ + j]);
        }
    } else if (blk < 128) {
        long i = ((long)(blk - 64) * 256 + tid) * 4;
        float4 v = *reinterpret_cast<const float4*>(hidden + (long)B_ * H_ + i);
        __half2 h0 = __floats2half2_rn(v.x, v.y);
        __half2 h1 = __floats2half2_rn(v.z, v.w);
        uint2 o = {*reinterpret_cast<uint32_t*>(&h0), *reinterpret_cast<uint32_t*>(&h1)};
        *reinterpret_cast<uint2*>(g_h1f + i) = o;
    } else if (blk < 192) {
        long i = ((long)(blk - 128) * 256 + tid) * 4;
        float4 z = {0.f, 0.f, 0.f, 0.f};
        *reinterpret_cast<float4*>(query + i) = z;
    } else if (blk < 448) {
        long i = ((long)(blk - 192) * 256 + tid) * 4;
        int n = (int)(i & (G4H_ - 1));
        float4 o = {bih0[n] + bhh0[n], bih0[n + 1] + bhh0[n + 1],
                    bih0[n + 2] + bhh0[n + 2], bih0[n + 3] + bhh0[n + 3]};
        *reinterpret_cast<float4*>(gates0 + i) = o;
    } else if (blk < 704) {
        long i = ((long)(blk - 448) * 256 + tid) * 4;
        int n = (int)(i & (G4H_ - 1));
        float4 o = {bih1[n] + bhh1[n], bih1[n + 1] + bhh1[n + 1],
                    bih1[n + 2] + bhh1[n + 2], bih1[n + 3] + bhh1[n + 3]};
        *reinterpret_cast<float4*>(gates1 + i) = o;
    } else {
        long i = ((long)(blk - 704) * 256 + tid) * 4;
        float4 v = *reinterpret_cast<const float4*>(wk + i);
        __half2 h0 = __floats2half2_rn(v.x * WKSCALE, v.y * WKSCALE);
        __half2 h1 = __floats2half2_rn(v.z * WKSCALE, v.w * WKSCALE);
        uint2 o = {*reinterpret_cast<uint32_t*>(&h0), *reinterpret_cast<uint32_t*>(&h1)};
        *reinterpret_cast<uint2*>(g_wk_h + i) = o;
    }
}

// ===================== global gather =========================================
__global__ void gather_kernel() {
    __shared__ int offs[B_ + 1];
    const int tid = threadIdx.x;
    if (tid == 0) {
        int acc = 0;
        for (int b = 0; b < B_; b++) { offs[b] = acc; acc += g_scnt[b]; }
        offs[B_] = acc;
        g_total = acc;
    }
    __syncthreads();
    for (int b = 0; b < B_; b++) {
        int o = offs[b], cnt = offs[b + 1] - o;
        for (int j = tid; j < cnt; j += 256)
            g_gidx[o + j] = b * S_ + g_sidx[b * S_ + j];
    }
    int total = offs[B_];
    for (int j = total + tid; j < B_ * S_; j += 256) g_gidx[j] = 0;
}

// ===================== prep2: gathered enc conversion ========================
#define ENC_RBLKS ((B_ * S_) / 4)

__global__ void prep2_kernel(const float* __restrict__ enc) {
    const int tid = threadIdx.x;
    int row0 = blockIdx.x * 4;
    int lim = (g_total + 255) & ~255;
    if (row0 >= lim) return;
    const int e = tid * 4;
#pragma unroll
    for (int rr = 0; rr < 4; rr++) {
        int row = row0 + rr;
        long src = (long)g_gidx[row] * ENC_ + e;
        float4 v = *reinterpret_cast<const float4*>(enc + src);
        __half2 h0 = __floats2half2_rn(v.x, v.y);
        __half2 h1 = __floats2half2_rn(v.z, v.w);
        uint2 o = {*reinterpret_cast<uint32_t*>(&h0), *reinterpret_cast<uint32_t*>(&h1)};
        *reinterpret_cast<uint2*>(g_enc_f16 + (long)row * ENC_ + e) = o;
    }
}

// ===================== fat-B HMMA kernel (fp16, cp.async B staging) ==========
// smem: A 2x8KB | Braw 2x32KB (swizzled fp32) | Bh 16KB | Bl 16KB
#define WO_SMEM_BYTES (1024 + 16384 + 65536 + 32768)

template<int NT, bool ATOMIC>
__global__ __launch_bounds__(256, 2)
void hmma_m64_kernel(const __half* __restrict__ a_g,
                     int Ktot,
                     const float* __restrict__ B1, int k1,
                     const float* __restrict__ B2,
                     const float* __restrict__ bias1,
                     float* __restrict__ C, int ldc, int nks) {
    extern __shared__ char smem[];
    uint32_t sb = smem_to_u32(smem);
    uint32_t tiles = (sb + 1023) & ~1023u;
    const uint32_t A_   = tiles;
    const uint32_t BRAW = tiles + 16384;
    const uint32_t BH   = tiles + 81920;
    const uint32_t BL   = BH + 16384;

    const int tid = threadIdx.x;
    const int wid = tid >> 5, lane = tid & 31;
    const int warp_m = (wid & 1) * 32;
    const int warp_n = (wid >> 1) * 32;
    const int n0 = blockIdx.x * 128;
    const int k2 = Ktot - k1;

    const int KT = Ktot / 64;
    const int kt0 = (int)blockIdx.y * (KT / nks);
    const int kt1 = kt0 + KT / nks;

    const int br = tid >> 1, bhalf = tid & 1;
    const int srr = br * 2 + bhalf;

    float c[2][4][4];
#pragma unroll
    for (int i = 0; i < 2; i++)
#pragma unroll
        for (int j = 0; j < 4; j++)
#pragma unroll
            for (int k = 0; k < 4; k++) c[i][j][k] = 0.f;

    auto load_stage = [&](int kt) {
        const int s = kt & 1;
        const int c0 = kt * 64;
#pragma unroll
        for (int i = 0; i < 2; i++) {
            int idx = tid + i * 256;
            int r = idx >> 3, cc = idx & 7;
            CP16(A_ + s * 8192 + swz(r, cc), a_g + (long)r * Ktot + c0 + cc * 8);
        }
#pragma unroll
        for (int i = 0; i < 8; i++) {
            int g = tid + i * 256;
            int brow = g >> 4, j = g & 15;
            int sr = brow * 2 + (j >> 3), cch = j & 7;
            uint32_t dst = BRAW + s * 32768 +
                           (uint32_t)(sr * 128 + ((cch ^ (sr & 7)) * 16));
            const float* src = (c0 < k1)
                ? B1 + (long)(n0 + brow) * k1 + c0 + j * 4
                : B2 + (long)(n0 + brow) * k2 + (c0 - k1) + j * 4;
            CP16(dst, src);
        }
    };

    load_stage(kt0);
    CP_COMMIT();

    for (int kt = kt0; kt < kt1; kt++) {
        const int s = kt & 1;
        if (kt + 1 < kt1) {
            load_stage(kt + 1);
            CP_COMMIT();
            cp_wait<1>();
        } else {
            cp_wait<0>();
        }
        __syncthreads();
        {
            const uint32_t braw = BRAW + s * 32768;
            const int sx = srr & 7;
#pragma unroll
            for (int jo = 0; jo < 4; jo++) {
                uint32_t o0 = braw + (uint32_t)(srr * 128 + (((2 * jo)     ^ sx) * 16));
                uint32_t o1 = braw + (uint32_t)(srr * 128 + (((2 * jo + 1) ^ sx) * 16));
                uint32_t u0, u1, u2, u3, w0, w1, w2, w3;
                LDS128U(o0, u0, u1, u2, u3);
                LDS128U(o1, w0, w1, w2, w3);
                uint4 Hq, Lq;
                split2h(__uint_as_float(u0), __uint_as_float(u1), Hq.x, Lq.x);
                split2h(__uint_as_float(u2), __uint_as_float(u3), Hq.y, Lq.y);
                split2h(__uint_as_float(w0), __uint_as_float(w1), Hq.z, Lq.z);
                split2h(__uint_as_float(w2), __uint_as_float(w3), Hq.w, Lq.w);
                uint32_t off = swz(br, bhalf * 4 + jo);
                STS128(BH + off, Hq.x, Hq.y, Hq.z, Hq.w);
                if (NT == 2) STS128(BL + off, Lq.x, Lq.y, Lq.z, Lq.w);
            }
        }
        __syncthreads();
        {
            const uint32_t Ah = A_ + s * 8192;
            const int lm = lane & 15, lh = lane >> 4;
#pragma unroll
            for (int ks = 0; ks < 4; ks++) {
                const int ch = ks * 2 + lh;
                uint32_t ah[2][4];
#pragma unroll
                for (int mf = 0; mf < 2; mf++) {
                    uint32_t off = swz(warp_m + mf * 16 + lm, ch);
                    ldmx4(Ah + off, ah[mf]);
                }
                uint32_t bb[2][4];
#pragma unroll
                for (int nf2 = 0; nf2 < 2; nf2++) {
                    uint32_t off = swz(warp_n + nf2 * 16 + lm, ch);
                    ldmx4(BH + off, bb[nf2]);
                }
#pragma unroll
                for (int nf2 = 0; nf2 < 2; nf2++)
#pragma unroll
                    for (int mf = 0; mf < 2; mf++) {
                        mma16816h(c[mf][nf2 * 2 + 0], ah[mf], bb[nf2][0], bb[nf2][2]);
                        mma16816h(c[mf][nf2 * 2 + 1], ah[mf], bb[nf2][1], bb[nf2][3]);
                    }
                if (NT == 2) {
#pragma unroll
                    for (int nf2 = 0; nf2 < 2; nf2++) {
                        uint32_t off = swz(warp_n + nf2 * 16 + lm, ch);
                        ldmx4(BL + off, bb[nf2]);
                    }
#pragma unroll
                    for (int nf2 = 0; nf2 < 2; nf2++)
#pragma unroll
                        for (int mf = 0; mf < 2; mf++) {
                            mma16816h(c[mf][nf2 * 2 + 0], ah[mf], bb[nf2][0], bb[nf2][2]);
                            mma16816h(c[mf][nf2 * 2 + 1], ah[mf], bb[nf2][1], bb[nf2][3]);
                        }
                }
            }
        }
        __syncthreads();
    }

#pragma unroll
    for (int mf = 0; mf < 2; mf++)
#pragma unroll
        for (int nf = 0; nf < 4; nf++) {
            int col = n0 + warp_n + nf * 8 + (lane & 3) * 2;
            int r0 = warp_m + mf * 16 + (lane >> 2);
            if (ATOMIC) {
                atomicAdd(&C[(long)r0 * ldc + col],           c[mf][nf][0] * INVWK);
                atomicAdd(&C[(long)r0 * ldc + col + 1],       c[mf][nf][1] * INVWK);
                atomicAdd(&C[(long)(r0 + 8) * ldc + col],     c[mf][nf][2] * INVWK);
                atomicAdd(&C[(long)(r0 + 8) * ldc + col + 1], c[mf][nf][3] * INVWK);
            } else {
                float b0 = 0.f, b1 = 0.f;
                if (bias1) { b0 = bias1[col]; b1 = bias1[col + 1]; }
                float2 o0 = {c[mf][nf][0] * INVWK + b0, c[mf][nf][1] * INVWK + b1};
                float2 o1 = {c[mf][nf][2] * INVWK + b0, c[mf][nf][3] * INVWK + b1};
                *reinterpret_cast<float2*>(C + (long)r0 * ldc + col) = o0;
                *reinterpret_cast<float2*>(C + (long)(r0 + 8) * ldc + col) = o1;
            }
        }
}

// ===================== energy: fp16 1-term Wk, compact 256-row tiles =========
#define EN_T 16384
#define EN_STAGE (3 * EN_T)                 // A0 A1 Bh = 48KB
#define EN_SMEM_BYTES (2048 + 2 * EN_STAGE)

__global__ __launch_bounds__(256, 1)
void energy_f16_kernel(const __half* __restrict__ ef,
                       const __half* __restrict__ wh,
                       const float* __restrict__ vvec,
                       const float* __restrict__ query,
                       float* __restrict__ energy) {
    const int total = g_total;
    const int mt = (int)blockIdx.y * 256;
    if (mt >= total) return;

    extern __shared__ char smem[];
    uint32_t sb = smem_to_u32(smem);
    uint32_t tiles = (sb + 2048 + 1023) & ~1023u;

    const int tid = threadIdx.x;
    const int wid = tid >> 5, lane = tid & 31;
    const int warp_m = (wid & 3) * 32;
    const int warp_n = (wid >> 2) * 64;
    const int n0 = blockIdx.x * 128;

    float* vs = (float*)smem;
    int*   sid = (int*)(vs + 128);
    if (tid < 128) vs[tid] = vvec[n0 + tid];
    sid[tid] = g_gidx[mt + tid];
    __syncthreads();

    const int rb = tid >> 3, cc8 = (tid & 7) * 8;
    uint32_t a0off[4], boff[4], soffs[4];
#pragma unroll
    for (int i = 0; i < 4; i++) {
        int r = rb + 32 * i;
        soffs[i] = swz(r, tid & 7);
        a0off[i] = (uint32_t)(mt + r) * ENC_ + cc8;
        boff[i]  = (uint32_t)(n0 + r) * ENC_ + cc8;
    }

    float c0[2][8][4], c1[2][8][4];
#pragma unroll
    for (int i = 0; i < 2; i++)
#pragma unroll
        for (int j = 0; j < 8; j++)
#pragma unroll
            for (int k = 0; k < 4; k++) { c0[i][j][k] = 0.f; c1[i][j][k] = 0.f; }

    auto load_stage = [&](int c0v, uint32_t stg) {
#pragma unroll
        for (int i = 0; i < 4; i++) {
            CP16(stg + soffs[i],            ef + a0off[i] + c0v);
            CP16(stg + EN_T + soffs[i],     ef + a0off[i] + 128 * ENC_ + c0v);
            CP16(stg + 2 * EN_T + soffs[i], wh + boff[i] + c0v);
        }
    };

    load_stage(0, tiles);
    CP_COMMIT();

    const int KT = ENC_ / 64;
    for (int kt = 0; kt < KT; kt++) {
        uint32_t stg = tiles + (kt & 1) * EN_STAGE;
        if (kt + 1 < KT) {
            load_stage((kt + 1) * 64, tiles + ((kt + 1) & 1) * EN_STAGE);
            CP_COMMIT();
            cp_wait<1>();
        } else {
            cp_wait<0>();
        }
        __syncthreads();
        {
            const uint32_t A0 = stg, A1 = stg + EN_T;
            const uint32_t Bh = stg + 2 * EN_T;
            const int lm = lane & 15, lh = lane >> 4;
#pragma unroll
            for (int ks = 0; ks < 4; ks++) {
                const int ch = ks * 2 + lh;
                uint32_t a0[2][4], a1[2][4];
#pragma unroll
                for (int mf = 0; mf < 2; mf++) {
                    uint32_t off = swz(warp_m + mf * 16 + lm, ch);
                    ldmx4(A0 + off, a0[mf]);
                    ldmx4(A1 + off, a1[mf]);
                }
                uint32_t bb[4][4];
#pragma unroll
                for (int nf2 = 0; nf2 < 4; nf2++) {
                    uint32_t off = swz(warp_n + nf2 * 16 + lm, ch);
                    ldmx4(Bh + off, bb[nf2]);
                }
#pragma unroll
                for (int nf2 = 0; nf2 < 4; nf2++)
#pragma unroll
                    for (int mf = 0; mf < 2; mf++) {
                        mma16816h(c0[mf][nf2 * 2 + 0], a0[mf], bb[nf2][0], bb[nf2][2]);
                        mma16816h(c0[mf][nf2 * 2 + 1], a0[mf], bb[nf2][1], bb[nf2][3]);
                        mma16816h(c1[mf][nf2 * 2 + 0], a1[mf], bb[nf2][0], bb[nf2][2]);
                        mma16816h(c1[mf][nf2 * 2 + 1], a1[mf], bb[nf2][1], bb[nf2][3]);
                    }
            }
        }
        __syncthreads();
    }

#pragma unroll
    for (int t = 0; t < 2; t++) {
#pragma unroll
        for (int mf = 0; mf < 2; mf++) {
            int rl = t * 128 + warp_m + mf * 16 + (lane >> 2);
            int rh = rl + 8;
            int gl = sid[rl], gh = sid[rh];
            const float* ql = query + (long)(gl >> 8) * H_ + n0;
            const float* qh = query + (long)(gh >> 8) * H_ + n0;
            float s_lo = 0.f, s_hi = 0.f;
#pragma unroll
            for (int nf = 0; nf < 8; nf++) {
                int col = warp_n + nf * 8 + (lane & 3) * 2;
                float v0 = vs[col], v1 = vs[col + 1];
                float* cc = t ? c1[mf][nf] : c0[mf][nf];
                s_lo += v0 * tanhf(ql[col] + cc[0] * INVWK) + v1 * tanhf(ql[col + 1] + cc[1] * INVWK);
                s_hi += v0 * tanhf(qh[col] + cc[2] * INVWK) + v1 * tanhf(qh[col + 1] + cc[3] * INVWK);
            }
            s_lo += __shfl_xor_sync(0xffffffff, s_lo, 1);
            s_lo += __shfl_xor_sync(0xffffffff, s_lo, 2);
            s_hi += __shfl_xor_sync(0xffffffff, s_hi, 1);
            s_hi += __shfl_xor_sync(0xffffffff, s_hi, 2);
            if ((lane & 3) == 0) {
                if (mt + rl < total) atomicAdd(&energy[gl], s_lo);
                if (mt + rh < total) atomicAdd(&energy[gh], s_hi);
            }
        }
    }
}

// ===================== fused softmax + compacted context =====================
__global__ void softmax_context_kernel(const float* __restrict__ energy,
                                       const float* __restrict__ enc,
                                       float* __restrict__ out_attn) {
    __shared__ float red[256];
    __shared__ float w[256];
    __shared__ int sid[256];
    __shared__ int cnts;
    const int b = blockIdx.x;
    const int tid = threadIdx.x;

    float val = energy[b * S_ + tid];
    red[tid] = val;
    sid[tid] = g_sidx[b * S_ + tid];
    if (tid == 0) cnts = g_scnt[b];
    __syncthreads();
#pragma unroll
    for (int off = 128; off > 0; off >>= 1) {
        if (tid < off) red[tid] = fmaxf(red[tid], red[tid + off]);
        __syncthreads();
    }
    float mx = red[0];
    __syncthreads();
    float ex = expf(val - mx);
    red[tid] = ex;
    __syncthreads();
#pragma unroll
    for (int off = 128; off > 0; off >>= 1) {
        if (tid < off) red[tid] += red[tid + off];
        __syncthreads();
    }
    float aw = ex / red[0];
    if (blockIdx.y == 0) out_attn[b * S_ + tid] = aw;
    w[tid] = aw;
    __syncthreads();

    const int cnt = cnts;
    const int col = blockIdx.y * 256 + tid;
    const float* eb = enc + (long)b * S_ * ENC_;
    float a0 = 0.f, a1 = 0.f, a2 = 0.f, a3 = 0.f;
    int j = 0;
    for (; j + 4 <= cnt; j += 4) {
        a0 = fmaf(w[sid[j]],     eb[(long)sid[j] * ENC_ + col],     a0);
        a1 = fmaf(w[sid[j + 1]], eb[(long)sid[j + 1] * ENC_ + col], a1);
        a2 = fmaf(w[sid[j + 2]], eb[(long)sid[j + 2] * ENC_ + col], a2);
        a3 = fmaf(w[sid[j + 3]], eb[(long)sid[j + 3] * ENC_ + col], a3);
    }
    for (; j < cnt; j++)
        a0 = fmaf(w[sid[j]], eb[(long)sid[j] * ENC_ + col], a0);
    float acc = (a0 + a1) + (a2 + a3);
    __half hv = __float2half_rn(acc);
    g_a0f[b * KCAT0 + E_ + col] = hv;
    g_featf[b * FDIM_ + H_ + col] = hv;
}

// ===================== LSTM pointwise ========================================
__global__ void lstm_kernel(const float* __restrict__ gates,
                            const float* __restrict__ c_prev,
                            float* __restrict__ c_out,
                            float* __restrict__ h_out_f32,
                            __half* __restrict__ hb,
                            int sb) {
    const int b = blockIdx.x;
    const int idx = blockIdx.y * 256 + threadIdx.x;
    float gi = gates[b * G4H_ + idx];
    float gf = gates[b * G4H_ + H_ + idx];
    float gg = gates[b * G4H_ + 2 * H_ + idx];
    float go = gates[b * G4H_ + 3 * H_ + idx];
    float c  = c_prev[b * H_ + idx];
    float si = 1.f / (1.f + expf(-gi));
    float sf = 1.f / (1.f + expf(-gf));
    float so = 1.f / (1.f + expf(-go));
    float cn = sf * c + si * tanhf(gg);
    float hn = so * tanhf(cn);
    c_out[b * H_ + idx]     = cn;
    h_out_f32[b * H_ + idx] = hn;
    hb[b * sb + idx] = __float2half_rn(hn);
}

// ===================== launch ================================================
extern "C" void kernel_launch(void* const* d_in, const int* in_sizes, int n_in,
                              void* d_out, int out_size) {
    const int*   tok    = (const int*)  d_in[0];
    const float* hidden = (const float*)d_in[1];
    const float* cell   = (const float*)d_in[2];
    const float* enc    = (const float*)d_in[3];
    const int*   mask   = (const int*)  d_in[4];
    const float* emb    = (const float*)d_in[5];
    const float* Wq     = (const float*)d_in[6];
    const float* Wk     = (const float*)d_in[7];
    const float* v      = (const float*)d_in[8];
    const float* Wih0   = (const float*)d_in[9];
    const float* Whh0   = (const float*)d_in[10];
    const float* bih0   = (const float*)d_in[11];
    const float* bhh0   = (const float*)d_in[12];
    const float* Wih1   = (const float*)d_in[13];
    const float* Whh1   = (const float*)d_in[14];
    const float* bih1   = (const float*)d_in[15];
    const float* bhh1   = (const float*)d_in[16];
    const float* Wout   = (const float*)d_in[17];
    const float* bout   = (const float*)d_in[18];

    float* out      = (float*)d_out;
    float* out_pred = out;
    float* out_hid  = out + (long)B_ * V_;
    float* out_cell = out_hid + 2 * B_ * H_;
    float* out_attn = out_cell + 2 * B_ * H_;

    void* sp = nullptr;
    cudaGetSymbolAddress(&sp, g_scratch);
    float* scratch = (float*)sp;
    float* query  = scratch + OFF_QUERY;
    float* gates0 = scratch + OFF_GATES0;
    float* gates1 = scratch + OFF_GATES1;
    float* energy = scratch + OFF_ENERGY;

    void *p_ef, *p_wh, *p_h1, *p_a0, *p_a1, *p_ft;
    cudaGetSymbolAddress(&p_ef, g_enc_f16);
    cudaGetSymbolAddress(&p_wh, g_wk_h);
    cudaGetSymbolAddress(&p_h1, g_h1f);
    cudaGetSymbolAddress(&p_a0, g_a0f);
    cudaGetSymbolAddress(&p_a1, g_a1f);
    cudaGetSymbolAddress(&p_ft, g_featf);

    cudaFuncSetAttribute((const void*)hmma_m64_kernel<2, true>,  cudaFuncAttributeMaxDynamicSharedMemorySize, WO_SMEM_BYTES);
    cudaFuncSetAttribute((const void*)hmma_m64_kernel<1, false>, cudaFuncAttributeMaxDynamicSharedMemorySize, WO_SMEM_BYTES);
    cudaFuncSetAttribute(energy_f16_kernel, cudaFuncAttributeMaxDynamicSharedMemorySize, EN_SMEM_BYTES);

    // 1. scan: mask compact + inits + scatters + Wk fp16 (hi only)
    scan_kernel<<<SCAN_BLKS, 256>>>(mask, hidden, tok, emb, Wk,
                                    bih0, bhh0, bih1, bhh1,
                                    energy, query, gates0, gates1);

    // 2. global compaction
    gather_kernel<<<1, 256>>>();

    // 3. prep2: gathered enc -> fp16 compact
    prep2_kernel<<<ENC_RBLKS, 256>>>(enc);

    // 4. query = hidden[1] @ Wq^T (fp16 2-term, K-split 8, atomic)
    hmma_m64_kernel<2, true><<<dim3(H_ / 128, 8), 256, WO_SMEM_BYTES>>>(
        (const __half*)p_h1, H_, Wq, H_, Wq, nullptr, query, H_, 8);

    // 5. energy (fp16 1-term Wk, compact A rows)
    energy_f16_kernel<<<dim3(H_ / 128, (B_ * S_) / 256), 256, EN_SMEM_BYTES>>>(
        (const __half*)p_ef, (const __half*)p_wh, v, query, energy);

    // 6. fused masked softmax + compacted context
    softmax_context_kernel<<<dim3(B_, 4), 256>>>(energy, enc, out_attn);

    // 7. layer-0 gates (K-split 5) + LSTM
    hmma_m64_kernel<2, true><<<dim3(G4H_ / 128, 5), 256, WO_SMEM_BYTES>>>(
        (const __half*)p_a0, KCAT0, Wih0, E_ + ENC_, Whh0, nullptr, gates0, G4H_, 5);
    lstm_kernel<<<dim3(B_, H_ / 256), 256>>>(gates0, cell, out_cell, out_hid,
                                             (__half*)p_a1, KCAT1);

    // 8. layer-1 gates (K-split 8) + LSTM
    hmma_m64_kernel<2, true><<<dim3(G4H_ / 128, 8), 256, WO_SMEM_BYTES>>>(
        (const __half*)p_a1, KCAT1, Wih1, H_, Whh1, nullptr, gates1, G4H_, 8);
    lstm_kernel<<<dim3(B_, H_ / 256), 256>>>(gates1, cell + B_ * H_, out_cell + B_ * H_,
                                             out_hid + B_ * H_, (__half*)p_ft, FDIM_);

    // 9. prediction = feat @ Wout^T + bout (fp16 1-term, single K-pass, non-atomic)
    hmma_m64_kernel<1, false><<<dim3(V_ / 128, 1), 256, WO_SMEM_BYTES>>>(
        (const __half*)p_ft, FDIM_, Wout, FDIM_, Wout, bout, out_pred, V_, 1);
}

// round 15
// speedup vs baseline: 2.8174x; 1.1411x over previous
#include <cuda_runtime.h>
#include <cuda_bf16.h>
#include <cuda_fp16.h>
#include <math.h>
#include <stdint.h>

#define B_   64
#define S_   256
#define H_   1024
#define ENC_ 1024
#define E_   512
#define V_   32000
#define FDIM_ (H_ + ENC_ + E_)   // 2560
#define G4H_  (4 * H_)           // 4096
#define KCAT0 2560
#define KCAT1 2048
#define WKSCALE 2048.0f
#define INVWK   (1.0f / 2048.0f)

// ---------------- scratch ----------------------------------------------------
#define OFF_QUERY   0
#define OFF_GATES0  (OFF_QUERY + B_ * H_)
#define OFF_GATES1  (OFF_GATES0 + B_ * G4H_)
#define OFF_ENERGY  (OFF_GATES1 + B_ * G4H_)
#define SCRATCH_TOTAL (OFF_ENERGY + B_ * S_)

__device__ __align__(16) float g_scratch[SCRATCH_TOTAL];
__device__ int g_sidx[B_ * S_];
__device__ int g_scnt[B_];
__device__ int g_gidx[B_ * S_];
__device__ int g_ctr;          // compacted-row counter; reset by wout each launch

// fp16 buffers (g_enc_f16 holds GATHERED unmasked rows, compact)
__device__ __align__(16) __half g_enc_f16[(long)B_ * S_ * ENC_];
__device__ __align__(16) __half g_wk_h[H_ * ENC_];
__device__ __align__(16) __half g_h1f[B_ * H_];
__device__ __align__(16) __half g_a0f[B_ * KCAT0];
__device__ __align__(16) __half g_a1f[B_ * KCAT1];
__device__ __align__(16) __half g_featf[B_ * FDIM_];

// ===================== low-level helpers =====================================
__device__ __forceinline__ uint32_t smem_to_u32(const void* p) {
    uint32_t a;
    asm("{ .reg .u64 t; cvta.to.shared.u64 t, %1; cvt.u32.u64 %0, t; }" : "=r"(a) : "l"(p));
    return a;
}

#define CP16(dst_u32, src_ptr) \
    asm volatile("cp.async.cg.shared.global [%0], [%1], 16;" :: "r"(dst_u32), "l"(src_ptr))
#define CP_COMMIT() asm volatile("cp.async.commit_group;" ::: "memory")
template<int N> __device__ __forceinline__ void cp_wait() {
    asm volatile("cp.async.wait_group %0;" :: "n"(N) : "memory");
}

__device__ __forceinline__ void ldmx4(uint32_t addr, uint32_t r[4]) {
    asm volatile("ldmatrix.sync.aligned.m8n8.x4.shared.b16 {%0,%1,%2,%3}, [%4];"
        : "=r"(r[0]), "=r"(r[1]), "=r"(r[2]), "=r"(r[3]) : "r"(addr));
}

__device__ __forceinline__ void mma16816h(float* c, const uint32_t a[4],
                                          uint32_t b0, uint32_t b1) {
    asm volatile("mma.sync.aligned.m16n8k16.row.col.f32.f16.f16.f32 "
        "{%0,%1,%2,%3}, {%4,%5,%6,%7}, {%8,%9}, {%0,%1,%2,%3};"
        : "+f"(c[0]), "+f"(c[1]), "+f"(c[2]), "+f"(c[3])
        : "r"(a[0]), "r"(a[1]), "r"(a[2]), "r"(a[3]), "r"(b0), "r"(b1));
}

#define STS128(addr, a, b, c, d) \
    asm volatile("st.shared.v4.b32 [%0], {%1,%2,%3,%4};" \
        :: "r"(addr), "r"(a), "r"(b), "r"(c), "r"(d) : "memory")

#define LDS128U(addr, r0, r1, r2, r3) \
    asm volatile("ld.shared.v4.b32 {%0,%1,%2,%3}, [%4];" \
        : "=r"(r0), "=r"(r1), "=r"(r2), "=r"(r3) : "r"(addr))

__device__ __forceinline__ uint32_t swz(int row, int chunk16) {
    return (uint32_t)(row * 128 + ((chunk16 ^ (row & 7)) * 16));
}

// fp16 scaled split: w*2048 = hi + lo
__device__ __forceinline__ void split2h(float a, float b, uint32_t& hi, uint32_t& lo) {
    float as = a * WKSCALE, bs = b * WKSCALE;
    __half2 h2 = __floats2half2_rn(as, bs);
    float ra = as - __half2float(__low2half(h2));
    float rb = bs - __half2float(__high2half(h2));
    __half2 l2 = __floats2half2_rn(ra, rb);
    hi = *reinterpret_cast<uint32_t*>(&h2);
    lo = *reinterpret_cast<uint32_t*>(&l2);
}

// ===================== scan kernel ===========================================
// [0,64): mask scan + gidx (atomic base) + energy init + embed + hidden scatter
// [64,128): h1 fp16   [128,192): query zero
// [192,448): gates0 bias  [448,704): gates1 bias
// [704,1728): Wk scaled fp16 (hi only)
#define SCAN_BLKS 1728

__global__ void scan_kernel(const int* __restrict__ mask,
                            const float* __restrict__ hidden,
                            const int* __restrict__ tok,
                            const float* __restrict__ emb,
                            const float* __restrict__ wk,
                            const float* __restrict__ bih0,
                            const float* __restrict__ bhh0,
                            const float* __restrict__ bih1,
                            const float* __restrict__ bhh1,
                            float* __restrict__ energy,
                            float* __restrict__ query,
                            float* __restrict__ gates0,
                            float* __restrict__ gates1) {
    const int tid = threadIdx.x;
    const int blk = blockIdx.x;
    if (blk < 64) {
        const int b = blk;
        __shared__ int sc[256];
        __shared__ int base_s;
        int m = (mask[b * S_ + tid] != 0) ? 1 : 0;
        sc[tid] = m;
        __syncthreads();
#pragma unroll
        for (int off = 1; off < 256; off <<= 1) {
            int t = (tid >= off) ? sc[tid - off] : 0;
            __syncthreads();
            sc[tid] += t;
            __syncthreads();
        }
        int total = sc[255];
        int my = sc[tid] - m;
        if (m) g_sidx[b * S_ + my] = tid;
        if (tid >= total) g_sidx[b * S_ + tid] = 0;
        energy[b * S_ + tid] = m ? 0.f : -1e10f;
        if (tid == 0) {
            g_scnt[b] = total;
            base_s = atomicAdd(&g_ctr, total);
        }
        __syncthreads();
        if (m) g_gidx[base_s + my] = b * S_ + tid;
        const int t = tok[b];
        for (int j = tid; j < E_; j += 256) {
            __half hv = __float2half_rn(emb[(long)t * E_ + j]);
            g_a0f[b * KCAT0 + j] = hv;
            g_featf[b * FDIM_ + (H_ + ENC_) + j] = hv;
        }
        for (int j = tid; j < H_; j += 256) {
            g_a0f[b * KCAT0 + (E_ + ENC_) + j] = __float2half_rn(hidden[b * H_ + j]);
            g_a1f[b * KCAT1 + H_ + j] = __float2half_rn(hidden[B_ * H_ + b * H_ + j]);
        }
    } else if (blk < 128) {
        long i = ((long)(blk - 64) * 256 + tid) * 4;
        float4 v = *reinterpret_cast<const float4*>(hidden + (long)B_ * H_ + i);
        __half2 h0 = __floats2half2_rn(v.x, v.y);
        __half2 h1 = __floats2half2_rn(v.z, v.w);
        uint2 o = {*reinterpret_cast<uint32_t*>(&h0), *reinterpret_cast<uint32_t*>(&h1)};
        *reinterpret_cast<uint2*>(g_h1f + i) = o;
    } else if (blk < 192) {
        long i = ((long)(blk - 128) * 256 + tid) * 4;
        float4 z = {0.f, 0.f, 0.f, 0.f};
        *reinterpret_cast<float4*>(query + i) = z;
    } else if (blk < 448) {
        long i = ((long)(blk - 192) * 256 + tid) * 4;
        int n = (int)(i & (G4H_ - 1));
        float4 o = {bih0[n] + bhh0[n], bih0[n + 1] + bhh0[n + 1],
                    bih0[n + 2] + bhh0[n + 2], bih0[n + 3] + bhh0[n + 3]};
        *reinterpret_cast<float4*>(gates0 + i) = o;
    } else if (blk < 704) {
        long i = ((long)(blk - 448) * 256 + tid) * 4;
        int n = (int)(i & (G4H_ - 1));
        float4 o = {bih1[n] + bhh1[n], bih1[n + 1] + bhh1[n + 1],
                    bih1[n + 2] + bhh1[n + 2], bih1[n + 3] + bhh1[n + 3]};
        *reinterpret_cast<float4*>(gates1 + i) = o;
    } else {
        long i = ((long)(blk - 704) * 256 + tid) * 4;
        float4 v = *reinterpret_cast<const float4*>(wk + i);
        __half2 h0 = __floats2half2_rn(v.x * WKSCALE, v.y * WKSCALE);
        __half2 h1 = __floats2half2_rn(v.z * WKSCALE, v.w * WKSCALE);
        uint2 o = {*reinterpret_cast<uint32_t*>(&h0), *reinterpret_cast<uint32_t*>(&h1)};
        *reinterpret_cast<uint2*>(g_wk_h + i) = o;
    }
}

// ===================== prep2: gathered enc conversion ========================
#define ENC_RBLKS ((B_ * S_) / 4)

__global__ void prep2_kernel(const float* __restrict__ enc) {
    const int tid = threadIdx.x;
    int row0 = blockIdx.x * 4;
    int lim = (g_ctr + 255) & ~255;
    if (row0 >= lim) return;
    const int e = tid * 4;
#pragma unroll
    for (int rr = 0; rr < 4; rr++) {
        int row = row0 + rr;
        long src = (long)g_gidx[row] * ENC_ + e;
        float4 v = *reinterpret_cast<const float4*>(enc + src);
        __half2 h0 = __floats2half2_rn(v.x, v.y);
        __half2 h1 = __floats2half2_rn(v.z, v.w);
        uint2 o = {*reinterpret_cast<uint32_t*>(&h0), *reinterpret_cast<uint32_t*>(&h1)};
        *reinterpret_cast<uint2*>(g_enc_f16 + (long)row * ENC_ + e) = o;
    }
}

// ===================== fat-B HMMA kernel (fp16, cp.async B staging) ==========
// smem: A 2x8KB | Braw 2x32KB (swizzled fp32) | Bh 16KB | Bl 16KB
#define WO_SMEM_BYTES (1024 + 16384 + 65536 + 32768)

template<int NT, bool ATOMIC>
__global__ __launch_bounds__(256, 2)
void hmma_m64_kernel(const __half* __restrict__ a_g,
                     int Ktot,
                     const float* __restrict__ B1, int k1,
                     const float* __restrict__ B2,
                     const float* __restrict__ bias1,
                     float* __restrict__ C, int ldc, int nks) {
    extern __shared__ char smem[];
    uint32_t sb = smem_to_u32(smem);
    uint32_t tiles = (sb + 1023) & ~1023u;
    const uint32_t A_   = tiles;
    const uint32_t BRAW = tiles + 16384;
    const uint32_t BH   = tiles + 81920;
    const uint32_t BL   = BH + 16384;

    const int tid = threadIdx.x;
    const int wid = tid >> 5, lane = tid & 31;
    const int warp_m = (wid & 1) * 32;
    const int warp_n = (wid >> 1) * 32;
    const int n0 = blockIdx.x * 128;
    const int k2 = Ktot - k1;

    // wout (the final, non-atomic instance) resets the compaction counter
    // for the next launch/replay.
    if (!ATOMIC && tid == 0 && blockIdx.x == 0 && blockIdx.y == 0) g_ctr = 0;

    const int KT = Ktot / 64;
    const int kt0 = (int)blockIdx.y * (KT / nks);
    const int kt1 = kt0 + KT / nks;

    const int br = tid >> 1, bhalf = tid & 1;
    const int srr = br * 2 + bhalf;

    float c[2][4][4];
#pragma unroll
    for (int i = 0; i < 2; i++)
#pragma unroll
        for (int j = 0; j < 4; j++)
#pragma unroll
            for (int k = 0; k < 4; k++) c[i][j][k] = 0.f;

    auto load_stage = [&](int kt) {
        const int s = kt & 1;
        const int c0 = kt * 64;
#pragma unroll
        for (int i = 0; i < 2; i++) {
            int idx = tid + i * 256;
            int r = idx >> 3, cc = idx & 7;
            CP16(A_ + s * 8192 + swz(r, cc), a_g + (long)r * Ktot + c0 + cc * 8);
        }
#pragma unroll
        for (int i = 0; i < 8; i++) {
            int g = tid + i * 256;
            int brow = g >> 4, j = g & 15;
            int sr = brow * 2 + (j >> 3), cch = j & 7;
            uint32_t dst = BRAW + s * 32768 +
                           (uint32_t)(sr * 128 + ((cch ^ (sr & 7)) * 16));
            const float* src = (c0 < k1)
                ? B1 + (long)(n0 + brow) * k1 + c0 + j * 4
                : B2 + (long)(n0 + brow) * k2 + (c0 - k1) + j * 4;
            CP16(dst, src);
        }
    };

    load_stage(kt0);
    CP_COMMIT();

    for (int kt = kt0; kt < kt1; kt++) {
        const int s = kt & 1;
        if (kt + 1 < kt1) {
            load_stage(kt + 1);
            CP_COMMIT();
            cp_wait<1>();
        } else {
            cp_wait<0>();
        }
        __syncthreads();
        {
            const uint32_t braw = BRAW + s * 32768;
            const int sx = srr & 7;
#pragma unroll
            for (int jo = 0; jo < 4; jo++) {
                uint32_t o0 = braw + (uint32_t)(srr * 128 + (((2 * jo)     ^ sx) * 16));
                uint32_t o1 = braw + (uint32_t)(srr * 128 + (((2 * jo + 1) ^ sx) * 16));
                uint32_t u0, u1, u2, u3, w0, w1, w2, w3;
                LDS128U(o0, u0, u1, u2, u3);
                LDS128U(o1, w0, w1, w2, w3);
                uint4 Hq, Lq;
                split2h(__uint_as_float(u0), __uint_as_float(u1), Hq.x, Lq.x);
                split2h(__uint_as_float(u2), __uint_as_float(u3), Hq.y, Lq.y);
                split2h(__uint_as_float(w0), __uint_as_float(w1), Hq.z, Lq.z);
                split2h(__uint_as_float(w2), __uint_as_float(w3), Hq.w, Lq.w);
                uint32_t off = swz(br, bhalf * 4 + jo);
                STS128(BH + off, Hq.x, Hq.y, Hq.z, Hq.w);
                if (NT == 2) STS128(BL + off, Lq.x, Lq.y, Lq.z, Lq.w);
            }
        }
        __syncthreads();
        {
            const uint32_t Ah = A_ + s * 8192;
            const int lm = lane & 15, lh = lane >> 4;
#pragma unroll
            for (int ks = 0; ks < 4; ks++) {
                const int ch = ks * 2 + lh;
                uint32_t ah[2][4];
#pragma unroll
                for (int mf = 0; mf < 2; mf++) {
                    uint32_t off = swz(warp_m + mf * 16 + lm, ch);
                    ldmx4(Ah + off, ah[mf]);
                }
                uint32_t bb[2][4];
#pragma unroll
                for (int nf2 = 0; nf2 < 2; nf2++) {
                    uint32_t off = swz(warp_n + nf2 * 16 + lm, ch);
                    ldmx4(BH + off, bb[nf2]);
                }
#pragma unroll
                for (int nf2 = 0; nf2 < 2; nf2++)
#pragma unroll
                    for (int mf = 0; mf < 2; mf++) {
                        mma16816h(c[mf][nf2 * 2 + 0], ah[mf], bb[nf2][0], bb[nf2][2]);
                        mma16816h(c[mf][nf2 * 2 + 1], ah[mf], bb[nf2][1], bb[nf2][3]);
                    }
                if (NT == 2) {
#pragma unroll
                    for (int nf2 = 0; nf2 < 2; nf2++) {
                        uint32_t off = swz(warp_n + nf2 * 16 + lm, ch);
                        ldmx4(BL + off, bb[nf2]);
                    }
#pragma unroll
                    for (int nf2 = 0; nf2 < 2; nf2++)
#pragma unroll
                        for (int mf = 0; mf < 2; mf++) {
                            mma16816h(c[mf][nf2 * 2 + 0], ah[mf], bb[nf2][0], bb[nf2][2]);
                            mma16816h(c[mf][nf2 * 2 + 1], ah[mf], bb[nf2][1], bb[nf2][3]);
                        }
                }
            }
        }
        __syncthreads();
    }

#pragma unroll
    for (int mf = 0; mf < 2; mf++)
#pragma unroll
        for (int nf = 0; nf < 4; nf++) {
            int col = n0 + warp_n + nf * 8 + (lane & 3) * 2;
            int r0 = warp_m + mf * 16 + (lane >> 2);
            if (ATOMIC) {
                atomicAdd(&C[(long)r0 * ldc + col],           c[mf][nf][0] * INVWK);
                atomicAdd(&C[(long)r0 * ldc + col + 1],       c[mf][nf][1] * INVWK);
                atomicAdd(&C[(long)(r0 + 8) * ldc + col],     c[mf][nf][2] * INVWK);
                atomicAdd(&C[(long)(r0 + 8) * ldc + col + 1], c[mf][nf][3] * INVWK);
            } else {
                float b0 = 0.f, b1 = 0.f;
                if (bias1) { b0 = bias1[col]; b1 = bias1[col + 1]; }
                float2 o0 = {c[mf][nf][0] * INVWK + b0, c[mf][nf][1] * INVWK + b1};
                float2 o1 = {c[mf][nf][2] * INVWK + b0, c[mf][nf][3] * INVWK + b1};
                *reinterpret_cast<float2*>(C + (long)r0 * ldc + col) = o0;
                *reinterpret_cast<float2*>(C + (long)(r0 + 8) * ldc + col) = o1;
            }
        }
}

// ===================== energy: fp16 1-term Wk, compact 256-row tiles =========
#define EN_T 16384
#define EN_STAGE (3 * EN_T)                 // A0 A1 Bh = 48KB
#define EN_SMEM_BYTES (2048 + 2 * EN_STAGE)

__global__ __launch_bounds__(256, 1)
void energy_f16_kernel(const __half* __restrict__ ef,
                       const __half* __restrict__ wh,
                       const float* __restrict__ vvec,
                       const float* __restrict__ query,
                       float* __restrict__ energy) {
    const int total = g_ctr;
    const int mt = (int)blockIdx.y * 256;
    if (mt >= total) return;

    extern __shared__ char smem[];
    uint32_t sb = smem_to_u32(smem);
    uint32_t tiles = (sb + 2048 + 1023) & ~1023u;

    const int tid = threadIdx.x;
    const int wid = tid >> 5, lane = tid & 31;
    const int warp_m = (wid & 3) * 32;
    const int warp_n = (wid >> 2) * 64;
    const int n0 = blockIdx.x * 128;

    float* vs = (float*)smem;
    int*   sid = (int*)(vs + 128);
    if (tid < 128) vs[tid] = vvec[n0 + tid];
    sid[tid] = g_gidx[mt + tid];
    __syncthreads();

    const int rb = tid >> 3, cc8 = (tid & 7) * 8;
    uint32_t a0off[4], boff[4], soffs[4];
#pragma unroll
    for (int i = 0; i < 4; i++) {
        int r = rb + 32 * i;
        soffs[i] = swz(r, tid & 7);
        a0off[i] = (uint32_t)(mt + r) * ENC_ + cc8;
        boff[i]  = (uint32_t)(n0 + r) * ENC_ + cc8;
    }

    float c0[2][8][4], c1[2][8][4];
#pragma unroll
    for (int i = 0; i < 2; i++)
#pragma unroll
        for (int j = 0; j < 8; j++)
#pragma unroll
            for (int k = 0; k < 4; k++) { c0[i][j][k] = 0.f; c1[i][j][k] = 0.f; }

    auto load_stage = [&](int c0v, uint32_t stg) {
#pragma unroll
        for (int i = 0; i < 4; i++) {
            CP16(stg + soffs[i],            ef + a0off[i] + c0v);
            CP16(stg + EN_T + soffs[i],     ef + a0off[i] + 128 * ENC_ + c0v);
            CP16(stg + 2 * EN_T + soffs[i], wh + boff[i] + c0v);
        }
    };

    load_stage(0, tiles);
    CP_COMMIT();

    const int KT = ENC_ / 64;
    for (int kt = 0; kt < KT; kt++) {
        uint32_t stg = tiles + (kt & 1) * EN_STAGE;
        if (kt + 1 < KT) {
            load_stage((kt + 1) * 64, tiles + ((kt + 1) & 1) * EN_STAGE);
            CP_COMMIT();
            cp_wait<1>();
        } else {
            cp_wait<0>();
        }
        __syncthreads();
        {
            const uint32_t A0 = stg, A1 = stg + EN_T;
            const uint32_t Bh = stg + 2 * EN_T;
            const int lm = lane & 15, lh = lane >> 4;
#pragma unroll
            for (int ks = 0; ks < 4; ks++) {
                const int ch = ks * 2 + lh;
                uint32_t a0[2][4], a1[2][4];
#pragma unroll
                for (int mf = 0; mf < 2; mf++) {
                    uint32_t off = swz(warp_m + mf * 16 + lm, ch);
                    ldmx4(A0 + off, a0[mf]);
                    ldmx4(A1 + off, a1[mf]);
                }
                uint32_t bb[4][4];
#pragma unroll
                for (int nf2 = 0; nf2 < 4; nf2++) {
                    uint32_t off = swz(warp_n + nf2 * 16 + lm, ch);
                    ldmx4(Bh + off, bb[nf2]);
                }
#pragma unroll
                for (int nf2 = 0; nf2 < 4; nf2++)
#pragma unroll
                    for (int mf = 0; mf < 2; mf++) {
                        mma16816h(c0[mf][nf2 * 2 + 0], a0[mf], bb[nf2][0], bb[nf2][2]);
                        mma16816h(c0[mf][nf2 * 2 + 1], a0[mf], bb[nf2][1], bb[nf2][3]);
                        mma16816h(c1[mf][nf2 * 2 + 0], a1[mf], bb[nf2][0], bb[nf2][2]);
                        mma16816h(c1[mf][nf2 * 2 + 1], a1[mf], bb[nf2][1], bb[nf2][3]);
                    }
            }
        }
        __syncthreads();
    }

#pragma unroll
    for (int t = 0; t < 2; t++) {
#pragma unroll
        for (int mf = 0; mf < 2; mf++) {
            int rl = t * 128 + warp_m + mf * 16 + (lane >> 2);
            int rh = rl + 8;
            int gl = sid[rl], gh = sid[rh];
            const float* ql = query + (long)(gl >> 8) * H_ + n0;
            const float* qh = query + (long)(gh >> 8) * H_ + n0;
            float s_lo = 0.f, s_hi = 0.f;
#pragma unroll
            for (int nf = 0; nf < 8; nf++) {
                int col = warp_n + nf * 8 + (lane & 3) * 2;
                float v0 = vs[col], v1 = vs[col + 1];
                float* cc = t ? c1[mf][nf] : c0[mf][nf];
                s_lo += v0 * tanhf(ql[col] + cc[0] * INVWK) + v1 * tanhf(ql[col + 1] + cc[1] * INVWK);
                s_hi += v0 * tanhf(qh[col] + cc[2] * INVWK) + v1 * tanhf(qh[col + 1] + cc[3] * INVWK);
            }
            s_lo += __shfl_xor_sync(0xffffffff, s_lo, 1);
            s_lo += __shfl_xor_sync(0xffffffff, s_lo, 2);
            s_hi += __shfl_xor_sync(0xffffffff, s_hi, 1);
            s_hi += __shfl_xor_sync(0xffffffff, s_hi, 2);
            if ((lane & 3) == 0) {
                if (mt + rl < total) atomicAdd(&energy[gl], s_lo);
                if (mt + rh < total) atomicAdd(&energy[gh], s_hi);
            }
        }
    }
}

// ===================== fused softmax + compacted context =====================
__global__ void softmax_context_kernel(const float* __restrict__ energy,
                                       const float* __restrict__ enc,
                                       float* __restrict__ out_attn) {
    __shared__ float red[256];
    __shared__ float w[256];
    __shared__ int sid[256];
    __shared__ int cnts;
    const int b = blockIdx.x;
    const int tid = threadIdx.x;

    float val = energy[b * S_ + tid];
    red[tid] = val;
    sid[tid] = g_sidx[b * S_ + tid];
    if (tid == 0) cnts = g_scnt[b];
    __syncthreads();
#pragma unroll
    for (int off = 128; off > 0; off >>= 1) {
        if (tid < off) red[tid] = fmaxf(red[tid], red[tid + off]);
        __syncthreads();
    }
    float mx = red[0];
    __syncthreads();
    float ex = expf(val - mx);
    red[tid] = ex;
    __syncthreads();
#pragma unroll
    for (int off = 128; off > 0; off >>= 1) {
        if (tid < off) red[tid] += red[tid + off];
        __syncthreads();
    }
    float aw = ex / red[0];
    if (blockIdx.y == 0) out_attn[b * S_ + tid] = aw;
    w[tid] = aw;
    __syncthreads();

    const int cnt = cnts;
    const int col = blockIdx.y * 256 + tid;
    const float* eb = enc + (long)b * S_ * ENC_;
    float a0 = 0.f, a1 = 0.f, a2 = 0.f, a3 = 0.f;
    int j = 0;
    for (; j + 4 <= cnt; j += 4) {
        a0 = fmaf(w[sid[j]],     eb[(long)sid[j] * ENC_ + col],     a0);
        a1 = fmaf(w[sid[j + 1]], eb[(long)sid[j + 1] * ENC_ + col], a1);
        a2 = fmaf(w[sid[j + 2]], eb[(long)sid[j + 2] * ENC_ + col], a2);
        a3 = fmaf(w[sid[j + 3]], eb[(long)sid[j + 3] * ENC_ + col], a3);
    }
    for (; j < cnt; j++)
        a0 = fmaf(w[sid[j]], eb[(long)sid[j] * ENC_ + col], a0);
    float acc = (a0 + a1) + (a2 + a3);
    __half hv = __float2half_rn(acc);
    g_a0f[b * KCAT0 + E_ + col] = hv;
    g_featf[b * FDIM_ + H_ + col] = hv;
}

// ===================== LSTM pointwise ========================================
__global__ void lstm_kernel(const float* __restrict__ gates,
                            const float* __restrict__ c_prev,
                            float* __restrict__ c_out,
                            float* __restrict__ h_out_f32,
                            __half* __restrict__ hb,
                            int sb) {
    const int b = blockIdx.x;
    const int idx = blockIdx.y * 256 + threadIdx.x;
    float gi = gates[b * G4H_ + idx];
    float gf = gates[b * G4H_ + H_ + idx];
    float gg = gates[b * G4H_ + 2 * H_ + idx];
    float go = gates[b * G4H_ + 3 * H_ + idx];
    float c  = c_prev[b * H_ + idx];
    float si = 1.f / (1.f + expf(-gi));
    float sf = 1.f / (1.f + expf(-gf));
    float so = 1.f / (1.f + expf(-go));
    float cn = sf * c + si * tanhf(gg);
    float hn = so * tanhf(cn);
    c_out[b * H_ + idx]     = cn;
    h_out_f32[b * H_ + idx] = hn;
    hb[b * sb + idx] = __float2half_rn(hn);
}

// ===================== launch ================================================
extern "C" void kernel_launch(void* const* d_in, const int* in_sizes, int n_in,
                              void* d_out, int out_size) {
    const int*   tok    = (const int*)  d_in[0];
    const float* hidden = (const float*)d_in[1];
    const float* cell   = (const float*)d_in[2];
    const float* enc    = (const float*)d_in[3];
    const int*   mask   = (const int*)  d_in[4];
    const float* emb    = (const float*)d_in[5];
    const float* Wq     = (const float*)d_in[6];
    const float* Wk     = (const float*)d_in[7];
    const float* v      = (const float*)d_in[8];
    const float* Wih0   = (const float*)d_in[9];
    const float* Whh0   = (const float*)d_in[10];
    const float* bih0   = (const float*)d_in[11];
    const float* bhh0   = (const float*)d_in[12];
    const float* Wih1   = (const float*)d_in[13];
    const float* Whh1   = (const float*)d_in[14];
    const float* bih1   = (const float*)d_in[15];
    const float* bhh1   = (const float*)d_in[16];
    const float* Wout   = (const float*)d_in[17];
    const float* bout   = (const float*)d_in[18];

    float* out      = (float*)d_out;
    float* out_pred = out;
    float* out_hid  = out + (long)B_ * V_;
    float* out_cell = out_hid + 2 * B_ * H_;
    float* out_attn = out_cell + 2 * B_ * H_;

    void* sp = nullptr;
    cudaGetSymbolAddress(&sp, g_scratch);
    float* scratch = (float*)sp;
    float* query  = scratch + OFF_QUERY;
    float* gates0 = scratch + OFF_GATES0;
    float* gates1 = scratch + OFF_GATES1;
    float* energy = scratch + OFF_ENERGY;

    void *p_ef, *p_wh, *p_h1, *p_a0, *p_a1, *p_ft;
    cudaGetSymbolAddress(&p_ef, g_enc_f16);
    cudaGetSymbolAddress(&p_wh, g_wk_h);
    cudaGetSymbolAddress(&p_h1, g_h1f);
    cudaGetSymbolAddress(&p_a0, g_a0f);
    cudaGetSymbolAddress(&p_a1, g_a1f);
    cudaGetSymbolAddress(&p_ft, g_featf);

    cudaFuncSetAttribute((const void*)hmma_m64_kernel<1, true>,  cudaFuncAttributeMaxDynamicSharedMemorySize, WO_SMEM_BYTES);
    cudaFuncSetAttribute((const void*)hmma_m64_kernel<1, false>, cudaFuncAttributeMaxDynamicSharedMemorySize, WO_SMEM_BYTES);
    cudaFuncSetAttribute(energy_f16_kernel, cudaFuncAttributeMaxDynamicSharedMemorySize, EN_SMEM_BYTES);

    // 1. scan: mask compact (+gidx via atomic base) + inits + scatters + Wk fp16
    scan_kernel<<<SCAN_BLKS, 256>>>(mask, hidden, tok, emb, Wk,
                                    bih0, bhh0, bih1, bhh1,
                                    energy, query, gates0, gates1);

    // 2. prep2: gathered enc -> fp16 compact
    prep2_kernel<<<ENC_RBLKS, 256>>>(enc);

    // 3. query = hidden[1] @ Wq^T (fp16 1-term, K-split 8, atomic)
    hmma_m64_kernel<1, true><<<dim3(H_ / 128, 8), 256, WO_SMEM_BYTES>>>(
        (const __half*)p_h1, H_, Wq, H_, Wq, nullptr, query, H_, 8);

    // 4. energy (fp16 1-term Wk, compact A rows)
    energy_f16_kernel<<<dim3(H_ / 128, (B_ * S_) / 256), 256, EN_SMEM_BYTES>>>(
        (const __half*)p_ef, (const __half*)p_wh, v, query, energy);

    // 5. fused masked softmax + compacted context
    softmax_context_kernel<<<dim3(B_, 4), 256>>>(energy, enc, out_attn);

    // 6. layer-0 gates (fp16 1-term, K-split 5) + LSTM
    hmma_m64_kernel<1, true><<<dim3(G4H_ / 128, 5), 256, WO_SMEM_BYTES>>>(
        (const __half*)p_a0, KCAT0, Wih0, E_ + ENC_, Whh0, nullptr, gates0, G4H_, 5);
    lstm_kernel<<<dim3(B_, H_ / 256), 256>>>(gates0, cell, out_cell, out_hid,
                                             (__half*)p_a1, KCAT1);

    // 7. layer-1 gates (fp16 1-term, K-split 8) + LSTM
    hmma_m64_kernel<1, true><<<dim3(G4H_ / 128, 8), 256, WO_SMEM_BYTES>>>(
        (const __half*)p_a1, KCAT1, Wih1, H_, Whh1, nullptr, gates1, G4H_, 8);
    lstm_kernel<<<dim3(B_, H_ / 256), 256>>>(gates1, cell + B_ * H_, out_cell + B_ * H_,
                                             out_hid + B_ * H_, (__half*)p_ft, FDIM_);

    // 8. prediction = feat @ Wout^T + bout (fp16 1-term, non-atomic; resets g_ctr)
    hmma_m64_kernel<1, false><<<dim3(V_ / 128, 1), 256, WO_SMEM_BYTES>>>(
        (const __half*)p_ft, FDIM_, Wout, FDIM_, Wout, bout, out_pred, V_, 1);
}

// round 16
// speedup vs baseline: 2.8662x; 1.0173x over previous
#include <cuda_runtime.h>
#include <cuda_bf16.h>
#include <cuda_fp16.h>
#include <math.h>
#include <stdint.h>

#define B_   64
#define S_   256
#define H_   1024
#define ENC_ 1024
#define E_   512
#define V_   32000
#define FDIM_ (H_ + ENC_ + E_)   // 2560
#define G4H_  (4 * H_)           // 4096
#define KCAT0 2560
#define KCAT1 2048
#define WKSCALE 2048.0f
#define INVWK   (1.0f / 2048.0f)

// ---------------- scratch ----------------------------------------------------
#define OFF_QUERY   0
#define OFF_GATES0  (OFF_QUERY + B_ * H_)
#define OFF_GATES1  (OFF_GATES0 + B_ * G4H_)
#define OFF_ENERGY  (OFF_GATES1 + B_ * G4H_)
#define SCRATCH_TOTAL (OFF_ENERGY + B_ * S_)

__device__ __align__(16) float g_scratch[SCRATCH_TOTAL];
__device__ int g_sidx[B_ * S_];
__device__ int g_scnt[B_];
__device__ int g_gidx[B_ * S_];
__device__ int g_ctr;          // compacted-row counter; reset by wout each launch

// fp16 buffers (g_enc_f16 holds GATHERED unmasked rows, compact)
__device__ __align__(16) __half g_enc_f16[(long)B_ * S_ * ENC_];
__device__ __align__(16) __half g_wk_h[H_ * ENC_];
__device__ __align__(16) __half g_h1f[B_ * H_];
__device__ __align__(16) __half g_a0f[B_ * KCAT0];
__device__ __align__(16) __half g_a1f[B_ * KCAT1];
__device__ __align__(16) __half g_featf[B_ * FDIM_];

// ===================== low-level helpers =====================================
__device__ __forceinline__ uint32_t smem_to_u32(const void* p) {
    uint32_t a;
    asm("{ .reg .u64 t; cvta.to.shared.u64 t, %1; cvt.u32.u64 %0, t; }" : "=r"(a) : "l"(p));
    return a;
}

#define CP16(dst_u32, src_ptr) \
    asm volatile("cp.async.cg.shared.global [%0], [%1], 16;" :: "r"(dst_u32), "l"(src_ptr))
#define CP_COMMIT() asm volatile("cp.async.commit_group;" ::: "memory")
template<int N> __device__ __forceinline__ void cp_wait() {
    asm volatile("cp.async.wait_group %0;" :: "n"(N) : "memory");
}

__device__ __forceinline__ void ldmx4(uint32_t addr, uint32_t r[4]) {
    asm volatile("ldmatrix.sync.aligned.m8n8.x4.shared.b16 {%0,%1,%2,%3}, [%4];"
        : "=r"(r[0]), "=r"(r[1]), "=r"(r[2]), "=r"(r[3]) : "r"(addr));
}

__device__ __forceinline__ void mma16816h(float* c, const uint32_t a[4],
                                          uint32_t b0, uint32_t b1) {
    asm volatile("mma.sync.aligned.m16n8k16.row.col.f32.f16.f16.f32 "
        "{%0,%1,%2,%3}, {%4,%5,%6,%7}, {%8,%9}, {%0,%1,%2,%3};"
        : "+f"(c[0]), "+f"(c[1]), "+f"(c[2]), "+f"(c[3])
        : "r"(a[0]), "r"(a[1]), "r"(a[2]), "r"(a[3]), "r"(b0), "r"(b1));
}

#define STS128(addr, a, b, c, d) \
    asm volatile("st.shared.v4.b32 [%0], {%1,%2,%3,%4};" \
        :: "r"(addr), "r"(a), "r"(b), "r"(c), "r"(d) : "memory")

#define LDS128U(addr, r0, r1, r2, r3) \
    asm volatile("ld.shared.v4.b32 {%0,%1,%2,%3}, [%4];" \
        : "=r"(r0), "=r"(r1), "=r"(r2), "=r"(r3) : "r"(addr))

__device__ __forceinline__ uint32_t swz(int row, int chunk16) {
    return (uint32_t)(row * 128 + ((chunk16 ^ (row & 7)) * 16));
}

// fast clamped tanh / sigmoid (abs err ~2e-7; MUFU-based)
__device__ __forceinline__ float ftanh(float x) {
    float xc = fminf(fmaxf(x, -40.0f), 40.0f);
    float e = __expf(2.0f * xc);
    return __fdividef(e - 1.0f, e + 1.0f);
}
__device__ __forceinline__ float fsigm(float x) {
    return __fdividef(1.0f, 1.0f + __expf(-x));
}

// fp16 scaled split: w*2048 = hi + lo
__device__ __forceinline__ void split2h(float a, float b, uint32_t& hi, uint32_t& lo) {
    float as = a * WKSCALE, bs = b * WKSCALE;
    __half2 h2 = __floats2half2_rn(as, bs);
    float ra = as - __half2float(__low2half(h2));
    float rb = bs - __half2float(__high2half(h2));
    __half2 l2 = __floats2half2_rn(ra, rb);
    hi = *reinterpret_cast<uint32_t*>(&h2);
    lo = *reinterpret_cast<uint32_t*>(&l2);
}

// ===================== scan kernel ===========================================
// [0,64): mask scan + gidx (atomic base) + energy init + embed + hidden scatter
// [64,128): h1 fp16   [128,192): query zero
// [192,448): gates0 bias  [448,704): gates1 bias
// [704,1728): Wk scaled fp16 (hi only)
#define SCAN_BLKS 1728

__global__ void scan_kernel(const int* __restrict__ mask,
                            const float* __restrict__ hidden,
                            const int* __restrict__ tok,
                            const float* __restrict__ emb,
                            const float* __restrict__ wk,
                            const float* __restrict__ bih0,
                            const float* __restrict__ bhh0,
                            const float* __restrict__ bih1,
                            const float* __restrict__ bhh1,
                            float* __restrict__ energy,
                            float* __restrict__ query,
                            float* __restrict__ gates0,
                            float* __restrict__ gates1) {
    const int tid = threadIdx.x;
    const int blk = blockIdx.x;
    if (blk < 64) {
        const int b = blk;
        __shared__ int sc[256];
        __shared__ int base_s;
        int m = (mask[b * S_ + tid] != 0) ? 1 : 0;
        sc[tid] = m;
        __syncthreads();
#pragma unroll
        for (int off = 1; off < 256; off <<= 1) {
            int t = (tid >= off) ? sc[tid - off] : 0;
            __syncthreads();
            sc[tid] += t;
            __syncthreads();
        }
        int total = sc[255];
        int my = sc[tid] - m;
        if (m) g_sidx[b * S_ + my] = tid;
        if (tid >= total) g_sidx[b * S_ + tid] = 0;
        energy[b * S_ + tid] = m ? 0.f : -1e10f;
        if (tid == 0) {
            g_scnt[b] = total;
            base_s = atomicAdd(&g_ctr, total);
        }
        __syncthreads();
        if (m) g_gidx[base_s + my] = b * S_ + tid;
        const int t = tok[b];
        for (int j = tid; j < E_; j += 256) {
            __half hv = __float2half_rn(emb[(long)t * E_ + j]);
            g_a0f[b * KCAT0 + j] = hv;
            g_featf[b * FDIM_ + (H_ + ENC_) + j] = hv;
        }
        for (int j = tid; j < H_; j += 256) {
            g_a0f[b * KCAT0 + (E_ + ENC_) + j] = __float2half_rn(hidden[b * H_ + j]);
            g_a1f[b * KCAT1 + H_ + j] = __float2half_rn(hidden[B_ * H_ + b * H_ + j]);
        }
    } else if (blk < 128) {
        long i = ((long)(blk - 64) * 256 + tid) * 4;
        float4 v = *reinterpret_cast<const float4*>(hidden + (long)B_ * H_ + i);
        __half2 h0 = __floats2half2_rn(v.x, v.y);
        __half2 h1 = __floats2half2_rn(v.z, v.w);
        uint2 o = {*reinterpret_cast<uint32_t*>(&h0), *reinterpret_cast<uint32_t*>(&h1)};
        *reinterpret_cast<uint2*>(g_h1f + i) = o;
    } else if (blk < 192) {
        long i = ((long)(blk - 128) * 256 + tid) * 4;
        float4 z = {0.f, 0.f, 0.f, 0.f};
        *reinterpret_cast<float4*>(query + i) = z;
    } else if (blk < 448) {
        long i = ((long)(blk - 192) * 256 + tid) * 4;
        int n = (int)(i & (G4H_ - 1));
        float4 o = {bih0[n] + bhh0[n], bih0[n + 1] + bhh0[n + 1],
                    bih0[n + 2] + bhh0[n + 2], bih0[n + 3] + bhh0[n + 3]};
        *reinterpret_cast<float4*>(gates0 + i) = o;
    } else if (blk < 704) {
        long i = ((long)(blk - 448) * 256 + tid) * 4;
        int n = (int)(i & (G4H_ - 1));
        float4 o = {bih1[n] + bhh1[n], bih1[n + 1] + bhh1[n + 1],
                    bih1[n + 2] + bhh1[n + 2], bih1[n + 3] + bhh1[n + 3]};
        *reinterpret_cast<float4*>(gates1 + i) = o;
    } else {
        long i = ((long)(blk - 704) * 256 + tid) * 4;
        float4 v = *reinterpret_cast<const float4*>(wk + i);
        __half2 h0 = __floats2half2_rn(v.x * WKSCALE, v.y * WKSCALE);
        __half2 h1 = __floats2half2_rn(v.z * WKSCALE, v.w * WKSCALE);
        uint2 o = {*reinterpret_cast<uint32_t*>(&h0), *reinterpret_cast<uint32_t*>(&h1)};
        *reinterpret_cast<uint2*>(g_wk_h + i) = o;
    }
}

// ===================== prep2: gathered enc conversion ========================
#define ENC_RBLKS ((B_ * S_) / 4)

__global__ void prep2_kernel(const float* __restrict__ enc) {
    const int tid = threadIdx.x;
    int row0 = blockIdx.x * 4;
    int lim = (g_ctr + 255) & ~255;
    if (row0 >= lim) return;
    const int e = tid * 4;
#pragma unroll
    for (int rr = 0; rr < 4; rr++) {
        int row = row0 + rr;
        long src = (long)g_gidx[row] * ENC_ + e;
        float4 v = *reinterpret_cast<const float4*>(enc + src);
        __half2 h0 = __floats2half2_rn(v.x, v.y);
        __half2 h1 = __floats2half2_rn(v.z, v.w);
        uint2 o = {*reinterpret_cast<uint32_t*>(&h0), *reinterpret_cast<uint32_t*>(&h1)};
        *reinterpret_cast<uint2*>(g_enc_f16 + (long)row * ENC_ + e) = o;
    }
}

// ===================== fat-B HMMA kernel (fp16, cp.async B staging) ==========
// smem: A 2x8KB | Braw 2x32KB (swizzled fp32) | Bh 16KB | Bl 16KB
#define WO_SMEM_BYTES (1024 + 16384 + 65536 + 32768)

template<int NT, bool ATOMIC>
__global__ __launch_bounds__(256, 2)
void hmma_m64_kernel(const __half* __restrict__ a_g,
                     int Ktot,
                     const float* __restrict__ B1, int k1,
                     const float* __restrict__ B2,
                     const float* __restrict__ bias1,
                     float* __restrict__ C, int ldc, int nks) {
    extern __shared__ char smem[];
    uint32_t sb = smem_to_u32(smem);
    uint32_t tiles = (sb + 1023) & ~1023u;
    const uint32_t A_   = tiles;
    const uint32_t BRAW = tiles + 16384;
    const uint32_t BH   = tiles + 81920;
    const uint32_t BL   = BH + 16384;

    const int tid = threadIdx.x;
    const int wid = tid >> 5, lane = tid & 31;
    const int warp_m = (wid & 1) * 32;
    const int warp_n = (wid >> 1) * 32;
    const int n0 = blockIdx.x * 128;
    const int k2 = Ktot - k1;

    // wout (the final, non-atomic instance) resets the compaction counter.
    if (!ATOMIC && tid == 0 && blockIdx.x == 0 && blockIdx.y == 0) g_ctr = 0;

    const int KT = Ktot / 64;
    const int kt0 = (int)blockIdx.y * (KT / nks);
    const int kt1 = kt0 + KT / nks;

    const int br = tid >> 1, bhalf = tid & 1;
    const int srr = br * 2 + bhalf;

    // precomputed ks=0 ldmatrix bases (XOR-fold ks<<5 in the loop)
    const int lm = lane & 15, lh = lane >> 4;
    uint32_t abase[2], bhb[2], blb[2];
#pragma unroll
    for (int mf = 0; mf < 2; mf++)
        abase[mf] = swz(warp_m + mf * 16 + lm, lh);
#pragma unroll
    for (int nf2 = 0; nf2 < 2; nf2++) {
        bhb[nf2] = BH + swz(warp_n + nf2 * 16 + lm, lh);
        blb[nf2] = BL + swz(warp_n + nf2 * 16 + lm, lh);
    }

    float c[2][4][4];
#pragma unroll
    for (int i = 0; i < 2; i++)
#pragma unroll
        for (int j = 0; j < 4; j++)
#pragma unroll
            for (int k = 0; k < 4; k++) c[i][j][k] = 0.f;

    auto load_stage = [&](int kt) {
        const int s = kt & 1;
        const int c0 = kt * 64;
#pragma unroll
        for (int i = 0; i < 2; i++) {
            int idx = tid + i * 256;
            int r = idx >> 3, cc = idx & 7;
            CP16(A_ + s * 8192 + swz(r, cc), a_g + (long)r * Ktot + c0 + cc * 8);
        }
#pragma unroll
        for (int i = 0; i < 8; i++) {
            int g = tid + i * 256;
            int brow = g >> 4, j = g & 15;
            int sr = brow * 2 + (j >> 3), cch = j & 7;
            uint32_t dst = BRAW + s * 32768 +
                           (uint32_t)(sr * 128 + ((cch ^ (sr & 7)) * 16));
            const float* src = (c0 < k1)
                ? B1 + (long)(n0 + brow) * k1 + c0 + j * 4
                : B2 + (long)(n0 + brow) * k2 + (c0 - k1) + j * 4;
            CP16(dst, src);
        }
    };

    load_stage(kt0);
    CP_COMMIT();

    for (int kt = kt0; kt < kt1; kt++) {
        const int s = kt & 1;
        if (kt + 1 < kt1) {
            load_stage(kt + 1);
            CP_COMMIT();
            cp_wait<1>();
        } else {
            cp_wait<0>();
        }
        __syncthreads();
        {
            const uint32_t braw = BRAW + s * 32768;
            const int sx = srr & 7;
#pragma unroll
            for (int jo = 0; jo < 4; jo++) {
                uint32_t o0 = braw + (uint32_t)(srr * 128 + (((2 * jo)     ^ sx) * 16));
                uint32_t o1 = braw + (uint32_t)(srr * 128 + (((2 * jo + 1) ^ sx) * 16));
                uint32_t u0, u1, u2, u3, w0, w1, w2, w3;
                LDS128U(o0, u0, u1, u2, u3);
                LDS128U(o1, w0, w1, w2, w3);
                uint4 Hq, Lq;
                split2h(__uint_as_float(u0), __uint_as_float(u1), Hq.x, Lq.x);
                split2h(__uint_as_float(u2), __uint_as_float(u3), Hq.y, Lq.y);
                split2h(__uint_as_float(w0), __uint_as_float(w1), Hq.z, Lq.z);
                split2h(__uint_as_float(w2), __uint_as_float(w3), Hq.w, Lq.w);
                uint32_t off = swz(br, bhalf * 4 + jo);
                STS128(BH + off, Hq.x, Hq.y, Hq.z, Hq.w);
                if (NT == 2) STS128(BL + off, Lq.x, Lq.y, Lq.z, Lq.w);
            }
        }
        __syncthreads();
        {
            const uint32_t Abase = A_ + s * 8192;
#pragma unroll
            for (int ks = 0; ks < 4; ks++) {
                const uint32_t x = (uint32_t)(ks << 5);
                uint32_t ah[2][4];
#pragma unroll
                for (int mf = 0; mf < 2; mf++)
                    ldmx4(Abase + (abase[mf] ^ x), ah[mf]);
                uint32_t bb[2][4];
#pragma unroll
                for (int nf2 = 0; nf2 < 2; nf2++)
                    ldmx4(bhb[nf2] ^ x, bb[nf2]);
#pragma unroll
                for (int nf2 = 0; nf2 < 2; nf2++)
#pragma unroll
                    for (int mf = 0; mf < 2; mf++) {
                        mma16816h(c[mf][nf2 * 2 + 0], ah[mf], bb[nf2][0], bb[nf2][2]);
                        mma16816h(c[mf][nf2 * 2 + 1], ah[mf], bb[nf2][1], bb[nf2][3]);
                    }
                if (NT == 2) {
#pragma unroll
                    for (int nf2 = 0; nf2 < 2; nf2++)
                        ldmx4(blb[nf2] ^ x, bb[nf2]);
#pragma unroll
                    for (int nf2 = 0; nf2 < 2; nf2++)
#pragma unroll
                        for (int mf = 0; mf < 2; mf++) {
                            mma16816h(c[mf][nf2 * 2 + 0], ah[mf], bb[nf2][0], bb[nf2][2]);
                            mma16816h(c[mf][nf2 * 2 + 1], ah[mf], bb[nf2][1], bb[nf2][3]);
                        }
                }
            }
        }
        __syncthreads();
    }

#pragma unroll
    for (int mf = 0; mf < 2; mf++)
#pragma unroll
        for (int nf = 0; nf < 4; nf++) {
            int col = n0 + warp_n + nf * 8 + (lane & 3) * 2;
            int r0 = warp_m + mf * 16 + (lane >> 2);
            if (ATOMIC) {
                atomicAdd(&C[(long)r0 * ldc + col],           c[mf][nf][0] * INVWK);
                atomicAdd(&C[(long)r0 * ldc + col + 1],       c[mf][nf][1] * INVWK);
                atomicAdd(&C[(long)(r0 + 8) * ldc + col],     c[mf][nf][2] * INVWK);
                atomicAdd(&C[(long)(r0 + 8) * ldc + col + 1], c[mf][nf][3] * INVWK);
            } else {
                float b0 = 0.f, b1 = 0.f;
                if (bias1) { b0 = bias1[col]; b1 = bias1[col + 1]; }
                float2 o0 = {c[mf][nf][0] * INVWK + b0, c[mf][nf][1] * INVWK + b1};
                float2 o1 = {c[mf][nf][2] * INVWK + b0, c[mf][nf][3] * INVWK + b1};
                *reinterpret_cast<float2*>(C + (long)r0 * ldc + col) = o0;
                *reinterpret_cast<float2*>(C + (long)(r0 + 8) * ldc + col) = o1;
            }
        }
}

// ===================== energy: fp16 1-term Wk, compact 256-row tiles =========
#define EN_T 16384
#define EN_STAGE (3 * EN_T)                 // A0 A1 Bh = 48KB
#define EN_SMEM_BYTES (2048 + 2 * EN_STAGE)

__global__ __launch_bounds__(256, 1)
void energy_f16_kernel(const __half* __restrict__ ef,
                       const __half* __restrict__ wh,
                       const float* __restrict__ vvec,
                       const float* __restrict__ query,
                       float* __restrict__ energy) {
    const int total = g_ctr;
    const int mt = (int)blockIdx.y * 256;
    if (mt >= total) return;

    extern __shared__ char smem[];
    uint32_t sb = smem_to_u32(smem);
    uint32_t tiles = (sb + 2048 + 1023) & ~1023u;

    const int tid = threadIdx.x;
    const int wid = tid >> 5, lane = tid & 31;
    const int warp_m = (wid & 3) * 32;
    const int warp_n = (wid >> 2) * 64;
    const int n0 = blockIdx.x * 128;

    float* vs = (float*)smem;
    int*   sid = (int*)(vs + 128);
    if (tid < 128) vs[tid] = vvec[n0 + tid];
    sid[tid] = g_gidx[mt + tid];
    __syncthreads();

    const int rb = tid >> 3, cc8 = (tid & 7) * 8;
    uint32_t a0off[4], boff[4], soffs[4];
#pragma unroll
    for (int i = 0; i < 4; i++) {
        int r = rb + 32 * i;
        soffs[i] = swz(r, tid & 7);
        a0off[i] = (uint32_t)(mt + r) * ENC_ + cc8;
        boff[i]  = (uint32_t)(n0 + r) * ENC_ + cc8;
    }

    // precomputed ks=0 ldmatrix bases (relative to stage start)
    const int lm = lane & 15, lh = lane >> 4;
    uint32_t a0b[2], a1b[2], bbb[4];
#pragma unroll
    for (int mf = 0; mf < 2; mf++) {
        a0b[mf] = swz(warp_m + mf * 16 + lm, lh);
        a1b[mf] = EN_T + swz(warp_m + mf * 16 + lm, lh);
    }
#pragma unroll
    for (int nf2 = 0; nf2 < 4; nf2++)
        bbb[nf2] = 2 * EN_T + swz(warp_n + nf2 * 16 + lm, lh);

    float c0[2][8][4], c1[2][8][4];
#pragma unroll
    for (int i = 0; i < 2; i++)
#pragma unroll
        for (int j = 0; j < 8; j++)
#pragma unroll
            for (int k = 0; k < 4; k++) { c0[i][j][k] = 0.f; c1[i][j][k] = 0.f; }

    auto load_stage = [&](int c0v, uint32_t stg) {
#pragma unroll
        for (int i = 0; i < 4; i++) {
            CP16(stg + soffs[i],            ef + a0off[i] + c0v);
            CP16(stg + EN_T + soffs[i],     ef + a0off[i] + 128 * ENC_ + c0v);
            CP16(stg + 2 * EN_T + soffs[i], wh + boff[i] + c0v);
        }
    };

    load_stage(0, tiles);
    CP_COMMIT();

    const int KT = ENC_ / 64;
    for (int kt = 0; kt < KT; kt++) {
        uint32_t stg = tiles + (kt & 1) * EN_STAGE;
        if (kt + 1 < KT) {
            load_stage((kt + 1) * 64, tiles + ((kt + 1) & 1) * EN_STAGE);
            CP_COMMIT();
            cp_wait<1>();
        } else {
            cp_wait<0>();
        }
        __syncthreads();
        {
#pragma unroll
            for (int ks = 0; ks < 4; ks++) {
                const uint32_t x = (uint32_t)(ks << 5);
                uint32_t a0[2][4], a1[2][4];
#pragma unroll
                for (int mf = 0; mf < 2; mf++) {
                    ldmx4(stg + (a0b[mf] ^ x), a0[mf]);
                    ldmx4(stg + (a1b[mf] ^ x), a1[mf]);
                }
                uint32_t bb[4][4];
#pragma unroll
                for (int nf2 = 0; nf2 < 4; nf2++)
                    ldmx4(stg + (bbb[nf2] ^ x), bb[nf2]);
#pragma unroll
                for (int nf2 = 0; nf2 < 4; nf2++)
#pragma unroll
                    for (int mf = 0; mf < 2; mf++) {
                        mma16816h(c0[mf][nf2 * 2 + 0], a0[mf], bb[nf2][0], bb[nf2][2]);
                        mma16816h(c0[mf][nf2 * 2 + 1], a0[mf], bb[nf2][1], bb[nf2][3]);
                        mma16816h(c1[mf][nf2 * 2 + 0], a1[mf], bb[nf2][0], bb[nf2][2]);
                        mma16816h(c1[mf][nf2 * 2 + 1], a1[mf], bb[nf2][1], bb[nf2][3]);
                    }
            }
        }
        __syncthreads();
    }

#pragma unroll
    for (int t = 0; t < 2; t++) {
#pragma unroll
        for (int mf = 0; mf < 2; mf++) {
            int rl = t * 128 + warp_m + mf * 16 + (lane >> 2);
            int rh = rl + 8;
            int gl = sid[rl], gh = sid[rh];
            const float* ql = query + (long)(gl >> 8) * H_ + n0;
            const float* qh = query + (long)(gh >> 8) * H_ + n0;
            float s_lo = 0.f, s_hi = 0.f;
#pragma unroll
            for (int nf = 0; nf < 8; nf++) {
                int col = warp_n + nf * 8 + (lane & 3) * 2;
                float v0 = vs[col], v1 = vs[col + 1];
                float* cc = t ? c1[mf][nf] : c0[mf][nf];
                s_lo += v0 * ftanh(ql[col] + cc[0] * INVWK) + v1 * ftanh(ql[col + 1] + cc[1] * INVWK);
                s_hi += v0 * ftanh(qh[col] + cc[2] * INVWK) + v1 * ftanh(qh[col + 1] + cc[3] * INVWK);
            }
            s_lo += __shfl_xor_sync(0xffffffff, s_lo, 1);
            s_lo += __shfl_xor_sync(0xffffffff, s_lo, 2);
            s_hi += __shfl_xor_sync(0xffffffff, s_hi, 1);
            s_hi += __shfl_xor_sync(0xffffffff, s_hi, 2);
            if ((lane & 3) == 0) {
                if (mt + rl < total) atomicAdd(&energy[gl], s_lo);
                if (mt + rh < total) atomicAdd(&energy[gh], s_hi);
            }
        }
    }
}

// ===================== fused softmax + compacted context =====================
__global__ void softmax_context_kernel(const float* __restrict__ energy,
                                       const float* __restrict__ enc,
                                       float* __restrict__ out_attn) {
    __shared__ float red[256];
    __shared__ float w[256];
    __shared__ int sid[256];
    __shared__ int cnts;
    const int b = blockIdx.x;
    const int tid = threadIdx.x;

    float val = energy[b * S_ + tid];
    red[tid] = val;
    sid[tid] = g_sidx[b * S_ + tid];
    if (tid == 0) cnts = g_scnt[b];
    __syncthreads();
#pragma unroll
    for (int off = 128; off > 0; off >>= 1) {
        if (tid < off) red[tid] = fmaxf(red[tid], red[tid + off]);
        __syncthreads();
    }
    float mx = red[0];
    __syncthreads();
    float ex = expf(val - mx);
    red[tid] = ex;
    __syncthreads();
#pragma unroll
    for (int off = 128; off > 0; off >>= 1) {
        if (tid < off) red[tid] += red[tid + off];
        __syncthreads();
    }
    float aw = ex / red[0];
    if (blockIdx.y == 0) out_attn[b * S_ + tid] = aw;
    w[tid] = aw;
    __syncthreads();

    const int cnt = cnts;
    const int col = blockIdx.y * 256 + tid;
    const float* eb = enc + (long)b * S_ * ENC_;
    float a0 = 0.f, a1 = 0.f, a2 = 0.f, a3 = 0.f;
    int j = 0;
    for (; j + 4 <= cnt; j += 4) {
        a0 = fmaf(w[sid[j]],     eb[(long)sid[j] * ENC_ + col],     a0);
        a1 = fmaf(w[sid[j + 1]], eb[(long)sid[j + 1] * ENC_ + col], a1);
        a2 = fmaf(w[sid[j + 2]], eb[(long)sid[j + 2] * ENC_ + col], a2);
        a3 = fmaf(w[sid[j + 3]], eb[(long)sid[j + 3] * ENC_ + col], a3);
    }
    for (; j < cnt; j++)
        a0 = fmaf(w[sid[j]], eb[(long)sid[j] * ENC_ + col], a0);
    float acc = (a0 + a1) + (a2 + a3);
    __half hv = __float2half_rn(acc);
    g_a0f[b * KCAT0 + E_ + col] = hv;
    g_featf[b * FDIM_ + H_ + col] = hv;
}

// ===================== LSTM pointwise ========================================
__global__ void lstm_kernel(const float* __restrict__ gates,
                            const float* __restrict__ c_prev,
                            float* __restrict__ c_out,
                            float* __restrict__ h_out_f32,
                            __half* __restrict__ hb,
                            int sb) {
    const int b = blockIdx.x;
    const int idx = blockIdx.y * 256 + threadIdx.x;
    float gi = gates[b * G4H_ + idx];
    float gf = gates[b * G4H_ + H_ + idx];
    float gg = gates[b * G4H_ + 2 * H_ + idx];
    float go = gates[b * G4H_ + 3 * H_ + idx];
    float c  = c_prev[b * H_ + idx];
    float si = fsigm(gi);
    float sf = fsigm(gf);
    float so = fsigm(go);
    float cn = sf * c + si * ftanh(gg);
    float hn = so * ftanh(cn);
    c_out[b * H_ + idx]     = cn;
    h_out_f32[b * H_ + idx] = hn;
    hb[b * sb + idx] = __float2half_rn(hn);
}

// ===================== launch ================================================
extern "C" void kernel_launch(void* const* d_in, const int* in_sizes, int n_in,
                              void* d_out, int out_size) {
    const int*   tok    = (const int*)  d_in[0];
    const float* hidden = (const float*)d_in[1];
    const float* cell   = (const float*)d_in[2];
    const float* enc    = (const float*)d_in[3];
    const int*   mask   = (const int*)  d_in[4];
    const float* emb    = (const float*)d_in[5];
    const float* Wq     = (const float*)d_in[6];
    const float* Wk     = (const float*)d_in[7];
    const float* v      = (const float*)d_in[8];
    const float* Wih0   = (const float*)d_in[9];
    const float* Whh0   = (const float*)d_in[10];
    const float* bih0   = (const float*)d_in[11];
    const float* bhh0   = (const float*)d_in[12];
    const float* Wih1   = (const float*)d_in[13];
    const float* Whh1   = (const float*)d_in[14];
    const float* bih1   = (const float*)d_in[15];
    const float* bhh1   = (const float*)d_in[16];
    const float* Wout   = (const float*)d_in[17];
    const float* bout   = (const float*)d_in[18];

    float* out      = (float*)d_out;
    float* out_pred = out;
    float* out_hid  = out + (long)B_ * V_;
    float* out_cell = out_hid + 2 * B_ * H_;
    float* out_attn = out_cell + 2 * B_ * H_;

    void* sp = nullptr;
    cudaGetSymbolAddress(&sp, g_scratch);
    float* scratch = (float*)sp;
    float* query  = scratch + OFF_QUERY;
    float* gates0 = scratch + OFF_GATES0;
    float* gates1 = scratch + OFF_GATES1;
    float* energy = scratch + OFF_ENERGY;

    void *p_ef, *p_wh, *p_h1, *p_a0, *p_a1, *p_ft;
    cudaGetSymbolAddress(&p_ef, g_enc_f16);
    cudaGetSymbolAddress(&p_wh, g_wk_h);
    cudaGetSymbolAddress(&p_h1, g_h1f);
    cudaGetSymbolAddress(&p_a0, g_a0f);
    cudaGetSymbolAddress(&p_a1, g_a1f);
    cudaGetSymbolAddress(&p_ft, g_featf);

    cudaFuncSetAttribute((const void*)hmma_m64_kernel<1, true>,  cudaFuncAttributeMaxDynamicSharedMemorySize, WO_SMEM_BYTES);
    cudaFuncSetAttribute((const void*)hmma_m64_kernel<1, false>, cudaFuncAttributeMaxDynamicSharedMemorySize, WO_SMEM_BYTES);
    cudaFuncSetAttribute(energy_f16_kernel, cudaFuncAttributeMaxDynamicSharedMemorySize, EN_SMEM_BYTES);

    // 1. scan: mask compact (+gidx via atomic base) + inits + scatters + Wk fp16
    scan_kernel<<<SCAN_BLKS, 256>>>(mask, hidden, tok, emb, Wk,
                                    bih0, bhh0, bih1, bhh1,
                                    energy, query, gates0, gates1);

    // 2. prep2: gathered enc -> fp16 compact
    prep2_kernel<<<ENC_RBLKS, 256>>>(enc);

    // 3. query = hidden[1] @ Wq^T (fp16 1-term, K-split 8, atomic)
    hmma_m64_kernel<1, true><<<dim3(H_ / 128, 8), 256, WO_SMEM_BYTES>>>(
        (const __half*)p_h1, H_, Wq, H_, Wq, nullptr, query, H_, 8);

    // 4. energy (fp16 1-term Wk, XOR-folded addressing)
    energy_f16_kernel<<<dim3(H_ / 128, (B_ * S_) / 256), 256, EN_SMEM_BYTES>>>(
        (const __half*)p_ef, (const __half*)p_wh, v, query, energy);

    // 5. fused masked softmax + compacted context
    softmax_context_kernel<<<dim3(B_, 4), 256>>>(energy, enc, out_attn);

    // 6. layer-0 gates (fp16 1-term, K-split 5) + LSTM
    hmma_m64_kernel<1, true><<<dim3(G4H_ / 128, 5), 256, WO_SMEM_BYTES>>>(
        (const __half*)p_a0, KCAT0, Wih0, E_ + ENC_, Whh0, nullptr, gates0, G4H_, 5);
    lstm_kernel<<<dim3(B_, H_ / 256), 256>>>(gates0, cell, out_cell, out_hid,
                                             (__half*)p_a1, KCAT1);

    // 7. layer-1 gates (fp16 1-term, K-split 8) + LSTM
    hmma_m64_kernel<1, true><<<dim3(G4H_ / 128, 8), 256, WO_SMEM_BYTES>>>(
        (const __half*)p_a1, KCAT1, Wih1, H_, Whh1, nullptr, gates1, G4H_, 8);
    lstm_kernel<<<dim3(B_, H_ / 256), 256>>>(gates1, cell + B_ * H_, out_cell + B_ * H_,
                                             out_hid + B_ * H_, (__half*)p_ft, FDIM_);

    // 8. prediction = feat @ Wout^T + bout (fp16 1-term, non-atomic; resets g_ctr)
    hmma_m64_kernel<1, false><<<dim3(V_ / 128, 1), 256, WO_SMEM_BYTES>>>(
        (const __half*)p_ft, FDIM_, Wout, FDIM_, Wout, bout, out_pred, V_, 1);
}